// round 1
// baseline (speedup 1.0000x reference)
#include <cuda_runtime.h>
#include <math.h>

#define S_  256
#define U_  64
#define H_  512
#define H2_ 256
#define V_  5000
#define KPT 768     /* H + H2 */
#define K3  1280    /* 2H + H2 */
#define MSU 16384   /* S*U */
#define PI_F 3.14159265358979323846f

/* ------------------------------------------------------------------ */
/* scratch (device globals; allocation-free)                           */
/* ------------------------------------------------------------------ */
__device__ float g_T   [168 * H2_];
__device__ float g_A1  [(size_t)MSU * KPT];
__device__ float g_poi [(size_t)MSU * H_];
__device__ float g_pre [(size_t)MSU * H_];
__device__ float g_out [(size_t)MSU * H_];
__device__ float g_w   [(size_t)U_ * S_ * S_];
__device__ float g_den [(size_t)U_ * S_];
__device__ float g_outw[(size_t)MSU * H_];
__device__ float g_A3  [(size_t)MSU * K3];
__device__ unsigned g_bar;

/* ------------------------------------------------------------------ */
/* 1. week distribution + time-embedding table T[168][H2]              */
/* T[slot,h] = sum_k ww[slot,k] * week_enc_w[ week_matrix[slot,k], h ] */
/* ------------------------------------------------------------------ */
__global__ void k_week(const float* __restrict__ sigma,
                       const float* __restrict__ wwi,
                       const int*   __restrict__ wm,
                       const float* __restrict__ wenc)
{
    const int slot = blockIdx.x;          // 0..167
    const int tid  = threadIdx.x;         // 0..255
    __shared__ float ww[168];
    __shared__ float red[256];

    float sig    = fabsf(sigma[slot]);
    float inv2s2 = 1.0f / (2.0f * sig * sig);
    float coef   = rsqrtf(2.0f * PI_F * sig * sig);

    float v = 0.0f;
    if (tid < 168) {
        float x = wwi[slot * 168 + tid];
        v = coef * expf(-x * x * inv2s2);
        ww[tid] = v;
    }
    red[tid] = v;
    __syncthreads();
    for (int off = 128; off > 0; off >>= 1) {
        if (tid < off) red[tid] += red[tid + off];
        __syncthreads();
    }
    const float inv = 1.0f / red[0];

    /* tid == h (H2 = 256 = blockDim) */
    float acc = 0.0f;
    for (int k = 0; k < 168; k++) {
        int row = wm[slot * 168 + k];
        acc += (ww[k] * inv) * wenc[row * H2_ + tid];
    }
    g_T[slot * H2_ + tid] = acc;
}

/* ------------------------------------------------------------------ */
/* 2. gather A1[m, 0:768] = [ enc_w[x[m]] | T[t_slot[m]] ]             */
/* ------------------------------------------------------------------ */
__global__ void k_gather1(const int* __restrict__ x,
                          const int* __restrict__ t_slot,
                          const float* __restrict__ enc_w)
{
    const int m  = blockIdx.x;
    const int xm = x[m];
    const int ts = t_slot[m];
    for (int c = threadIdx.x; c < KPT; c += blockDim.x) {
        float v = (c < H_) ? enc_w[(size_t)xm * H_ + c]
                           : g_T[ts * H2_ + (c - H_)];
        g_A1[(size_t)m * KPT + c] = v;
    }
}

/* ------------------------------------------------------------------ */
/* generic SGEMM:  C[M,N] = A[M,K] @ B[N,K]^T + bias1 (+ bias2)        */
/* BM=BN=128, BK=16, 256 threads, 8x8 register tile                    */
/* M must be a multiple of 128, K a multiple of 16; N guarded.         */
/* ------------------------------------------------------------------ */
__global__ __launch_bounds__(256)
void sgemm_bias(const float* __restrict__ A, const float* __restrict__ B,
                const float* __restrict__ bias1, const float* __restrict__ bias2,
                float* __restrict__ C, int M, int N, int K)
{
    __shared__ float As[16][132];
    __shared__ float Bs[16][132];

    const int tid = threadIdx.x;
    const int m0  = blockIdx.y * 128;
    const int n0  = blockIdx.x * 128;
    const int ty  = tid >> 4;   /* 0..15 */
    const int tx  = tid & 15;   /* 0..15 */
    const int lr  = tid >> 2;   /* 0..63 */
    const int lkq = tid & 3;    /* 0..3  */

    float acc[8][8];
#pragma unroll
    for (int i = 0; i < 8; i++)
#pragma unroll
        for (int j = 0; j < 8; j++) acc[i][j] = 0.0f;

    for (int k0 = 0; k0 < K; k0 += 16) {
#pragma unroll
        for (int half = 0; half < 2; half++) {
            int row = lr + half * 64;
            float4 v = *(const float4*)&A[(size_t)(m0 + row) * K + k0 + lkq * 4];
            As[lkq * 4 + 0][row] = v.x; As[lkq * 4 + 1][row] = v.y;
            As[lkq * 4 + 2][row] = v.z; As[lkq * 4 + 3][row] = v.w;
        }
#pragma unroll
        for (int half = 0; half < 2; half++) {
            int row = lr + half * 64;
            float4 v = make_float4(0.f, 0.f, 0.f, 0.f);
            if (n0 + row < N)
                v = *(const float4*)&B[(size_t)(n0 + row) * K + k0 + lkq * 4];
            Bs[lkq * 4 + 0][row] = v.x; Bs[lkq * 4 + 1][row] = v.y;
            Bs[lkq * 4 + 2][row] = v.z; Bs[lkq * 4 + 3][row] = v.w;
        }
        __syncthreads();
#pragma unroll
        for (int kk = 0; kk < 16; kk++) {
            float a[8], b[8];
            *(float4*)&a[0] = *(const float4*)&As[kk][ty * 4];
            *(float4*)&a[4] = *(const float4*)&As[kk][ty * 4 + 64];
            *(float4*)&b[0] = *(const float4*)&Bs[kk][tx * 4];
            *(float4*)&b[4] = *(const float4*)&Bs[kk][tx * 4 + 64];
#pragma unroll
            for (int i = 0; i < 8; i++)
#pragma unroll
                for (int j = 0; j < 8; j++)
                    acc[i][j] += a[i] * b[j];
        }
        __syncthreads();
    }

#pragma unroll
    for (int j = 0; j < 8; j++) {
        int n = n0 + tx * 4 + ((j < 4) ? j : (64 + j - 4));
        if (n >= N) continue;
        float bv = bias1[n];
        if (bias2) bv += bias2[n];
#pragma unroll
        for (int i = 0; i < 8; i++) {
            int m = m0 + ty * 4 + ((i < 4) ? i : (64 + i - 4));
            C[(size_t)m * N + n] = acc[i][j] + bv;
        }
    }
}

/* ------------------------------------------------------------------ */
/* barrier counter reset                                               */
/* ------------------------------------------------------------------ */
__global__ void k_zero_bar() { g_bar = 0u; }

/* ------------------------------------------------------------------ */
/* 3. persistent RNN:  out[s] = tanh( pre[s] + out[s-1] @ W_hh^T )     */
/* 128 blocks = 16 u-groups (4 u) x 8 n-groups (64 n).                 */
/* W_hh slice held in registers (128 floats / thread), h via global.   */
/* ------------------------------------------------------------------ */
__global__ __launch_bounds__(256, 1)
void k_rnn(const float* __restrict__ pre, const float* __restrict__ Whh,
           const float* __restrict__ h0, float* __restrict__ out)
{
    extern __shared__ float sh[];       /* 131072 B */
    const int tid = threadIdx.x;
    const int gu  = blockIdx.x >> 3;    /* 0..15 */
    const int gn  = blockIdx.x & 7;     /* 0..7  */
    const int n_l = tid & 63;
    const int kq  = tid >> 6;           /* 0..3  */
    const unsigned nblocks = gridDim.x;

    /* stage W slice (64 contiguous rows) coalesced, then copy to regs */
    const float* Wbase = Whh + (size_t)(gn * 64) * H_;
    for (int idx = tid * 4; idx < 64 * H_; idx += 256 * 4)
        *(float4*)&sh[idx] = *(const float4*)&Wbase[idx];
    __syncthreads();

    float wreg[128];
#pragma unroll
    for (int i = 0; i < 128; i++)
        wreg[i] = sh[n_l * H_ + kq * 128 + i];
    __syncthreads();

    float* hsh  = sh;          /* 4 x 512   */
    float* psum = sh + 2048;   /* 16 x 64   */
    const int ub = gu * 4;

    for (int s = 0; s < S_; s++) {
        const float* hp = (s == 0) ? h0 : (out + (size_t)(s - 1) * U_ * H_);
        for (int idx = tid; idx < 4 * H_; idx += 256) {
            int uu = idx >> 9, k = idx & 511;
            hsh[idx] = __ldcg(&hp[(size_t)(ub + uu) * H_ + k]);
        }
        __syncthreads();

#pragma unroll
        for (int uu = 0; uu < 4; uu++) {
            const float* hrow = hsh + uu * H_ + kq * 128;
            float a = 0.0f;
#pragma unroll
            for (int i = 0; i < 128; i++) a += hrow[i] * wreg[i];
            psum[(uu * 4 + kq) * 64 + n_l] = a;
        }
        __syncthreads();

        {
            int uu = tid >> 6, nn = tid & 63;
            float v = psum[(uu * 4 + 0) * 64 + nn] + psum[(uu * 4 + 1) * 64 + nn]
                    + psum[(uu * 4 + 2) * 64 + nn] + psum[(uu * 4 + 3) * 64 + nn];
            size_t o = (size_t)s * U_ * H_ + (size_t)(ub + uu) * H_ + gn * 64 + nn;
            out[o] = tanhf(pre[o] + v);
        }

        if (s < S_ - 1) {
            __syncthreads();
            if (tid == 0) {
                __threadfence();
                atomicAdd(&g_bar, 1u);
                unsigned target = (unsigned)(s + 1) * nblocks;
                while (*((volatile unsigned*)&g_bar) < target) { }
            }
            __syncthreads();
        }
    }
}

/* ------------------------------------------------------------------ */
/* 4. attention weights w[u,i,j] and row sums den[u,i]                 */
/* ------------------------------------------------------------------ */
__global__ void k_w(const float* __restrict__ t, const float* __restrict__ s)
{
    const int i = blockIdx.x, u = blockIdx.y;
    const int j = threadIdx.x;            /* 256 == S */
    __shared__ float red[256];

    float wv = 0.0f;
    if (j <= i) {
        float dt = t[i * U_ + u] - t[j * U_ + u];
        float d0 = s[((size_t)i * U_ + u) * 2 + 0] - s[((size_t)j * U_ + u) * 2 + 0];
        float d1 = s[((size_t)i * U_ + u) * 2 + 1] - s[((size_t)j * U_ + u) * 2 + 1];
        float ds = sqrtf(d0 * d0 + d1 * d1);
        float ft = (cosf(dt * (2.0f * PI_F / 86400.0f)) + 1.0f) * 0.5f
                 * expf(-(dt / 86400.0f) * 0.1f);
        float fs = expf(-ds * 100.0f);
        wv = ft * fs + 1e-10f;
    }
    g_w[((size_t)u * S_ + i) * S_ + j] = wv;

    red[j] = wv;
    __syncthreads();
    for (int off = 128; off > 0; off >>= 1) {
        if (j < off) red[j] += red[j + off];
        __syncthreads();
    }
    if (j == 0) g_den[u * S_ + i] = red[0];
}

/* ------------------------------------------------------------------ */
/* 5. weighted causal sum: outw[i,u,:] = (sum_j w*out[j,u,:]) / den    */
/* block = (i-tile of 8, u); 512 threads = h                           */
/* ------------------------------------------------------------------ */
__global__ __launch_bounds__(512)
void k_att()
{
    __shared__ float wsh[8 * 64];
    const int it = blockIdx.x;         /* 0..31 */
    const int u  = blockIdx.y;
    const int i0 = it * 8;
    const int h  = threadIdx.x;        /* 0..511 */
    const float* wb = g_w + (size_t)u * S_ * S_;

    float acc[8];
#pragma unroll
    for (int ii = 0; ii < 8; ii++) acc[ii] = 0.0f;

    const int jend = i0 + 8;
    for (int j0 = 0; j0 < jend; j0 += 64) {
        int ii = h >> 6, jj = h & 63;
        wsh[h] = wb[(size_t)(i0 + ii) * S_ + j0 + jj];
        __syncthreads();
        int jcnt = (jend - j0 < 64) ? (jend - j0) : 64;
        for (int q = 0; q < jcnt; q++) {
            float ov = g_out[((size_t)(j0 + q) * U_ + u) * H_ + h];
#pragma unroll
            for (int ii2 = 0; ii2 < 8; ii2++)
                acc[ii2] += wsh[ii2 * 64 + q] * ov;
        }
        __syncthreads();
    }
#pragma unroll
    for (int ii = 0; ii < 8; ii++) {
        float d = g_den[u * S_ + i0 + ii];
        g_outw[((size_t)(i0 + ii) * U_ + u) * H_ + h] = acc[ii] / d;
    }
}

/* ------------------------------------------------------------------ */
/* 6. gather A3[m, 0:1280] = [ outw[m] | user_w[au[u]] | T[yts[m]] ]   */
/* ------------------------------------------------------------------ */
__global__ void k_gather3(const float* __restrict__ user_w,
                          const int*   __restrict__ au,
                          const int*   __restrict__ yts)
{
    const int m  = blockIdx.x;
    const int u  = m & (U_ - 1);
    const int uw = au[u];
    const int ts = yts[m];
    for (int c = threadIdx.x; c < K3; c += blockDim.x) {
        float v;
        if (c < H_)            v = g_outw[(size_t)m * H_ + c];
        else if (c < 2 * H_)   v = user_w[(size_t)uw * H_ + (c - H_)];
        else                   v = g_T[ts * H2_ + (c - 2 * H_)];
        g_A3[(size_t)m * K3 + c] = v;
    }
}

/* ------------------------------------------------------------------ */
/* 7. copy h_final = out[S-1]                                          */
/* ------------------------------------------------------------------ */
__global__ void k_hfinal(float* __restrict__ dst)
{
    int i = blockIdx.x * blockDim.x + threadIdx.x;
    if (i < U_ * H_) dst[i] = g_out[(size_t)(S_ - 1) * U_ * H_ + i];
}

/* ------------------------------------------------------------------ */
extern "C" void kernel_launch(void* const* d_in, const int* in_sizes, int n_in,
                              void* d_out, int out_size)
{
    const int*   x        = (const int*)  d_in[0];
    const float* t        = (const float*)d_in[1];
    const int*   t_slot   = (const int*)  d_in[2];
    const float* s        = (const float*)d_in[3];
    const int*   y_t_slot = (const int*)  d_in[5];
    const float* h0       = (const float*)d_in[7];
    const int*   act_user = (const int*)  d_in[8];
    const int*   wm       = (const int*)  d_in[9];
    const float* wwi      = (const float*)d_in[10];
    const float* sigma    = (const float*)d_in[11];
    const float* enc_w    = (const float*)d_in[12];
    const float* user_w   = (const float*)d_in[13];
    const float* wenc     = (const float*)d_in[14];
    const float* fcpt_w   = (const float*)d_in[15];
    const float* fcpt_b   = (const float*)d_in[16];
    const float* W_ih     = (const float*)d_in[17];
    const float* W_hh     = (const float*)d_in[18];
    const float* b_ih     = (const float*)d_in[19];
    const float* b_hh     = (const float*)d_in[20];
    const float* fc_w     = (const float*)d_in[21];
    const float* fc_b     = (const float*)d_in[22];
    float* out = (float*)d_out;

    void *pA1, *pPoi, *pPre, *pOut, *pA3;
    cudaGetSymbolAddress(&pA1,  g_A1);
    cudaGetSymbolAddress(&pPoi, g_poi);
    cudaGetSymbolAddress(&pPre, g_pre);
    cudaGetSymbolAddress(&pOut, g_out);
    cudaGetSymbolAddress(&pA3,  g_A3);

    /* 1. time-embedding table */
    k_week<<<168, 256>>>(sigma, wwi, wm, wenc);

    /* 2. gather + front GEMMs */
    k_gather1<<<MSU, 256>>>(x, t_slot, enc_w);
    sgemm_bias<<<dim3(512 / 128, MSU / 128), 256>>>(
        (const float*)pA1, fcpt_w, fcpt_b, nullptr, (float*)pPoi, MSU, H_, KPT);
    sgemm_bias<<<dim3(512 / 128, MSU / 128), 256>>>(
        (const float*)pPoi, W_ih, b_ih, b_hh, (float*)pPre, MSU, H_, H_);

    /* 3. RNN (persistent, grid barrier) */
    k_zero_bar<<<1, 1>>>();
    cudaFuncSetAttribute(k_rnn, cudaFuncAttributeMaxDynamicSharedMemorySize, 131072);
    k_rnn<<<128, 256, 131072>>>((const float*)pPre, W_hh, h0, (float*)pOut);

    /* 4-5. spatiotemporal attention */
    k_w<<<dim3(S_, U_), 256>>>(t, s);
    k_att<<<dim3(S_ / 8, U_), 512>>>();

    /* 6. final projection */
    k_gather3<<<MSU, 256>>>(user_w, act_user, y_t_slot);
    sgemm_bias<<<dim3((V_ + 127) / 128, MSU / 128), 256>>>(
        (const float*)pA3, fc_w, fc_b, nullptr, out, MSU, V_, K3);

    /* 7. h_final tail */
    size_t yelems = (size_t)S_ * U_ * V_;
    if ((size_t)out_size >= yelems + U_ * H_)
        k_hfinal<<<(U_ * H_ + 255) / 256, 256>>>(out + yelems);
}

// round 3
// speedup vs baseline: 1.8013x; 1.8013x over previous
#include <cuda_runtime.h>
#include <cuda_bf16.h>
#include <math.h>
#include <stdint.h>

#define S_  256
#define U_  64
#define H_  512
#define H2_ 256
#define V_  5000
#define KPT 768     /* H + H2 */
#define K3  1280    /* 2H + H2 */
#define MSU 16384   /* S*U */
#define VPAD 5120
#define PI_F 3.14159265358979323846f

/* ------------------------------------------------------------------ */
/* scratch (device globals; allocation-free)                           */
/* ------------------------------------------------------------------ */
__device__ float         g_T    [168 * H2_];
__device__ __nv_bfloat16 g_A1h  [(size_t)MSU * KPT];
__device__ __nv_bfloat16 g_A1l  [(size_t)MSU * KPT];
__device__ __nv_bfloat16 g_poih [(size_t)MSU * H_];
__device__ __nv_bfloat16 g_poil [(size_t)MSU * H_];
__device__ float         g_pre  [(size_t)MSU * H_];
__device__ float         g_out  [(size_t)MSU * H_];
__device__ float         g_w    [(size_t)U_ * S_ * S_];
__device__ float         g_den  [(size_t)U_ * S_];
__device__ float         g_outw [(size_t)MSU * H_];
__device__ __nv_bfloat16 g_A3h  [(size_t)MSU * K3];
__device__ __nv_bfloat16 g_A3l  [(size_t)MSU * K3];
__device__ __nv_bfloat16 g_fcpth[(size_t)512 * KPT];
__device__ __nv_bfloat16 g_fcptl[(size_t)512 * KPT];
__device__ __nv_bfloat16 g_wihh [(size_t)512 * H_];
__device__ __nv_bfloat16 g_wihl [(size_t)512 * H_];
__device__ __nv_bfloat16 g_fcwh [(size_t)VPAD * K3];
__device__ __nv_bfloat16 g_fcwl [(size_t)VPAD * K3];
__device__ unsigned g_bar;

/* ------------------------------------------------------------------ */
/* helpers                                                             */
/* ------------------------------------------------------------------ */
__device__ __forceinline__ uint32_t smem_u32(const void* p) {
    uint32_t a;
    asm("{ .reg .u64 t; cvta.to.shared.u64 t, %1; cvt.u32.u64 %0, t; }"
        : "=r"(a) : "l"(p));
    return a;
}

#define CP_ASYNC16(dst, src) \
    asm volatile("cp.async.cg.shared.global [%0], [%1], 16;" :: "r"(dst), "l"(src))
#define CP_COMMIT() asm volatile("cp.async.commit_group;" ::: "memory")
#define CP_WAIT(n)  asm volatile("cp.async.wait_group %0;" :: "n"(n) : "memory")

#define LDS32(v, addr) \
    asm volatile("ld.shared.b32 %0, [%1];" : "=r"(v) : "r"(addr))

__device__ __forceinline__ void mma16816(float* c, const uint32_t* a, const uint32_t* b)
{
    asm volatile(
        "mma.sync.aligned.m16n8k16.row.col.f32.bf16.bf16.f32 "
        "{%0,%1,%2,%3}, {%4,%5,%6,%7}, {%8,%9}, {%0,%1,%2,%3};"
        : "+f"(c[0]), "+f"(c[1]), "+f"(c[2]), "+f"(c[3])
        : "r"(a[0]), "r"(a[1]), "r"(a[2]), "r"(a[3]), "r"(b[0]), "r"(b[1]));
}

__device__ __forceinline__ void split2(float v, __nv_bfloat16& h, __nv_bfloat16& l)
{
    h = __float2bfloat16(v);
    l = __float2bfloat16(v - __bfloat162float(h));
}

/* ------------------------------------------------------------------ */
/* split-bf16 HMMA GEMM:  C[M,Nreal] = A[M,K] @ B[Npad,K]^T + bias     */
/* BM=128, BN=256, BK=32, 256 threads (8 warps 2Mx4N), double-buffered */
/* 3 terms: Ah.Bh + Ah.Bl + Al.Bh (fp32 accum)                          */
/* ------------------------------------------------------------------ */
#define SWH 40                         /* smem row stride in halves    */
#define STAGE_B  61440                 /* bytes per stage              */
#define OFF_AL   10240
#define OFF_BH   20480
#define OFF_BL   40960
#define GEMM_SMEM (2 * STAGE_B)

__global__ __launch_bounds__(256, 1)
void hmma_gemm(const __nv_bfloat16* __restrict__ Ah, const __nv_bfloat16* __restrict__ Al,
               const __nv_bfloat16* __restrict__ Bh, const __nv_bfloat16* __restrict__ Bl,
               const float* __restrict__ bias1, const float* __restrict__ bias2,
               float* __restrict__ Cf,
               __nv_bfloat16* __restrict__ Ch, __nv_bfloat16* __restrict__ Cl,
               int K, int Nreal)
{
    extern __shared__ char smem[];
    const uint32_t sbase = smem_u32(smem);
    const int tid  = threadIdx.x;
    const int m0   = blockIdx.y * 128;
    const int n0   = blockIdx.x * 256;
    const int warp = tid >> 5, lane = tid & 31;
    const int wm = warp >> 2, wn = warp & 3;
    const int g  = lane >> 2, tig = lane & 3;
    const int L = K >> 5;

    float acc[4][8][4];
#pragma unroll
    for (int mi = 0; mi < 4; mi++)
#pragma unroll
        for (int ni = 0; ni < 8; ni++)
#pragma unroll
            for (int q = 0; q < 4; q++) acc[mi][ni][q] = 0.0f;

    /* ---- stage loader ---- */
    auto load_stage = [&](int chunk, int buf) {
        const uint32_t sg = sbase + (uint32_t)buf * STAGE_B;
        const int k0 = chunk << 5;
#pragma unroll 2
        for (int idx = tid; idx < 512; idx += 256) {
            int r = idx >> 2, c = idx & 3;
            uint32_t dsto = (uint32_t)(r * SWH + c * 8) * 2u;
            size_t srco = (size_t)(m0 + r) * K + k0 + c * 8;
            CP_ASYNC16(sg + dsto,            Ah + srco);
            CP_ASYNC16(sg + OFF_AL + dsto,   Al + srco);
        }
#pragma unroll 4
        for (int idx = tid; idx < 1024; idx += 256) {
            int r = idx >> 2, c = idx & 3;
            uint32_t dsto = (uint32_t)(r * SWH + c * 8) * 2u;
            size_t srco = (size_t)(n0 + r) * K + k0 + c * 8;
            CP_ASYNC16(sg + OFF_BH + dsto,   Bh + srco);
            CP_ASYNC16(sg + OFF_BL + dsto,   Bl + srco);
        }
        CP_COMMIT();
    };

    load_stage(0, 0);

    for (int i = 0; i < L; i++) {
        if (i + 1 < L) { load_stage(i + 1, (i + 1) & 1); CP_WAIT(1); }
        else           { CP_WAIT(0); }
        __syncthreads();

        const uint32_t sg = sbase + (uint32_t)(i & 1) * STAGE_B;
#pragma unroll
        for (int ks = 0; ks < 2; ks++) {
            const int kc = ks * 16 + tig * 2;
            uint32_t ah[4][4], al[4][4], bb[8][2];
            /* A hi fragments */
#pragma unroll
            for (int mi = 0; mi < 4; mi++) {
                uint32_t a0 = sg + (uint32_t)((wm * 64 + mi * 16 + g) * SWH + kc) * 2u;
                LDS32(ah[mi][0], a0);
                LDS32(ah[mi][1], a0 + 8u * SWH * 2u);
                LDS32(ah[mi][2], a0 + 16u);
                LDS32(ah[mi][3], a0 + 8u * SWH * 2u + 16u);
            }
            /* B hi fragments + main term */
#pragma unroll
            for (int ni = 0; ni < 8; ni++) {
                uint32_t b0 = sg + OFF_BH + (uint32_t)((wn * 64 + ni * 8 + g) * SWH + kc) * 2u;
                LDS32(bb[ni][0], b0);
                LDS32(bb[ni][1], b0 + 16u);
            }
#pragma unroll
            for (int mi = 0; mi < 4; mi++)
#pragma unroll
                for (int ni = 0; ni < 8; ni++)
                    mma16816(acc[mi][ni], ah[mi], bb[ni]);
            /* A lo x B hi */
#pragma unroll
            for (int mi = 0; mi < 4; mi++) {
                uint32_t a0 = sg + OFF_AL + (uint32_t)((wm * 64 + mi * 16 + g) * SWH + kc) * 2u;
                LDS32(al[mi][0], a0);
                LDS32(al[mi][1], a0 + 8u * SWH * 2u);
                LDS32(al[mi][2], a0 + 16u);
                LDS32(al[mi][3], a0 + 8u * SWH * 2u + 16u);
            }
#pragma unroll
            for (int mi = 0; mi < 4; mi++)
#pragma unroll
                for (int ni = 0; ni < 8; ni++)
                    mma16816(acc[mi][ni], al[mi], bb[ni]);
            /* A hi x B lo (reuse bb regs) */
#pragma unroll
            for (int ni = 0; ni < 8; ni++) {
                uint32_t b0 = sg + OFF_BL + (uint32_t)((wn * 64 + ni * 8 + g) * SWH + kc) * 2u;
                LDS32(bb[ni][0], b0);
                LDS32(bb[ni][1], b0 + 16u);
            }
#pragma unroll
            for (int mi = 0; mi < 4; mi++)
#pragma unroll
                for (int ni = 0; ni < 8; ni++)
                    mma16816(acc[mi][ni], ah[mi], bb[ni]);
        }
        __syncthreads();
    }

    /* ---- epilogue ---- */
#pragma unroll
    for (int mi = 0; mi < 4; mi++) {
        const int row0 = m0 + wm * 64 + mi * 16 + g;
#pragma unroll
        for (int ni = 0; ni < 8; ni++) {
            const int n = n0 + wn * 64 + ni * 8 + tig * 2;
#pragma unroll
            for (int q = 0; q < 4; q++) {
                int rr = row0 + ((q >= 2) ? 8 : 0);
                int nn = n + (q & 1);
                if (nn >= Nreal) continue;
                float f = acc[mi][ni][q] + bias1[nn] + (bias2 ? bias2[nn] : 0.0f);
                if (Cf) {
                    Cf[(size_t)rr * Nreal + nn] = f;
                } else {
                    __nv_bfloat16 hi, lo;
                    split2(f, hi, lo);
                    Ch[(size_t)rr * Nreal + nn] = hi;
                    Cl[(size_t)rr * Nreal + nn] = lo;
                }
            }
        }
    }
}

/* ------------------------------------------------------------------ */
/* weight split: dst[r<rows] = split(src), pad rows zeroed             */
/* ------------------------------------------------------------------ */
__global__ void k_splitW(const float* __restrict__ src,
                         __nv_bfloat16* __restrict__ dh, __nv_bfloat16* __restrict__ dl,
                         int rows, int K, int padRows)
{
    size_t total = (size_t)padRows * K;
    for (size_t idx = (size_t)blockIdx.x * blockDim.x + threadIdx.x;
         idx < total; idx += (size_t)gridDim.x * blockDim.x) {
        int r = (int)(idx / K);
        float v = (r < rows) ? src[idx] : 0.0f;
        __nv_bfloat16 hi, lo;
        split2(v, hi, lo);
        dh[idx] = hi; dl[idx] = lo;
    }
}

/* ------------------------------------------------------------------ */
/* 1. week distribution + time-embedding table T[168][H2]              */
/* ------------------------------------------------------------------ */
__global__ void k_week(const float* __restrict__ sigma,
                       const float* __restrict__ wwi,
                       const int*   __restrict__ wm,
                       const float* __restrict__ wenc)
{
    const int slot = blockIdx.x;
    const int tid  = threadIdx.x;
    __shared__ float ww[168];
    __shared__ float red[256];

    float sig    = fabsf(sigma[slot]);
    float inv2s2 = 1.0f / (2.0f * sig * sig);
    float coef   = rsqrtf(2.0f * PI_F * sig * sig);

    float v = 0.0f;
    if (tid < 168) {
        float x = wwi[slot * 168 + tid];
        v = coef * expf(-x * x * inv2s2);
        ww[tid] = v;
    }
    red[tid] = v;
    __syncthreads();
    for (int off = 128; off > 0; off >>= 1) {
        if (tid < off) red[tid] += red[tid + off];
        __syncthreads();
    }
    const float inv = 1.0f / red[0];

    float acc = 0.0f;
    for (int k = 0; k < 168; k++) {
        int row = wm[slot * 168 + k];
        acc += (ww[k] * inv) * wenc[row * H2_ + tid];
    }
    g_T[slot * H2_ + tid] = acc;
}

/* ------------------------------------------------------------------ */
/* 2. gather + split A1[m, 0:768] = [ enc_w[x[m]] | T[t_slot[m]] ]     */
/* ------------------------------------------------------------------ */
__global__ void k_gather1(const int* __restrict__ x,
                          const int* __restrict__ t_slot,
                          const float* __restrict__ enc_w)
{
    const int m  = blockIdx.x;
    const int xm = x[m];
    const int ts = t_slot[m];
    for (int c = threadIdx.x; c < KPT; c += blockDim.x) {
        float v = (c < H_) ? enc_w[(size_t)xm * H_ + c]
                           : g_T[ts * H2_ + (c - H_)];
        __nv_bfloat16 hi, lo;
        split2(v, hi, lo);
        g_A1h[(size_t)m * KPT + c] = hi;
        g_A1l[(size_t)m * KPT + c] = lo;
    }
}

/* ------------------------------------------------------------------ */
/* barrier counter reset                                               */
/* ------------------------------------------------------------------ */
__global__ void k_zero_bar() { g_bar = 0u; }

/* ------------------------------------------------------------------ */
/* 3. persistent RNN:  out[s] = tanh( pre[s] + out[s-1] @ W_hh^T )     */
/* ------------------------------------------------------------------ */
__global__ __launch_bounds__(256, 1)
void k_rnn(const float* __restrict__ pre, const float* __restrict__ Whh,
           const float* __restrict__ h0, float* __restrict__ out)
{
    extern __shared__ float sh[];
    const int tid = threadIdx.x;
    const int gu  = blockIdx.x >> 3;
    const int gn  = blockIdx.x & 7;
    const int n_l = tid & 63;
    const int kq  = tid >> 6;
    const unsigned nblocks = gridDim.x;

    const float* Wbase = Whh + (size_t)(gn * 64) * H_;
    for (int idx = tid * 4; idx < 64 * H_; idx += 256 * 4)
        *(float4*)&sh[idx] = *(const float4*)&Wbase[idx];
    __syncthreads();

    float wreg[128];
#pragma unroll
    for (int i = 0; i < 128; i++)
        wreg[i] = sh[n_l * H_ + kq * 128 + i];
    __syncthreads();

    float* hsh  = sh;
    float* psum = sh + 2048;
    const int ub = gu * 4;

    for (int s = 0; s < S_; s++) {
        const float* hp = (s == 0) ? h0 : (out + (size_t)(s - 1) * U_ * H_);
        for (int idx = tid; idx < 4 * H_; idx += 256) {
            int uu = idx >> 9, k = idx & 511;
            hsh[idx] = __ldcg(&hp[(size_t)(ub + uu) * H_ + k]);
        }
        __syncthreads();

#pragma unroll
        for (int uu = 0; uu < 4; uu++) {
            const float* hrow = hsh + uu * H_ + kq * 128;
            float a = 0.0f;
#pragma unroll
            for (int i = 0; i < 128; i++) a += hrow[i] * wreg[i];
            psum[(uu * 4 + kq) * 64 + n_l] = a;
        }
        __syncthreads();

        {
            int uu = tid >> 6, nn = tid & 63;
            float v = psum[(uu * 4 + 0) * 64 + nn] + psum[(uu * 4 + 1) * 64 + nn]
                    + psum[(uu * 4 + 2) * 64 + nn] + psum[(uu * 4 + 3) * 64 + nn];
            size_t o = (size_t)s * U_ * H_ + (size_t)(ub + uu) * H_ + gn * 64 + nn;
            out[o] = tanhf(pre[o] + v);
        }

        if (s < S_ - 1) {
            __syncthreads();
            if (tid == 0) {
                __threadfence();
                atomicAdd(&g_bar, 1u);
                unsigned target = (unsigned)(s + 1) * nblocks;
                while (*((volatile unsigned*)&g_bar) < target) { }
            }
            __syncthreads();
        }
    }
}

/* ------------------------------------------------------------------ */
/* 4. attention weights w[u,i,j] and row sums den[u,i]                 */
/* ------------------------------------------------------------------ */
__global__ void k_w(const float* __restrict__ t, const float* __restrict__ s)
{
    const int i = blockIdx.x, u = blockIdx.y;
    const int j = threadIdx.x;
    __shared__ float red[256];

    float wv = 0.0f;
    if (j <= i) {
        float dt = t[i * U_ + u] - t[j * U_ + u];
        float d0 = s[((size_t)i * U_ + u) * 2 + 0] - s[((size_t)j * U_ + u) * 2 + 0];
        float d1 = s[((size_t)i * U_ + u) * 2 + 1] - s[((size_t)j * U_ + u) * 2 + 1];
        float ds = sqrtf(d0 * d0 + d1 * d1);
        float ft = (cosf(dt * (2.0f * PI_F / 86400.0f)) + 1.0f) * 0.5f
                 * expf(-(dt / 86400.0f) * 0.1f);
        float fs = expf(-ds * 100.0f);
        wv = ft * fs + 1e-10f;
    }
    g_w[((size_t)u * S_ + i) * S_ + j] = wv;

    red[j] = wv;
    __syncthreads();
    for (int off = 128; off > 0; off >>= 1) {
        if (j < off) red[j] += red[j + off];
        __syncthreads();
    }
    if (j == 0) g_den[u * S_ + i] = red[0];
}

/* ------------------------------------------------------------------ */
/* 5. weighted causal sum: outw[i,u,:] = (sum_j w*out[j,u,:]) / den    */
/* ------------------------------------------------------------------ */
__global__ __launch_bounds__(512)
void k_att()
{
    __shared__ float wsh[8 * 64];
    const int it = blockIdx.x;
    const int u  = blockIdx.y;
    const int i0 = it * 8;
    const int h  = threadIdx.x;
    const float* wb = g_w + (size_t)u * S_ * S_;

    float acc[8];
#pragma unroll
    for (int ii = 0; ii < 8; ii++) acc[ii] = 0.0f;

    const int jend = i0 + 8;
    for (int j0 = 0; j0 < jend; j0 += 64) {
        int ii = h >> 6, jj = h & 63;
        wsh[h] = wb[(size_t)(i0 + ii) * S_ + j0 + jj];
        __syncthreads();
        int jcnt = (jend - j0 < 64) ? (jend - j0) : 64;
        for (int q = 0; q < jcnt; q++) {
            float ov = g_out[((size_t)(j0 + q) * U_ + u) * H_ + h];
#pragma unroll
            for (int ii2 = 0; ii2 < 8; ii2++)
                acc[ii2] += wsh[ii2 * 64 + q] * ov;
        }
        __syncthreads();
    }
#pragma unroll
    for (int ii = 0; ii < 8; ii++) {
        float d = g_den[u * S_ + i0 + ii];
        g_outw[((size_t)(i0 + ii) * U_ + u) * H_ + h] = acc[ii] / d;
    }
}

/* ------------------------------------------------------------------ */
/* 6. gather + split A3[m, 0:1280]                                     */
/* ------------------------------------------------------------------ */
__global__ void k_gather3(const float* __restrict__ user_w,
                          const int*   __restrict__ au,
                          const int*   __restrict__ yts)
{
    const int m  = blockIdx.x;
    const int u  = m & (U_ - 1);
    const int uw = au[u];
    const int ts = yts[m];
    for (int c = threadIdx.x; c < K3; c += blockDim.x) {
        float v;
        if (c < H_)            v = g_outw[(size_t)m * H_ + c];
        else if (c < 2 * H_)   v = user_w[(size_t)uw * H_ + (c - H_)];
        else                   v = g_T[ts * H2_ + (c - 2 * H_)];
        __nv_bfloat16 hi, lo;
        split2(v, hi, lo);
        g_A3h[(size_t)m * K3 + c] = hi;
        g_A3l[(size_t)m * K3 + c] = lo;
    }
}

/* ------------------------------------------------------------------ */
/* 7. copy h_final = out[S-1]                                          */
/* ------------------------------------------------------------------ */
__global__ void k_hfinal(float* __restrict__ dst)
{
    int i = blockIdx.x * blockDim.x + threadIdx.x;
    if (i < U_ * H_) dst[i] = g_out[(size_t)(S_ - 1) * U_ * H_ + i];
}

/* ------------------------------------------------------------------ */
extern "C" void kernel_launch(void* const* d_in, const int* in_sizes, int n_in,
                              void* d_out, int out_size)
{
    const int*   x        = (const int*)  d_in[0];
    const float* t        = (const float*)d_in[1];
    const int*   t_slot   = (const int*)  d_in[2];
    const float* s        = (const float*)d_in[3];
    const int*   y_t_slot = (const int*)  d_in[5];
    const float* h0       = (const float*)d_in[7];
    const int*   act_user = (const int*)  d_in[8];
    const int*   wm       = (const int*)  d_in[9];
    const float* wwi      = (const float*)d_in[10];
    const float* sigma    = (const float*)d_in[11];
    const float* enc_w    = (const float*)d_in[12];
    const float* user_w   = (const float*)d_in[13];
    const float* wenc     = (const float*)d_in[14];
    const float* fcpt_w   = (const float*)d_in[15];
    const float* fcpt_b   = (const float*)d_in[16];
    const float* W_ih     = (const float*)d_in[17];
    const float* W_hh     = (const float*)d_in[18];
    const float* b_ih     = (const float*)d_in[19];
    const float* b_hh     = (const float*)d_in[20];
    const float* fc_w     = (const float*)d_in[21];
    const float* fc_b     = (const float*)d_in[22];
    float* out = (float*)d_out;

    void *pA1h, *pA1l, *pPoih, *pPoil, *pPre, *pOut;
    void *pA3h, *pA3l, *pFcpth, *pFcptl, *pWihh, *pWihl, *pFcwh, *pFcwl;
    cudaGetSymbolAddress(&pA1h,  g_A1h);  cudaGetSymbolAddress(&pA1l,  g_A1l);
    cudaGetSymbolAddress(&pPoih, g_poih); cudaGetSymbolAddress(&pPoil, g_poil);
    cudaGetSymbolAddress(&pPre,  g_pre);  cudaGetSymbolAddress(&pOut,  g_out);
    cudaGetSymbolAddress(&pA3h,  g_A3h);  cudaGetSymbolAddress(&pA3l,  g_A3l);
    cudaGetSymbolAddress(&pFcpth, g_fcpth); cudaGetSymbolAddress(&pFcptl, g_fcptl);
    cudaGetSymbolAddress(&pWihh, g_wihh); cudaGetSymbolAddress(&pWihl, g_wihl);
    cudaGetSymbolAddress(&pFcwh, g_fcwh); cudaGetSymbolAddress(&pFcwl, g_fcwl);

    cudaFuncSetAttribute(hmma_gemm, cudaFuncAttributeMaxDynamicSharedMemorySize, GEMM_SMEM);
    cudaFuncSetAttribute(k_rnn,     cudaFuncAttributeMaxDynamicSharedMemorySize, 131072);

    /* 1. time-embedding table + weight splits */
    k_week<<<168, 256>>>(sigma, wwi, wm, wenc);
    k_splitW<<<256, 256>>>(fcpt_w, (__nv_bfloat16*)pFcpth, (__nv_bfloat16*)pFcptl, 512, KPT, 512);
    k_splitW<<<256, 256>>>(W_ih,   (__nv_bfloat16*)pWihh,  (__nv_bfloat16*)pWihl,  512, H_,  512);
    k_splitW<<<512, 256>>>(fc_w,   (__nv_bfloat16*)pFcwh,  (__nv_bfloat16*)pFcwl,  V_,  K3,  VPAD);

    /* 2. gather + front GEMMs (HMMA) */
    k_gather1<<<MSU, 256>>>(x, t_slot, enc_w);
    hmma_gemm<<<dim3(512 / 256, MSU / 128), 256, GEMM_SMEM>>>(
        (const __nv_bfloat16*)pA1h, (const __nv_bfloat16*)pA1l,
        (const __nv_bfloat16*)pFcpth, (const __nv_bfloat16*)pFcptl,
        fcpt_b, nullptr, nullptr,
        (__nv_bfloat16*)pPoih, (__nv_bfloat16*)pPoil, KPT, 512);
    hmma_gemm<<<dim3(512 / 256, MSU / 128), 256, GEMM_SMEM>>>(
        (const __nv_bfloat16*)pPoih, (const __nv_bfloat16*)pPoil,
        (const __nv_bfloat16*)pWihh, (const __nv_bfloat16*)pWihl,
        b_ih, b_hh, (float*)pPre, nullptr, nullptr, H_, 512);

    /* 3. RNN (persistent, grid barrier) */
    k_zero_bar<<<1, 1>>>();
    k_rnn<<<128, 256, 131072>>>((const float*)pPre, W_hh, h0, (float*)pOut);

    /* 4-5. spatiotemporal attention */
    k_w<<<dim3(S_, U_), 256>>>(t, s);
    k_att<<<dim3(S_ / 8, U_), 512>>>();

    /* 6. final projection (HMMA) */
    k_gather3<<<MSU, 256>>>(user_w, act_user, y_t_slot);
    hmma_gemm<<<dim3(VPAD / 256, MSU / 128), 256, GEMM_SMEM>>>(
        (const __nv_bfloat16*)pA3h, (const __nv_bfloat16*)pA3l,
        (const __nv_bfloat16*)pFcwh, (const __nv_bfloat16*)pFcwl,
        fc_b, nullptr, out, nullptr, nullptr, K3, V_);

    /* 7. h_final tail */
    size_t yelems = (size_t)S_ * U_ * V_;
    if ((size_t)out_size >= yelems + U_ * H_)
        k_hfinal<<<(U_ * H_ + 255) / 256, 256>>>(out + yelems);
}

// round 4
// speedup vs baseline: 2.1664x; 1.2027x over previous
#include <cuda_runtime.h>
#include <cuda_bf16.h>
#include <math.h>
#include <stdint.h>

#define S_  256
#define U_  64
#define H_  512
#define H2_ 256
#define V_  5000
#define MSU 16384   /* S*U */
#define VPAD 5120
#define PI_F 3.14159265358979323846f

/* ------------------------------------------------------------------ */
/* scratch (device globals; allocation-free)                           */
/* ------------------------------------------------------------------ */
__device__ float         g_T    [168 * H2_];
__device__ __nv_bfloat16 g_ench [(size_t)VPAD * H_];
__device__ __nv_bfloat16 g_encl [(size_t)VPAD * H_];
__device__ __nv_bfloat16 g_M1h  [(size_t)VPAD * H_];
__device__ __nv_bfloat16 g_M1l  [(size_t)VPAD * H_];
__device__ float         g_E2   [(size_t)VPAD * H_];
__device__ __nv_bfloat16 g_Th   [256 * H2_];
__device__ __nv_bfloat16 g_Tl   [256 * H2_];
__device__ __nv_bfloat16 g_N1h  [256 * H_];
__device__ __nv_bfloat16 g_N1l  [256 * H_];
__device__ float         g_T2   [256 * H_];
__device__ __nv_bfloat16 g_uwh  [128 * H_];
__device__ __nv_bfloat16 g_uwl  [128 * H_];
__device__ float         g_P2   [(size_t)128 * V_];
__device__ float         g_P3   [(size_t)256 * V_];
__device__ __nv_bfloat16 g_fcpAh[512 * H_];
__device__ __nv_bfloat16 g_fcpAl[512 * H_];
__device__ __nv_bfloat16 g_fcpBh[512 * H2_];
__device__ __nv_bfloat16 g_fcpBl[512 * H2_];
__device__ __nv_bfloat16 g_wihh [512 * H_];
__device__ __nv_bfloat16 g_wihl [512 * H_];
__device__ __nv_bfloat16 g_fcwAh[(size_t)VPAD * H_];
__device__ __nv_bfloat16 g_fcwAl[(size_t)VPAD * H_];
__device__ __nv_bfloat16 g_fcwBh[(size_t)VPAD * H_];
__device__ __nv_bfloat16 g_fcwBl[(size_t)VPAD * H_];
__device__ __nv_bfloat16 g_fcwCh[(size_t)VPAD * H2_];
__device__ __nv_bfloat16 g_fcwCl[(size_t)VPAD * H2_];
__device__ float         g_cvec [H_];
__device__ float         g_pre  [(size_t)MSU * H_];
__device__ float         g_out  [(size_t)MSU * H_];
__device__ float         g_w    [(size_t)U_ * S_ * S_];
__device__ float         g_den  [(size_t)U_ * S_];
__device__ __nv_bfloat16 g_owh  [(size_t)MSU * H_];
__device__ __nv_bfloat16 g_owl  [(size_t)MSU * H_];
__device__ unsigned g_bar;

/* ------------------------------------------------------------------ */
/* helpers                                                             */
/* ------------------------------------------------------------------ */
__device__ __forceinline__ uint32_t smem_u32(const void* p) {
    uint32_t a;
    asm("{ .reg .u64 t; cvta.to.shared.u64 t, %1; cvt.u32.u64 %0, t; }"
        : "=r"(a) : "l"(p));
    return a;
}

#define CP_ASYNC16(dst, src) \
    asm volatile("cp.async.cg.shared.global [%0], [%1], 16;" :: "r"(dst), "l"(src))
#define CP_COMMIT() asm volatile("cp.async.commit_group;" ::: "memory")
#define CP_WAIT(n)  asm volatile("cp.async.wait_group %0;" :: "n"(n) : "memory")

#define LDS32(v, addr) \
    asm volatile("ld.shared.b32 %0, [%1];" : "=r"(v) : "r"(addr))

__device__ __forceinline__ void mma16816(float* c, const uint32_t* a, const uint32_t* b)
{
    asm volatile(
        "mma.sync.aligned.m16n8k16.row.col.f32.bf16.bf16.f32 "
        "{%0,%1,%2,%3}, {%4,%5,%6,%7}, {%8,%9}, {%0,%1,%2,%3};"
        : "+f"(c[0]), "+f"(c[1]), "+f"(c[2]), "+f"(c[3])
        : "r"(a[0]), "r"(a[1]), "r"(a[2]), "r"(a[3]), "r"(b[0]), "r"(b[1]));
}

__device__ __forceinline__ void split2(float v, __nv_bfloat16& h, __nv_bfloat16& l)
{
    h = __float2bfloat16(v);
    l = __float2bfloat16(v - __bfloat162float(h));
}

/* ------------------------------------------------------------------ */
/* split-bf16 HMMA GEMM:  C[M,Nreal] = A[M,K] @ B[Npad,K]^T (+extras)  */
/* BM=128, BN=256, BK=32, 256 threads (8 warps 2Mx4N), double-buffered */
/* 3 terms: Ah.Bh + Ah.Bl + Al.Bh (fp32 accum)                          */
/* epilogue: + bias1[n] + add1[(m&63),n] + add2[idx2[m],n]             */
/* ------------------------------------------------------------------ */
#define SWH 40                         /* smem row stride in halves    */
#define STAGE_B  61440                 /* bytes per stage              */
#define OFF_AL   10240
#define OFF_BH   20480
#define OFF_BL   40960
#define GEMM_SMEM (2 * STAGE_B)

__global__ __launch_bounds__(256, 1)
void hmma_gemm(const __nv_bfloat16* __restrict__ Ah, const __nv_bfloat16* __restrict__ Al,
               const __nv_bfloat16* __restrict__ Bh, const __nv_bfloat16* __restrict__ Bl,
               const float* __restrict__ bias1,
               const float* __restrict__ add1,
               const float* __restrict__ add2, const int* __restrict__ idx2,
               float* __restrict__ Cf,
               __nv_bfloat16* __restrict__ Ch, __nv_bfloat16* __restrict__ Cl,
               int K, int Nreal)
{
    extern __shared__ char smem[];
    const uint32_t sbase = smem_u32(smem);
    const int tid  = threadIdx.x;
    const int m0   = blockIdx.y * 128;
    const int n0   = blockIdx.x * 256;
    const int warp = tid >> 5, lane = tid & 31;
    const int wm = warp >> 2, wn = warp & 3;
    const int g  = lane >> 2, tig = lane & 3;
    const int L = K >> 5;

    float acc[4][8][4];
#pragma unroll
    for (int mi = 0; mi < 4; mi++)
#pragma unroll
        for (int ni = 0; ni < 8; ni++)
#pragma unroll
            for (int q = 0; q < 4; q++) acc[mi][ni][q] = 0.0f;

    auto load_stage = [&](int chunk, int buf) {
        const uint32_t sg = sbase + (uint32_t)buf * STAGE_B;
        const int k0 = chunk << 5;
#pragma unroll 2
        for (int idx = tid; idx < 512; idx += 256) {
            int r = idx >> 2, c = idx & 3;
            uint32_t dsto = (uint32_t)(r * SWH + c * 8) * 2u;
            size_t srco = (size_t)(m0 + r) * K + k0 + c * 8;
            CP_ASYNC16(sg + dsto,            Ah + srco);
            CP_ASYNC16(sg + OFF_AL + dsto,   Al + srco);
        }
#pragma unroll 4
        for (int idx = tid; idx < 1024; idx += 256) {
            int r = idx >> 2, c = idx & 3;
            uint32_t dsto = (uint32_t)(r * SWH + c * 8) * 2u;
            size_t srco = (size_t)(n0 + r) * K + k0 + c * 8;
            CP_ASYNC16(sg + OFF_BH + dsto,   Bh + srco);
            CP_ASYNC16(sg + OFF_BL + dsto,   Bl + srco);
        }
        CP_COMMIT();
    };

    load_stage(0, 0);

    for (int i = 0; i < L; i++) {
        if (i + 1 < L) { load_stage(i + 1, (i + 1) & 1); CP_WAIT(1); }
        else           { CP_WAIT(0); }
        __syncthreads();

        const uint32_t sg = sbase + (uint32_t)(i & 1) * STAGE_B;
#pragma unroll
        for (int ks = 0; ks < 2; ks++) {
            const int kc = ks * 16 + tig * 2;
            uint32_t ah[4][4], al[4][4], bb[8][2];
#pragma unroll
            for (int mi = 0; mi < 4; mi++) {
                uint32_t a0 = sg + (uint32_t)((wm * 64 + mi * 16 + g) * SWH + kc) * 2u;
                LDS32(ah[mi][0], a0);
                LDS32(ah[mi][1], a0 + 8u * SWH * 2u);
                LDS32(ah[mi][2], a0 + 16u);
                LDS32(ah[mi][3], a0 + 8u * SWH * 2u + 16u);
            }
#pragma unroll
            for (int ni = 0; ni < 8; ni++) {
                uint32_t b0 = sg + OFF_BH + (uint32_t)((wn * 64 + ni * 8 + g) * SWH + kc) * 2u;
                LDS32(bb[ni][0], b0);
                LDS32(bb[ni][1], b0 + 16u);
            }
#pragma unroll
            for (int mi = 0; mi < 4; mi++)
#pragma unroll
                for (int ni = 0; ni < 8; ni++)
                    mma16816(acc[mi][ni], ah[mi], bb[ni]);
#pragma unroll
            for (int mi = 0; mi < 4; mi++) {
                uint32_t a0 = sg + OFF_AL + (uint32_t)((wm * 64 + mi * 16 + g) * SWH + kc) * 2u;
                LDS32(al[mi][0], a0);
                LDS32(al[mi][1], a0 + 8u * SWH * 2u);
                LDS32(al[mi][2], a0 + 16u);
                LDS32(al[mi][3], a0 + 8u * SWH * 2u + 16u);
            }
#pragma unroll
            for (int mi = 0; mi < 4; mi++)
#pragma unroll
                for (int ni = 0; ni < 8; ni++)
                    mma16816(acc[mi][ni], al[mi], bb[ni]);
#pragma unroll
            for (int ni = 0; ni < 8; ni++) {
                uint32_t b0 = sg + OFF_BL + (uint32_t)((wn * 64 + ni * 8 + g) * SWH + kc) * 2u;
                LDS32(bb[ni][0], b0);
                LDS32(bb[ni][1], b0 + 16u);
            }
#pragma unroll
            for (int mi = 0; mi < 4; mi++)
#pragma unroll
                for (int ni = 0; ni < 8; ni++)
                    mma16816(acc[mi][ni], ah[mi], bb[ni]);
        }
        __syncthreads();
    }

    /* ---- epilogue ---- */
#pragma unroll
    for (int mi = 0; mi < 4; mi++) {
        const int row0 = m0 + wm * 64 + mi * 16 + g;
        int i2[2] = { 0, 0 };
        if (add2) { i2[0] = idx2[row0]; i2[1] = idx2[row0 + 8]; }
#pragma unroll
        for (int ni = 0; ni < 8; ni++) {
            const int n = n0 + wn * 64 + ni * 8 + tig * 2;
#pragma unroll
            for (int q = 0; q < 4; q++) {
                int rr = row0 + ((q >= 2) ? 8 : 0);
                int nn = n + (q & 1);
                if (nn >= Nreal) continue;
                float f = acc[mi][ni][q];
                if (bias1) f += bias1[nn];
                if (add1)  f += add1[(size_t)(rr & 63) * Nreal + nn];
                if (add2)  f += add2[(size_t)i2[q >> 1] * Nreal + nn];
                if (Cf) {
                    Cf[(size_t)rr * Nreal + nn] = f;
                } else {
                    __nv_bfloat16 hi, lo;
                    split2(f, hi, lo);
                    Ch[(size_t)rr * Nreal + nn] = hi;
                    Cl[(size_t)rr * Nreal + nn] = lo;
                }
            }
        }
    }
}

/* ------------------------------------------------------------------ */
/* subview split: d*[r,c] = split(src[r, col0+c]) for r<rows else 0    */
/* ------------------------------------------------------------------ */
__global__ void k_split_sub(const float* __restrict__ src, int pitch, int col0,
                            int rows, int cols, int padRows,
                            __nv_bfloat16* __restrict__ dh, __nv_bfloat16* __restrict__ dl)
{
    size_t total = (size_t)padRows * cols;
    for (size_t idx = (size_t)blockIdx.x * blockDim.x + threadIdx.x;
         idx < total; idx += (size_t)gridDim.x * blockDim.x) {
        int r = (int)(idx / cols);
        int c = (int)(idx - (size_t)r * cols);
        float v = (r < rows) ? src[(size_t)r * pitch + col0 + c] : 0.0f;
        __nv_bfloat16 hi, lo;
        split2(v, hi, lo);
        dh[idx] = hi; dl[idx] = lo;
    }
}

/* ------------------------------------------------------------------ */
/* gathered user rows, split, padded to 128                            */
/* ------------------------------------------------------------------ */
__global__ void k_userw(const float* __restrict__ user_w, const int* __restrict__ au)
{
    const int u = blockIdx.x;            /* 0..127 */
    const int c = threadIdx.x;           /* 0..511 */
    float v = 0.0f;
    if (u < U_) v = user_w[(size_t)au[u] * H_ + c];
    __nv_bfloat16 hi, lo;
    split2(v, hi, lo);
    g_uwh[u * H_ + c] = hi;
    g_uwl[u * H_ + c] = lo;
}

/* ------------------------------------------------------------------ */
/* cvec[n] = b_ih[n] + b_hh[n] + sum_k fcpt_b[k] * W_ih[n,k]           */
/* ------------------------------------------------------------------ */
__global__ void k_cvec(const float* __restrict__ fcpt_b, const float* __restrict__ W_ih,
                       const float* __restrict__ b_ih, const float* __restrict__ b_hh)
{
    const int n = blockIdx.x * blockDim.x + threadIdx.x;
    if (n >= H_) return;
    float a = b_ih[n] + b_hh[n];
    for (int k = 0; k < H_; k++) a += fcpt_b[k] * W_ih[(size_t)n * H_ + k];
    g_cvec[n] = a;
}

/* ------------------------------------------------------------------ */
/* pre[m,c] = E2[x[m],c] + T2[ts[m],c] + cvec[c]                       */
/* ------------------------------------------------------------------ */
__global__ __launch_bounds__(512)
void k_pre(const int* __restrict__ x, const int* __restrict__ ts)
{
    const int m = blockIdx.x;
    const int c = threadIdx.x;
    const int xm = x[m], tm = ts[m];
    g_pre[(size_t)m * H_ + c] =
        g_E2[(size_t)xm * H_ + c] + g_T2[(size_t)tm * H_ + c] + g_cvec[c];
}

/* ------------------------------------------------------------------ */
/* 1. week distribution + time-embedding table T[168][H2]              */
/* ------------------------------------------------------------------ */
__global__ void k_week(const float* __restrict__ sigma,
                       const float* __restrict__ wwi,
                       const int*   __restrict__ wm,
                       const float* __restrict__ wenc)
{
    const int slot = blockIdx.x;
    const int tid  = threadIdx.x;
    __shared__ float ww[168];
    __shared__ float red[256];

    float sig    = fabsf(sigma[slot]);
    float inv2s2 = 1.0f / (2.0f * sig * sig);
    float coef   = rsqrtf(2.0f * PI_F * sig * sig);

    float v = 0.0f;
    if (tid < 168) {
        float x = wwi[slot * 168 + tid];
        v = coef * expf(-x * x * inv2s2);
        ww[tid] = v;
    }
    red[tid] = v;
    __syncthreads();
    for (int off = 128; off > 0; off >>= 1) {
        if (tid < off) red[tid] += red[tid + off];
        __syncthreads();
    }
    const float inv = 1.0f / red[0];

    float acc = 0.0f;
    for (int k = 0; k < 168; k++) {
        int row = wm[slot * 168 + k];
        acc += (ww[k] * inv) * wenc[row * H2_ + tid];
    }
    g_T[slot * H2_ + tid] = acc;
}

/* ------------------------------------------------------------------ */
/* barrier counter reset                                               */
/* ------------------------------------------------------------------ */
__global__ void k_zero_bar() { g_bar = 0u; }

/* ------------------------------------------------------------------ */
/* 3. persistent RNN:  out[s] = tanh( pre[s] + out[s-1] @ W_hh^T )     */
/* 128 blocks = 16 u-groups (4 u) x 8 n-groups (64 n), W in registers  */
/* ------------------------------------------------------------------ */
__global__ __launch_bounds__(256, 1)
void k_rnn(const float* __restrict__ pre, const float* __restrict__ Whh,
           const float* __restrict__ h0, float* __restrict__ out)
{
    extern __shared__ float sh[];
    const int tid = threadIdx.x;
    const int gu  = blockIdx.x >> 3;
    const int gn  = blockIdx.x & 7;
    const int n_l = tid & 63;
    const int kq  = tid >> 6;
    const unsigned nblocks = gridDim.x;

    const float* Wbase = Whh + (size_t)(gn * 64) * H_;
    for (int idx = tid * 4; idx < 64 * H_; idx += 256 * 4)
        *(float4*)&sh[idx] = *(const float4*)&Wbase[idx];
    __syncthreads();

    float4 wreg[32];
#pragma unroll
    for (int i = 0; i < 32; i++)
        wreg[i] = *(const float4*)&sh[n_l * H_ + kq * 128 + i * 4];
    __syncthreads();

    float* hsh  = sh;          /* 4 x 512 floats */
    float* psum = sh + 2048;   /* 16 x 64        */
    const int ub = gu * 4;

    for (int s = 0; s < S_; s++) {
        const float* hp = (s == 0) ? (h0 + (size_t)ub * H_)
                                   : (out + (size_t)(s - 1) * U_ * H_ + (size_t)ub * H_);
        {
            const float4* src = (const float4*)hp;
            float4* dst = (float4*)hsh;
            for (int idx = tid; idx < 512; idx += 256)
                dst[idx] = __ldcg(&src[idx]);
        }
        __syncthreads();

        {
            const float4* h0p = (const float4*)(hsh + 0 * H_ + kq * 128);
            const float4* h1p = (const float4*)(hsh + 1 * H_ + kq * 128);
            const float4* h2p = (const float4*)(hsh + 2 * H_ + kq * 128);
            const float4* h3p = (const float4*)(hsh + 3 * H_ + kq * 128);
            float a0 = 0.f, a1 = 0.f, a2 = 0.f, a3 = 0.f;
            float b0 = 0.f, b1 = 0.f, b2 = 0.f, b3 = 0.f;
#pragma unroll
            for (int i = 0; i < 32; i += 2) {
                float4 w0 = wreg[i], w1 = wreg[i + 1];
                float4 x0 = h0p[i], y0 = h0p[i + 1];
                float4 x1 = h1p[i], y1 = h1p[i + 1];
                float4 x2 = h2p[i], y2 = h2p[i + 1];
                float4 x3 = h3p[i], y3 = h3p[i + 1];
                a0 += x0.x*w0.x + x0.y*w0.y + x0.z*w0.z + x0.w*w0.w;
                b0 += y0.x*w1.x + y0.y*w1.y + y0.z*w1.z + y0.w*w1.w;
                a1 += x1.x*w0.x + x1.y*w0.y + x1.z*w0.z + x1.w*w0.w;
                b1 += y1.x*w1.x + y1.y*w1.y + y1.z*w1.z + y1.w*w1.w;
                a2 += x2.x*w0.x + x2.y*w0.y + x2.z*w0.z + x2.w*w0.w;
                b2 += y2.x*w1.x + y2.y*w1.y + y2.z*w1.z + y2.w*w1.w;
                a3 += x3.x*w0.x + x3.y*w0.y + x3.z*w0.z + x3.w*w0.w;
                b3 += y3.x*w1.x + y3.y*w1.y + y3.z*w1.z + y3.w*w1.w;
            }
            psum[(0 * 4 + kq) * 64 + n_l] = a0 + b0;
            psum[(1 * 4 + kq) * 64 + n_l] = a1 + b1;
            psum[(2 * 4 + kq) * 64 + n_l] = a2 + b2;
            psum[(3 * 4 + kq) * 64 + n_l] = a3 + b3;
        }
        __syncthreads();

        {
            int uu = tid >> 6, nn = tid & 63;
            float v = psum[(uu * 4 + 0) * 64 + nn] + psum[(uu * 4 + 1) * 64 + nn]
                    + psum[(uu * 4 + 2) * 64 + nn] + psum[(uu * 4 + 3) * 64 + nn];
            size_t o = (size_t)s * U_ * H_ + (size_t)(ub + uu) * H_ + gn * 64 + nn;
            out[o] = tanhf(pre[o] + v);
        }

        if (s < S_ - 1) {
            __syncthreads();
            if (tid == 0) {
                __threadfence();
                atomicAdd(&g_bar, 1u);
                unsigned target = (unsigned)(s + 1) * nblocks;
                while (*((volatile unsigned*)&g_bar) < target) { }
            }
            __syncthreads();
        }
    }
}

/* ------------------------------------------------------------------ */
/* 4. attention weights w[u,i,j] and row sums den[u,i]                 */
/* ------------------------------------------------------------------ */
__global__ void k_w(const float* __restrict__ t, const float* __restrict__ s)
{
    const int i = blockIdx.x, u = blockIdx.y;
    const int j = threadIdx.x;
    __shared__ float red[256];

    float wv = 0.0f;
    if (j <= i) {
        float dt = t[i * U_ + u] - t[j * U_ + u];
        float d0 = s[((size_t)i * U_ + u) * 2 + 0] - s[((size_t)j * U_ + u) * 2 + 0];
        float d1 = s[((size_t)i * U_ + u) * 2 + 1] - s[((size_t)j * U_ + u) * 2 + 1];
        float ds = sqrtf(d0 * d0 + d1 * d1);
        float ft = (cosf(dt * (2.0f * PI_F / 86400.0f)) + 1.0f) * 0.5f
                 * expf(-(dt / 86400.0f) * 0.1f);
        float fs = expf(-ds * 100.0f);
        wv = ft * fs + 1e-10f;
    }
    g_w[((size_t)u * S_ + i) * S_ + j] = wv;

    red[j] = wv;
    __syncthreads();
    for (int off = 128; off > 0; off >>= 1) {
        if (j < off) red[j] += red[j + off];
        __syncthreads();
    }
    if (j == 0) g_den[u * S_ + i] = red[0];
}

/* ------------------------------------------------------------------ */
/* 5. weighted causal sum -> split bf16 outw                           */
/* ------------------------------------------------------------------ */
__global__ __launch_bounds__(512)
void k_att()
{
    __shared__ float wsh[8 * 64];
    const int it = blockIdx.x;
    const int u  = blockIdx.y;
    const int i0 = it * 8;
    const int h  = threadIdx.x;
    const float* wb = g_w + (size_t)u * S_ * S_;

    float acc[8];
#pragma unroll
    for (int ii = 0; ii < 8; ii++) acc[ii] = 0.0f;

    const int jend = i0 + 8;
    for (int j0 = 0; j0 < jend; j0 += 64) {
        int ii = h >> 6, jj = h & 63;
        wsh[h] = wb[(size_t)(i0 + ii) * S_ + j0 + jj];
        __syncthreads();
        int jcnt = (jend - j0 < 64) ? (jend - j0) : 64;
        for (int q = 0; q < jcnt; q++) {
            float ov = g_out[((size_t)(j0 + q) * U_ + u) * H_ + h];
#pragma unroll
            for (int ii2 = 0; ii2 < 8; ii2++)
                acc[ii2] += wsh[ii2 * 64 + q] * ov;
        }
        __syncthreads();
    }
#pragma unroll
    for (int ii = 0; ii < 8; ii++) {
        float d = g_den[u * S_ + i0 + ii];
        float f = acc[ii] / d;
        __nv_bfloat16 hi, lo;
        split2(f, hi, lo);
        size_t o = ((size_t)(i0 + ii) * U_ + u) * H_ + h;
        g_owh[o] = hi;
        g_owl[o] = lo;
    }
}

/* ------------------------------------------------------------------ */
/* 7. copy h_final = out[S-1]                                          */
/* ------------------------------------------------------------------ */
__global__ void k_hfinal(float* __restrict__ dst)
{
    int i = blockIdx.x * blockDim.x + threadIdx.x;
    if (i < U_ * H_) dst[i] = g_out[(size_t)(S_ - 1) * U_ * H_ + i];
}

/* ------------------------------------------------------------------ */
extern "C" void kernel_launch(void* const* d_in, const int* in_sizes, int n_in,
                              void* d_out, int out_size)
{
    const int*   x        = (const int*)  d_in[0];
    const float* t        = (const float*)d_in[1];
    const int*   t_slot   = (const int*)  d_in[2];
    const float* s        = (const float*)d_in[3];
    const int*   y_t_slot = (const int*)  d_in[5];
    const float* h0       = (const float*)d_in[7];
    const int*   act_user = (const int*)  d_in[8];
    const int*   wm       = (const int*)  d_in[9];
    const float* wwi      = (const float*)d_in[10];
    const float* sigma    = (const float*)d_in[11];
    const float* enc_w    = (const float*)d_in[12];
    const float* user_w   = (const float*)d_in[13];
    const float* wenc     = (const float*)d_in[14];
    const float* fcpt_w   = (const float*)d_in[15];
    const float* fcpt_b   = (const float*)d_in[16];
    const float* W_ih     = (const float*)d_in[17];
    const float* W_hh     = (const float*)d_in[18];
    const float* b_ih     = (const float*)d_in[19];
    const float* b_hh     = (const float*)d_in[20];
    const float* fc_w     = (const float*)d_in[21];
    const float* fc_b     = (const float*)d_in[22];
    float* out = (float*)d_out;

    /* device-symbol pointers */
    void *pT, *pEnch, *pEncl, *pM1h, *pM1l, *pE2, *pTh, *pTl, *pN1h, *pN1l, *pT2;
    void *pUwh, *pUwl, *pP2, *pP3;
    void *pFcpAh, *pFcpAl, *pFcpBh, *pFcpBl, *pWihh, *pWihl;
    void *pFcwAh, *pFcwAl, *pFcwBh, *pFcwBl, *pFcwCh, *pFcwCl;
    void *pPre, *pOut, *pOwh, *pOwl;
    cudaGetSymbolAddress(&pT, g_T);
    cudaGetSymbolAddress(&pEnch, g_ench);  cudaGetSymbolAddress(&pEncl, g_encl);
    cudaGetSymbolAddress(&pM1h, g_M1h);    cudaGetSymbolAddress(&pM1l, g_M1l);
    cudaGetSymbolAddress(&pE2, g_E2);
    cudaGetSymbolAddress(&pTh, g_Th);      cudaGetSymbolAddress(&pTl, g_Tl);
    cudaGetSymbolAddress(&pN1h, g_N1h);    cudaGetSymbolAddress(&pN1l, g_N1l);
    cudaGetSymbolAddress(&pT2, g_T2);
    cudaGetSymbolAddress(&pUwh, g_uwh);    cudaGetSymbolAddress(&pUwl, g_uwl);
    cudaGetSymbolAddress(&pP2, g_P2);      cudaGetSymbolAddress(&pP3, g_P3);
    cudaGetSymbolAddress(&pFcpAh, g_fcpAh); cudaGetSymbolAddress(&pFcpAl, g_fcpAl);
    cudaGetSymbolAddress(&pFcpBh, g_fcpBh); cudaGetSymbolAddress(&pFcpBl, g_fcpBl);
    cudaGetSymbolAddress(&pWihh, g_wihh);  cudaGetSymbolAddress(&pWihl, g_wihl);
    cudaGetSymbolAddress(&pFcwAh, g_fcwAh); cudaGetSymbolAddress(&pFcwAl, g_fcwAl);
    cudaGetSymbolAddress(&pFcwBh, g_fcwBh); cudaGetSymbolAddress(&pFcwBl, g_fcwBl);
    cudaGetSymbolAddress(&pFcwCh, g_fcwCh); cudaGetSymbolAddress(&pFcwCl, g_fcwCl);
    cudaGetSymbolAddress(&pPre, g_pre);    cudaGetSymbolAddress(&pOut, g_out);
    cudaGetSymbolAddress(&pOwh, g_owh);    cudaGetSymbolAddress(&pOwl, g_owl);

    cudaFuncSetAttribute(hmma_gemm, cudaFuncAttributeMaxDynamicSharedMemorySize, GEMM_SMEM);
    cudaFuncSetAttribute(k_rnn,     cudaFuncAttributeMaxDynamicSharedMemorySize, 131072);

    /* ---- constant tables & splits ---- */
    k_week<<<168, 256>>>(sigma, wwi, wm, wenc);
    k_split_sub<<<256, 256>>>(enc_w,  H_,  0,    V_,   H_,  VPAD,
                              (__nv_bfloat16*)pEnch, (__nv_bfloat16*)pEncl);
    k_split_sub<<<128, 256>>>(fcpt_w, 768, 0,    512,  H_,  512,
                              (__nv_bfloat16*)pFcpAh, (__nv_bfloat16*)pFcpAl);
    k_split_sub<<<64, 256>>>(fcpt_w,  768, 512,  512,  H2_, 512,
                              (__nv_bfloat16*)pFcpBh, (__nv_bfloat16*)pFcpBl);
    k_split_sub<<<128, 256>>>(W_ih,   H_,  0,    512,  H_,  512,
                              (__nv_bfloat16*)pWihh, (__nv_bfloat16*)pWihl);
    k_split_sub<<<256, 256>>>(fc_w,   1280, 0,   V_,   H_,  VPAD,
                              (__nv_bfloat16*)pFcwAh, (__nv_bfloat16*)pFcwAl);
    k_split_sub<<<256, 256>>>(fc_w,   1280, 512, V_,   H_,  VPAD,
                              (__nv_bfloat16*)pFcwBh, (__nv_bfloat16*)pFcwBl);
    k_split_sub<<<256, 256>>>(fc_w,   1280, 1024, V_,  H2_, VPAD,
                              (__nv_bfloat16*)pFcwCh, (__nv_bfloat16*)pFcwCl);
    k_split_sub<<<32, 256>>>((const float*)pT, H2_, 0, 168, H2_, 256,
                              (__nv_bfloat16*)pTh, (__nv_bfloat16*)pTl);
    k_userw<<<128, 512>>>(user_w, act_user);
    k_cvec<<<2, 256>>>(fcpt_b, W_ih, b_ih, b_hh);

    /* ---- folded front-end tables ---- */
    /* M1 = enc @ fcptA^T  (split out) */
    hmma_gemm<<<dim3(2, VPAD / 128), 256, GEMM_SMEM>>>(
        (const __nv_bfloat16*)pEnch, (const __nv_bfloat16*)pEncl,
        (const __nv_bfloat16*)pFcpAh, (const __nv_bfloat16*)pFcpAl,
        nullptr, nullptr, nullptr, nullptr,
        nullptr, (__nv_bfloat16*)pM1h, (__nv_bfloat16*)pM1l, H_, H_);
    /* E2 = M1 @ W_ih^T (fp32) */
    hmma_gemm<<<dim3(2, VPAD / 128), 256, GEMM_SMEM>>>(
        (const __nv_bfloat16*)pM1h, (const __nv_bfloat16*)pM1l,
        (const __nv_bfloat16*)pWihh, (const __nv_bfloat16*)pWihl,
        nullptr, nullptr, nullptr, nullptr,
        (float*)pE2, nullptr, nullptr, H_, H_);
    /* N1 = T @ fcptB^T (split out) */
    hmma_gemm<<<dim3(2, 2), 256, GEMM_SMEM>>>(
        (const __nv_bfloat16*)pTh, (const __nv_bfloat16*)pTl,
        (const __nv_bfloat16*)pFcpBh, (const __nv_bfloat16*)pFcpBl,
        nullptr, nullptr, nullptr, nullptr,
        nullptr, (__nv_bfloat16*)pN1h, (__nv_bfloat16*)pN1l, H2_, H_);
    /* T2 = N1 @ W_ih^T (fp32) */
    hmma_gemm<<<dim3(2, 2), 256, GEMM_SMEM>>>(
        (const __nv_bfloat16*)pN1h, (const __nv_bfloat16*)pN1l,
        (const __nv_bfloat16*)pWihh, (const __nv_bfloat16*)pWihl,
        nullptr, nullptr, nullptr, nullptr,
        (float*)pT2, nullptr, nullptr, H_, H_);
    /* P2 = userw @ fcwB^T (fp32, [128,5000]) */
    hmma_gemm<<<dim3(VPAD / 256, 1), 256, GEMM_SMEM>>>(
        (const __nv_bfloat16*)pUwh, (const __nv_bfloat16*)pUwl,
        (const __nv_bfloat16*)pFcwBh, (const __nv_bfloat16*)pFcwBl,
        nullptr, nullptr, nullptr, nullptr,
        (float*)pP2, nullptr, nullptr, H_, V_);
    /* P3 = T @ fcwC^T (fp32, [256,5000]) */
    hmma_gemm<<<dim3(VPAD / 256, 2), 256, GEMM_SMEM>>>(
        (const __nv_bfloat16*)pTh, (const __nv_bfloat16*)pTl,
        (const __nv_bfloat16*)pFcwCh, (const __nv_bfloat16*)pFcwCl,
        nullptr, nullptr, nullptr, nullptr,
        (float*)pP3, nullptr, nullptr, H2_, V_);

    /* ---- pre = E2[x] + T2[ts] + cvec ---- */
    k_pre<<<MSU, 512>>>(x, t_slot);

    /* ---- RNN ---- */
    k_zero_bar<<<1, 1>>>();
    k_rnn<<<128, 256, 131072>>>((const float*)pPre, W_hh, h0, (float*)pOut);

    /* ---- attention ---- */
    k_w<<<dim3(S_, U_), 256>>>(t, s);
    k_att<<<dim3(S_ / 8, U_), 512>>>();

    /* ---- final projection with fused adds ---- */
    hmma_gemm<<<dim3(VPAD / 256, MSU / 128), 256, GEMM_SMEM>>>(
        (const __nv_bfloat16*)pOwh, (const __nv_bfloat16*)pOwl,
        (const __nv_bfloat16*)pFcwAh, (const __nv_bfloat16*)pFcwAl,
        fc_b, (const float*)pP2, (const float*)pP3, y_t_slot,
        out, nullptr, nullptr, H_, V_);

    /* ---- h_final tail ---- */
    size_t yelems = (size_t)S_ * U_ * V_;
    if ((size_t)out_size >= yelems + U_ * H_)
        k_hfinal<<<(U_ * H_ + 255) / 256, 256>>>(out + yelems);
}

// round 5
// speedup vs baseline: 2.2262x; 1.0276x over previous
#include <cuda_runtime.h>
#include <cuda_bf16.h>
#include <math.h>
#include <stdint.h>

#define S_  256
#define U_  64
#define H_  512
#define H2_ 256
#define V_  5000
#define MSU 16384   /* S*U */
#define VPAD 5120
#define PI_F 3.14159265358979323846f

/* ------------------------------------------------------------------ */
/* scratch (device globals; allocation-free)                           */
/* ------------------------------------------------------------------ */
__device__ float         g_T    [168 * H2_];
__device__ __nv_bfloat16 g_ench [(size_t)VPAD * H_];
__device__ __nv_bfloat16 g_encl [(size_t)VPAD * H_];
__device__ __nv_bfloat16 g_M1h  [(size_t)VPAD * H_];
__device__ __nv_bfloat16 g_M1l  [(size_t)VPAD * H_];
__device__ float         g_E2   [(size_t)VPAD * H_];
__device__ __nv_bfloat16 g_Th   [256 * H2_];
__device__ __nv_bfloat16 g_Tl   [256 * H2_];
__device__ __nv_bfloat16 g_N1h  [256 * H_];
__device__ __nv_bfloat16 g_N1l  [256 * H_];
__device__ float         g_T2   [256 * H_];
__device__ __nv_bfloat16 g_uwh  [128 * H_];
__device__ __nv_bfloat16 g_uwl  [128 * H_];
__device__ float         g_P2   [(size_t)128 * V_];
__device__ float         g_P3   [(size_t)256 * V_];
__device__ __nv_bfloat16 g_fcpAh[512 * H_];
__device__ __nv_bfloat16 g_fcpAl[512 * H_];
__device__ __nv_bfloat16 g_fcpBh[512 * H2_];
__device__ __nv_bfloat16 g_fcpBl[512 * H2_];
__device__ __nv_bfloat16 g_wihh [512 * H_];
__device__ __nv_bfloat16 g_wihl [512 * H_];
__device__ __nv_bfloat16 g_fcwAh[(size_t)VPAD * H_];
__device__ __nv_bfloat16 g_fcwAl[(size_t)VPAD * H_];
__device__ __nv_bfloat16 g_fcwBh[(size_t)VPAD * H_];
__device__ __nv_bfloat16 g_fcwBl[(size_t)VPAD * H_];
__device__ __nv_bfloat16 g_fcwCh[(size_t)VPAD * H2_];
__device__ __nv_bfloat16 g_fcwCl[(size_t)VPAD * H2_];
__device__ float         g_cvec [H_];
__device__ float         g_pre  [(size_t)MSU * H_];
__device__ float         g_out  [(size_t)MSU * H_];
__device__ float         g_w    [(size_t)U_ * S_ * S_];
__device__ float         g_den  [(size_t)U_ * S_];
__device__ __nv_bfloat16 g_owh  [(size_t)MSU * H_];
__device__ __nv_bfloat16 g_owl  [(size_t)MSU * H_];

/* ------------------------------------------------------------------ */
/* helpers                                                             */
/* ------------------------------------------------------------------ */
__device__ __forceinline__ uint32_t smem_u32(const void* p) {
    uint32_t a;
    asm("{ .reg .u64 t; cvta.to.shared.u64 t, %1; cvt.u32.u64 %0, t; }"
        : "=r"(a) : "l"(p));
    return a;
}

#define CP_ASYNC16(dst, src) \
    asm volatile("cp.async.cg.shared.global [%0], [%1], 16;" :: "r"(dst), "l"(src))
#define CP_COMMIT() asm volatile("cp.async.commit_group;" ::: "memory")
#define CP_WAIT(n)  asm volatile("cp.async.wait_group %0;" :: "n"(n) : "memory")

#define LDS32(v, addr) \
    asm volatile("ld.shared.b32 %0, [%1];" : "=r"(v) : "r"(addr))

#define LDSM4(r0, r1, r2, r3, a) \
    asm volatile("ldmatrix.sync.aligned.m8n8.x4.shared.b16 {%0,%1,%2,%3}, [%4];" \
        : "=r"(r0), "=r"(r1), "=r"(r2), "=r"(r3) : "r"(a))

#define CLUSTER_SYNC() do { \
    asm volatile("barrier.cluster.arrive.aligned;" ::: "memory"); \
    asm volatile("barrier.cluster.wait.aligned;" ::: "memory"); \
} while (0)

__device__ __forceinline__ void st_cluster_b16(uint32_t addr, uint32_t rank, uint16_t v) {
    asm volatile(
        "{ .reg .b32 ra; mapa.shared::cluster.u32 ra, %0, %1; "
        "st.shared::cluster.b16 [ra], %2; }"
        :: "r"(addr), "r"(rank), "h"(v) : "memory");
}

__device__ __forceinline__ void mma16816(float* c, const uint32_t* a, const uint32_t* b)
{
    asm volatile(
        "mma.sync.aligned.m16n8k16.row.col.f32.bf16.bf16.f32 "
        "{%0,%1,%2,%3}, {%4,%5,%6,%7}, {%8,%9}, {%0,%1,%2,%3};"
        : "+f"(c[0]), "+f"(c[1]), "+f"(c[2]), "+f"(c[3])
        : "r"(a[0]), "r"(a[1]), "r"(a[2]), "r"(a[3]), "r"(b[0]), "r"(b[1]));
}

__device__ __forceinline__ void split2(float v, __nv_bfloat16& h, __nv_bfloat16& l)
{
    h = __float2bfloat16(v);
    l = __float2bfloat16(v - __bfloat162float(h));
}

/* ------------------------------------------------------------------ */
/* split-bf16 HMMA GEMM:  C[M,Nreal] = A[M,K] @ B[Npad,K]^T (+extras)  */
/* BM=128, BN=256, BK=32, 256 threads (8 warps 2Mx4N), double-buffered */
/* 3 terms: Ah.Bh + Ah.Bl + Al.Bh (fp32 accum); ldmatrix fragments     */
/* ------------------------------------------------------------------ */
#define SWH 40                         /* smem row stride in halves    */
#define STAGE_B  61440
#define OFF_AL   10240
#define OFF_BH   20480
#define OFF_BL   40960
#define GEMM_SMEM (2 * STAGE_B)

__global__ __launch_bounds__(256, 1)
void hmma_gemm(const __nv_bfloat16* __restrict__ Ah, const __nv_bfloat16* __restrict__ Al,
               const __nv_bfloat16* __restrict__ Bh, const __nv_bfloat16* __restrict__ Bl,
               const float* __restrict__ bias1,
               const float* __restrict__ add1,
               const float* __restrict__ add2, const int* __restrict__ idx2,
               float* __restrict__ Cf,
               __nv_bfloat16* __restrict__ Ch, __nv_bfloat16* __restrict__ Cl,
               int K, int Nreal)
{
    extern __shared__ char smem[];
    const uint32_t sbase = smem_u32(smem);
    const int tid  = threadIdx.x;
    const int m0   = blockIdx.y * 128;
    const int n0   = blockIdx.x * 256;
    const int warp = tid >> 5, lane = tid & 31;
    const int wm = warp >> 2, wn = warp & 3;
    const int g  = lane >> 2, tig = lane & 3;
    const int L = K >> 5;

    /* ldmatrix per-lane offsets */
    const uint32_t aoffc = ((uint32_t)(wm * 64 + (lane & 15)) * SWH) * 2u
                         + (uint32_t)(lane >> 4) * 16u;
    const int sel  = (lane >> 3) & 3;
    const uint32_t boffc = ((uint32_t)(wn * 64 + ((sel & 2) << 2) + (lane & 7)) * SWH) * 2u
                         + (uint32_t)(sel & 1) * 16u;

    float acc[4][8][4];
#pragma unroll
    for (int mi = 0; mi < 4; mi++)
#pragma unroll
        for (int ni = 0; ni < 8; ni++)
#pragma unroll
            for (int q = 0; q < 4; q++) acc[mi][ni][q] = 0.0f;

    auto load_stage = [&](int chunk, int buf) {
        const uint32_t sg = sbase + (uint32_t)buf * STAGE_B;
        const int k0 = chunk << 5;
#pragma unroll 2
        for (int idx = tid; idx < 512; idx += 256) {
            int r = idx >> 2, c = idx & 3;
            uint32_t dsto = (uint32_t)(r * SWH + c * 8) * 2u;
            size_t srco = (size_t)(m0 + r) * K + k0 + c * 8;
            CP_ASYNC16(sg + dsto,            Ah + srco);
            CP_ASYNC16(sg + OFF_AL + dsto,   Al + srco);
        }
#pragma unroll 4
        for (int idx = tid; idx < 1024; idx += 256) {
            int r = idx >> 2, c = idx & 3;
            uint32_t dsto = (uint32_t)(r * SWH + c * 8) * 2u;
            size_t srco = (size_t)(n0 + r) * K + k0 + c * 8;
            CP_ASYNC16(sg + OFF_BH + dsto,   Bh + srco);
            CP_ASYNC16(sg + OFF_BL + dsto,   Bl + srco);
        }
        CP_COMMIT();
    };

    load_stage(0, 0);

    for (int i = 0; i < L; i++) {
        if (i + 1 < L) { load_stage(i + 1, (i + 1) & 1); CP_WAIT(1); }
        else           { CP_WAIT(0); }
        __syncthreads();

        const uint32_t sg = sbase + (uint32_t)(i & 1) * STAGE_B;
#pragma unroll
        for (int ks = 0; ks < 2; ks++) {
            const uint32_t kb = (uint32_t)ks * 32u;
            uint32_t ah[4][4], al[4][4], bb[8][2];
#pragma unroll
            for (int mi = 0; mi < 4; mi++)
                LDSM4(ah[mi][0], ah[mi][1], ah[mi][2], ah[mi][3],
                      sg + kb + aoffc + (uint32_t)mi * (16 * SWH * 2));
#pragma unroll
            for (int n2 = 0; n2 < 4; n2++)
                LDSM4(bb[2*n2][0], bb[2*n2][1], bb[2*n2+1][0], bb[2*n2+1][1],
                      sg + OFF_BH + kb + boffc + (uint32_t)n2 * (16 * SWH * 2));
#pragma unroll
            for (int mi = 0; mi < 4; mi++)
#pragma unroll
                for (int ni = 0; ni < 8; ni++)
                    mma16816(acc[mi][ni], ah[mi], bb[ni]);
#pragma unroll
            for (int mi = 0; mi < 4; mi++)
                LDSM4(al[mi][0], al[mi][1], al[mi][2], al[mi][3],
                      sg + OFF_AL + kb + aoffc + (uint32_t)mi * (16 * SWH * 2));
#pragma unroll
            for (int mi = 0; mi < 4; mi++)
#pragma unroll
                for (int ni = 0; ni < 8; ni++)
                    mma16816(acc[mi][ni], al[mi], bb[ni]);
#pragma unroll
            for (int n2 = 0; n2 < 4; n2++)
                LDSM4(bb[2*n2][0], bb[2*n2][1], bb[2*n2+1][0], bb[2*n2+1][1],
                      sg + OFF_BL + kb + boffc + (uint32_t)n2 * (16 * SWH * 2));
#pragma unroll
            for (int mi = 0; mi < 4; mi++)
#pragma unroll
                for (int ni = 0; ni < 8; ni++)
                    mma16816(acc[mi][ni], ah[mi], bb[ni]);
        }
        __syncthreads();
    }

    /* ---- epilogue ---- */
#pragma unroll
    for (int mi = 0; mi < 4; mi++) {
        const int row0 = m0 + wm * 64 + mi * 16 + g;
        int i2[2] = { 0, 0 };
        if (add2) { i2[0] = idx2[row0]; i2[1] = idx2[row0 + 8]; }
#pragma unroll
        for (int ni = 0; ni < 8; ni++) {
            const int n = n0 + wn * 64 + ni * 8 + tig * 2;
#pragma unroll
            for (int q = 0; q < 4; q++) {
                int rr = row0 + ((q >= 2) ? 8 : 0);
                int nn = n + (q & 1);
                if (nn >= Nreal) continue;
                float f = acc[mi][ni][q];
                if (bias1) f += bias1[nn];
                if (add1)  f += add1[(size_t)(rr & 63) * Nreal + nn];
                if (add2)  f += add2[(size_t)i2[q >> 1] * Nreal + nn];
                if (Cf) {
                    Cf[(size_t)rr * Nreal + nn] = f;
                } else {
                    __nv_bfloat16 hi, lo;
                    split2(f, hi, lo);
                    Ch[(size_t)rr * Nreal + nn] = hi;
                    Cl[(size_t)rr * Nreal + nn] = lo;
                }
            }
        }
    }
}

/* ------------------------------------------------------------------ */
/* subview split                                                       */
/* ------------------------------------------------------------------ */
__global__ void k_split_sub(const float* __restrict__ src, int pitch, int col0,
                            int rows, int cols, int padRows,
                            __nv_bfloat16* __restrict__ dh, __nv_bfloat16* __restrict__ dl)
{
    size_t total = (size_t)padRows * cols;
    for (size_t idx = (size_t)blockIdx.x * blockDim.x + threadIdx.x;
         idx < total; idx += (size_t)gridDim.x * blockDim.x) {
        int r = (int)(idx / cols);
        int c = (int)(idx - (size_t)r * cols);
        float v = (r < rows) ? src[(size_t)r * pitch + col0 + c] : 0.0f;
        __nv_bfloat16 hi, lo;
        split2(v, hi, lo);
        dh[idx] = hi; dl[idx] = lo;
    }
}

/* ------------------------------------------------------------------ */
/* gathered user rows, split, padded to 128                            */
/* ------------------------------------------------------------------ */
__global__ void k_userw(const float* __restrict__ user_w, const int* __restrict__ au)
{
    const int u = blockIdx.x;
    const int c = threadIdx.x;
    float v = 0.0f;
    if (u < U_) v = user_w[(size_t)au[u] * H_ + c];
    __nv_bfloat16 hi, lo;
    split2(v, hi, lo);
    g_uwh[u * H_ + c] = hi;
    g_uwl[u * H_ + c] = lo;
}

/* ------------------------------------------------------------------ */
/* cvec[n] = b_ih[n] + b_hh[n] + sum_k fcpt_b[k] * W_ih[n,k]           */
/* ------------------------------------------------------------------ */
__global__ void k_cvec(const float* __restrict__ fcpt_b, const float* __restrict__ W_ih,
                       const float* __restrict__ b_ih, const float* __restrict__ b_hh)
{
    const int n = blockIdx.x * blockDim.x + threadIdx.x;
    if (n >= H_) return;
    float a = b_ih[n] + b_hh[n];
    for (int k = 0; k < H_; k++) a += fcpt_b[k] * W_ih[(size_t)n * H_ + k];
    g_cvec[n] = a;
}

/* ------------------------------------------------------------------ */
/* pre[m,c] = E2[x[m],c] + T2[ts[m],c]   (cvec folded into T2)         */
/* ------------------------------------------------------------------ */
__global__ __launch_bounds__(512)
void k_pre(const int* __restrict__ x, const int* __restrict__ ts)
{
    const int m = blockIdx.x;
    const int c = threadIdx.x;
    const int xm = x[m], tm = ts[m];
    g_pre[(size_t)m * H_ + c] = g_E2[(size_t)xm * H_ + c] + g_T2[(size_t)tm * H_ + c];
}

/* ------------------------------------------------------------------ */
/* week distribution + time-embedding table T[168][H2]                 */
/* ------------------------------------------------------------------ */
__global__ void k_week(const float* __restrict__ sigma,
                       const float* __restrict__ wwi,
                       const int*   __restrict__ wm,
                       const float* __restrict__ wenc)
{
    const int slot = blockIdx.x;
    const int tid  = threadIdx.x;
    __shared__ float ww[168];
    __shared__ float red[256];

    float sig    = fabsf(sigma[slot]);
    float inv2s2 = 1.0f / (2.0f * sig * sig);
    float coef   = rsqrtf(2.0f * PI_F * sig * sig);

    float v = 0.0f;
    if (tid < 168) {
        float x = wwi[slot * 168 + tid];
        v = coef * expf(-x * x * inv2s2);
        ww[tid] = v;
    }
    red[tid] = v;
    __syncthreads();
    for (int off = 128; off > 0; off >>= 1) {
        if (tid < off) red[tid] += red[tid + off];
        __syncthreads();
    }
    const float inv = 1.0f / red[0];

    float acc = 0.0f;
    for (int k = 0; k < 168; k++) {
        int row = wm[slot * 168 + k];
        acc += (ww[k] * inv) * wenc[row * H2_ + tid];
    }
    g_T[slot * H2_ + tid] = acc;
}

/* ------------------------------------------------------------------ */
/* RNN: cluster(8) HMMA.  out[s] = tanh(pre[s] + h @ W_hh^T)           */
/* 128 blocks = 16 clusters x 8 ranks; rank gn owns 64 W-rows.         */
/* W bf16 hi/lo fragments in registers; h exchanged via DSMEM.         */
/* ------------------------------------------------------------------ */
#define WPAD 520
#define WST_H    0
#define WST_L    66560
#define HB0H     133120
#define HB0L     141440
#define HB1H     149760
#define HB1L     158080
#define PSUM_OFF 166400
#define RNN_SMEM 182784

__global__ __cluster_dims__(8, 1, 1) __launch_bounds__(256, 1)
void k_rnn(const float* __restrict__ pre, const float* __restrict__ Whh,
           const float* __restrict__ h0, float* __restrict__ out)
{
    extern __shared__ char sm[];
    const uint32_t sb = smem_u32(sm);
    const int tid = threadIdx.x;
    const int warp = tid >> 5, lane = tid & 31;
    const int gu = blockIdx.x >> 3;
    uint32_t gn;
    asm("mov.u32 %0, %%cluster_ctarank;" : "=r"(gn));

    __nv_bfloat16* wsth = (__nv_bfloat16*)(sm + WST_H);
    __nv_bfloat16* wstl = (__nv_bfloat16*)(sm + WST_L);

    /* stage W slice (64 rows) as split bf16 */
    for (int idx = tid; idx < 64 * 512; idx += 256) {
        int r = idx >> 9, c = idx & 511;
        float v = Whh[(size_t)(gn * 64 + r) * H_ + c];
        __nv_bfloat16 hi, lo;
        split2(v, hi, lo);
        wsth[r * WPAD + c] = hi;
        wstl[r * WPAD + c] = lo;
    }
    __syncthreads();

    /* load W fragments to registers: warp owns k-slice [warp*64, +64) */
    uint32_t Wh[4][4][4], Wl[4][4][4];
    {
        const uint32_t la = (uint32_t)(lane & 15) * (WPAD * 2)
                          + (uint32_t)(lane >> 4) * 16u;
#pragma unroll
        for (int mi = 0; mi < 4; mi++)
#pragma unroll
            for (int kt = 0; kt < 4; kt++) {
                uint32_t ofs = la + (uint32_t)mi * 16u * (WPAD * 2)
                             + (uint32_t)(warp * 64 + kt * 16) * 2u;
                LDSM4(Wh[mi][kt][0], Wh[mi][kt][1], Wh[mi][kt][2], Wh[mi][kt][3],
                      sb + WST_H + ofs);
                LDSM4(Wl[mi][kt][0], Wl[mi][kt][1], Wl[mi][kt][2], Wl[mi][kt][3],
                      sb + WST_L + ofs);
            }
    }

    /* init h buffers: zero all (padding users 4..7), then fill buf0 u<4 */
    __nv_bfloat16* hb00 = (__nv_bfloat16*)(sm + HB0H);
    __nv_bfloat16* hb01 = (__nv_bfloat16*)(sm + HB0L);
    __nv_bfloat16* hb10 = (__nv_bfloat16*)(sm + HB1H);
    __nv_bfloat16* hb11 = (__nv_bfloat16*)(sm + HB1L);
    const __nv_bfloat16 z = __float2bfloat16(0.0f);
    for (int idx = tid; idx < 8 * WPAD; idx += 256) {
        hb00[idx] = z; hb01[idx] = z; hb10[idx] = z; hb11[idx] = z;
    }
    __syncthreads();
    for (int idx = tid; idx < 4 * 512; idx += 256) {
        int u = idx >> 9, c = idx & 511;
        float v = h0[(size_t)(gu * 4 + u) * H_ + c];
        __nv_bfloat16 hi, lo;
        split2(v, hi, lo);
        hb00[u * WPAD + c] = hi;
        hb01[u * WPAD + c] = lo;
    }
    CLUSTER_SYNC();

    float* psum = (float*)(sm + PSUM_OFF);
    const int n_out = tid & 63, u_out = tid >> 6;
    const int mi_r = n_out >> 4, r16 = n_out & 15;
    const int lr = ((r16 & 7) << 2) + (u_out >> 1);
    const int cc = (u_out & 1) + ((r16 >> 3) << 1);
    const uint32_t bbase = (uint32_t)(lane >> 2) * (WPAD * 2)
                         + (uint32_t)(warp * 64 + (lane & 3) * 2) * 2u;

    for (int s = 0; s < S_; s++) {
        const int cb = s & 1;
        const size_t o = (size_t)s * U_ * H_ + (size_t)(gu * 4 + u_out) * H_
                       + gn * 64 + n_out;
        float pv = __ldcg(pre + o);

        const uint32_t hbh = sb + (cb ? HB1H : HB0H);
        const uint32_t hbl = sb + (cb ? HB1L : HB0L);

        float acc[4][4];
#pragma unroll
        for (int mi = 0; mi < 4; mi++)
#pragma unroll
            for (int q = 0; q < 4; q++) acc[mi][q] = 0.0f;

#pragma unroll
        for (int kt = 0; kt < 4; kt++) {
            uint32_t off = bbase + (uint32_t)kt * 32u;
            uint32_t bh[2], bl[2];
            LDS32(bh[0], hbh + off); LDS32(bh[1], hbh + off + 16u);
            LDS32(bl[0], hbl + off); LDS32(bl[1], hbl + off + 16u);
#pragma unroll
            for (int mi = 0; mi < 4; mi++) {
                mma16816(acc[mi], Wh[mi][kt], bh);
                mma16816(acc[mi], Wl[mi][kt], bh);
                mma16816(acc[mi], Wh[mi][kt], bl);
            }
        }
#pragma unroll
        for (int mi = 0; mi < 4; mi++) {
            float4 v4 = make_float4(acc[mi][0], acc[mi][1], acc[mi][2], acc[mi][3]);
            *(float4*)&psum[(warp * 4 + mi) * 128 + lane * 4] = v4;
        }
        __syncthreads();

        float v = 0.0f;
#pragma unroll
        for (int w2 = 0; w2 < 8; w2++)
            v += psum[(w2 * 4 + mi_r) * 128 + lr * 4 + cc];

        float hv = tanhf(pv + v);
        out[o] = hv;

        if (s < S_ - 1) {
            __nv_bfloat16 hi, lo;
            split2(hv, hi, lo);
            uint16_t hu = *(uint16_t*)&hi, lu = *(uint16_t*)&lo;
            uint32_t dsth = sb + (cb ? HB0H : HB1H)
                          + (uint32_t)(u_out * WPAD + gn * 64 + n_out) * 2u;
            uint32_t dstl = dsth + (HB0L - HB0H);
#pragma unroll
            for (int r = 0; r < 8; r++) {
                st_cluster_b16(dsth, (uint32_t)r, hu);
                st_cluster_b16(dstl, (uint32_t)r, lu);
            }
            CLUSTER_SYNC();
        }
    }
}

/* ------------------------------------------------------------------ */
/* attention weights w[u,i,j] and row sums den[u,i]                    */
/* ------------------------------------------------------------------ */
__global__ void k_w(const float* __restrict__ t, const float* __restrict__ s)
{
    const int i = blockIdx.x, u = blockIdx.y;
    const int j = threadIdx.x;
    __shared__ float red[256];

    float wv = 0.0f;
    if (j <= i) {
        float dt = t[i * U_ + u] - t[j * U_ + u];
        float d0 = s[((size_t)i * U_ + u) * 2 + 0] - s[((size_t)j * U_ + u) * 2 + 0];
        float d1 = s[((size_t)i * U_ + u) * 2 + 1] - s[((size_t)j * U_ + u) * 2 + 1];
        float ds = sqrtf(d0 * d0 + d1 * d1);
        float ft = (cosf(dt * (2.0f * PI_F / 86400.0f)) + 1.0f) * 0.5f
                 * expf(-(dt / 86400.0f) * 0.1f);
        float fs = expf(-ds * 100.0f);
        wv = ft * fs + 1e-10f;
    }
    g_w[((size_t)u * S_ + i) * S_ + j] = wv;

    red[j] = wv;
    __syncthreads();
    for (int off = 128; off > 0; off >>= 1) {
        if (j < off) red[j] += red[j + off];
        __syncthreads();
    }
    if (j == 0) g_den[u * S_ + i] = red[0];
}

/* ------------------------------------------------------------------ */
/* weighted causal sum -> split bf16 outw                              */
/* ------------------------------------------------------------------ */
__global__ __launch_bounds__(512)
void k_att()
{
    __shared__ float wsh[8 * 64];
    const int it = blockIdx.x;
    const int u  = blockIdx.y;
    const int i0 = it * 8;
    const int h  = threadIdx.x;
    const float* wb = g_w + (size_t)u * S_ * S_;

    float acc[8];
#pragma unroll
    for (int ii = 0; ii < 8; ii++) acc[ii] = 0.0f;

    const int jend = i0 + 8;
    for (int j0 = 0; j0 < jend; j0 += 64) {
        int ii = h >> 6, jj = h & 63;
        wsh[h] = wb[(size_t)(i0 + ii) * S_ + j0 + jj];
        __syncthreads();
        int jcnt = (jend - j0 < 64) ? (jend - j0) : 64;
        for (int q = 0; q < jcnt; q++) {
            float ov = g_out[((size_t)(j0 + q) * U_ + u) * H_ + h];
#pragma unroll
            for (int ii2 = 0; ii2 < 8; ii2++)
                acc[ii2] += wsh[ii2 * 64 + q] * ov;
        }
        __syncthreads();
    }
#pragma unroll
    for (int ii = 0; ii < 8; ii++) {
        float d = g_den[u * S_ + i0 + ii];
        float f = acc[ii] / d;
        __nv_bfloat16 hi, lo;
        split2(f, hi, lo);
        size_t o = ((size_t)(i0 + ii) * U_ + u) * H_ + h;
        g_owh[o] = hi;
        g_owl[o] = lo;
    }
}

/* ------------------------------------------------------------------ */
/* copy h_final = out[S-1]                                             */
/* ------------------------------------------------------------------ */
__global__ void k_hfinal(float* __restrict__ dst)
{
    int i = blockIdx.x * blockDim.x + threadIdx.x;
    if (i < U_ * H_) dst[i] = g_out[(size_t)(S_ - 1) * U_ * H_ + i];
}

/* ------------------------------------------------------------------ */
extern "C" void kernel_launch(void* const* d_in, const int* in_sizes, int n_in,
                              void* d_out, int out_size)
{
    const int*   x        = (const int*)  d_in[0];
    const float* t        = (const float*)d_in[1];
    const int*   t_slot   = (const int*)  d_in[2];
    const float* s        = (const float*)d_in[3];
    const int*   y_t_slot = (const int*)  d_in[5];
    const float* h0       = (const float*)d_in[7];
    const int*   act_user = (const int*)  d_in[8];
    const int*   wm       = (const int*)  d_in[9];
    const float* wwi      = (const float*)d_in[10];
    const float* sigma    = (const float*)d_in[11];
    const float* enc_w    = (const float*)d_in[12];
    const float* user_w   = (const float*)d_in[13];
    const float* wenc     = (const float*)d_in[14];
    const float* fcpt_w   = (const float*)d_in[15];
    const float* fcpt_b   = (const float*)d_in[16];
    const float* W_ih     = (const float*)d_in[17];
    const float* W_hh     = (const float*)d_in[18];
    const float* b_ih     = (const float*)d_in[19];
    const float* b_hh     = (const float*)d_in[20];
    const float* fc_w     = (const float*)d_in[21];
    const float* fc_b     = (const float*)d_in[22];
    float* out = (float*)d_out;

    void *pT, *pEnch, *pEncl, *pM1h, *pM1l, *pE2, *pTh, *pTl, *pN1h, *pN1l, *pT2;
    void *pUwh, *pUwl, *pP2, *pP3, *pCvec;
    void *pFcpAh, *pFcpAl, *pFcpBh, *pFcpBl, *pWihh, *pWihl;
    void *pFcwAh, *pFcwAl, *pFcwBh, *pFcwBl, *pFcwCh, *pFcwCl;
    void *pPre, *pOut, *pOwh, *pOwl;
    cudaGetSymbolAddress(&pT, g_T);
    cudaGetSymbolAddress(&pEnch, g_ench);  cudaGetSymbolAddress(&pEncl, g_encl);
    cudaGetSymbolAddress(&pM1h, g_M1h);    cudaGetSymbolAddress(&pM1l, g_M1l);
    cudaGetSymbolAddress(&pE2, g_E2);
    cudaGetSymbolAddress(&pTh, g_Th);      cudaGetSymbolAddress(&pTl, g_Tl);
    cudaGetSymbolAddress(&pN1h, g_N1h);    cudaGetSymbolAddress(&pN1l, g_N1l);
    cudaGetSymbolAddress(&pT2, g_T2);
    cudaGetSymbolAddress(&pUwh, g_uwh);    cudaGetSymbolAddress(&pUwl, g_uwl);
    cudaGetSymbolAddress(&pP2, g_P2);      cudaGetSymbolAddress(&pP3, g_P3);
    cudaGetSymbolAddress(&pCvec, g_cvec);
    cudaGetSymbolAddress(&pFcpAh, g_fcpAh); cudaGetSymbolAddress(&pFcpAl, g_fcpAl);
    cudaGetSymbolAddress(&pFcpBh, g_fcpBh); cudaGetSymbolAddress(&pFcpBl, g_fcpBl);
    cudaGetSymbolAddress(&pWihh, g_wihh);  cudaGetSymbolAddress(&pWihl, g_wihl);
    cudaGetSymbolAddress(&pFcwAh, g_fcwAh); cudaGetSymbolAddress(&pFcwAl, g_fcwAl);
    cudaGetSymbolAddress(&pFcwBh, g_fcwBh); cudaGetSymbolAddress(&pFcwBl, g_fcwBl);
    cudaGetSymbolAddress(&pFcwCh, g_fcwCh); cudaGetSymbolAddress(&pFcwCl, g_fcwCl);
    cudaGetSymbolAddress(&pPre, g_pre);    cudaGetSymbolAddress(&pOut, g_out);
    cudaGetSymbolAddress(&pOwh, g_owh);    cudaGetSymbolAddress(&pOwl, g_owl);

    cudaFuncSetAttribute(hmma_gemm, cudaFuncAttributeMaxDynamicSharedMemorySize, GEMM_SMEM);
    cudaFuncSetAttribute(k_rnn,     cudaFuncAttributeMaxDynamicSharedMemorySize, RNN_SMEM);

    /* ---- constant tables & splits ---- */
    k_week<<<168, 256>>>(sigma, wwi, wm, wenc);
    k_split_sub<<<256, 256>>>(enc_w,  H_,  0,    V_,   H_,  VPAD,
                              (__nv_bfloat16*)pEnch, (__nv_bfloat16*)pEncl);
    k_split_sub<<<128, 256>>>(fcpt_w, 768, 0,    512,  H_,  512,
                              (__nv_bfloat16*)pFcpAh, (__nv_bfloat16*)pFcpAl);
    k_split_sub<<<64, 256>>>(fcpt_w,  768, 512,  512,  H2_, 512,
                              (__nv_bfloat16*)pFcpBh, (__nv_bfloat16*)pFcpBl);
    k_split_sub<<<128, 256>>>(W_ih,   H_,  0,    512,  H_,  512,
                              (__nv_bfloat16*)pWihh, (__nv_bfloat16*)pWihl);
    k_split_sub<<<256, 256>>>(fc_w,   1280, 0,   V_,   H_,  VPAD,
                              (__nv_bfloat16*)pFcwAh, (__nv_bfloat16*)pFcwAl);
    k_split_sub<<<256, 256>>>(fc_w,   1280, 512, V_,   H_,  VPAD,
                              (__nv_bfloat16*)pFcwBh, (__nv_bfloat16*)pFcwBl);
    k_split_sub<<<256, 256>>>(fc_w,   1280, 1024, V_,  H2_, VPAD,
                              (__nv_bfloat16*)pFcwCh, (__nv_bfloat16*)pFcwCl);
    k_split_sub<<<32, 256>>>((const float*)pT, H2_, 0, 168, H2_, 256,
                              (__nv_bfloat16*)pTh, (__nv_bfloat16*)pTl);
    k_userw<<<128, 512>>>(user_w, act_user);
    k_cvec<<<2, 256>>>(fcpt_b, W_ih, b_ih, b_hh);

    /* ---- folded front-end tables ---- */
    hmma_gemm<<<dim3(2, VPAD / 128), 256, GEMM_SMEM>>>(
        (const __nv_bfloat16*)pEnch, (const __nv_bfloat16*)pEncl,
        (const __nv_bfloat16*)pFcpAh, (const __nv_bfloat16*)pFcpAl,
        nullptr, nullptr, nullptr, nullptr,
        nullptr, (__nv_bfloat16*)pM1h, (__nv_bfloat16*)pM1l, H_, H_);
    hmma_gemm<<<dim3(2, VPAD / 128), 256, GEMM_SMEM>>>(
        (const __nv_bfloat16*)pM1h, (const __nv_bfloat16*)pM1l,
        (const __nv_bfloat16*)pWihh, (const __nv_bfloat16*)pWihl,
        nullptr, nullptr, nullptr, nullptr,
        (float*)pE2, nullptr, nullptr, H_, H_);
    hmma_gemm<<<dim3(2, 2), 256, GEMM_SMEM>>>(
        (const __nv_bfloat16*)pTh, (const __nv_bfloat16*)pTl,
        (const __nv_bfloat16*)pFcpBh, (const __nv_bfloat16*)pFcpBl,
        nullptr, nullptr, nullptr, nullptr,
        nullptr, (__nv_bfloat16*)pN1h, (__nv_bfloat16*)pN1l, H2_, H_);
    hmma_gemm<<<dim3(2, 2), 256, GEMM_SMEM>>>(
        (const __nv_bfloat16*)pN1h, (const __nv_bfloat16*)pN1l,
        (const __nv_bfloat16*)pWihh, (const __nv_bfloat16*)pWihl,
        (const float*)pCvec, nullptr, nullptr, nullptr,
        (float*)pT2, nullptr, nullptr, H_, H_);
    hmma_gemm<<<dim3(VPAD / 256, 1), 256, GEMM_SMEM>>>(
        (const __nv_bfloat16*)pUwh, (const __nv_bfloat16*)pUwl,
        (const __nv_bfloat16*)pFcwBh, (const __nv_bfloat16*)pFcwBl,
        nullptr, nullptr, nullptr, nullptr,
        (float*)pP2, nullptr, nullptr, H_, V_);
    hmma_gemm<<<dim3(VPAD / 256, 2), 256, GEMM_SMEM>>>(
        (const __nv_bfloat16*)pTh, (const __nv_bfloat16*)pTl,
        (const __nv_bfloat16*)pFcwCh, (const __nv_bfloat16*)pFcwCl,
        nullptr, nullptr, nullptr, nullptr,
        (float*)pP3, nullptr, nullptr, H2_, V_);

    /* ---- pre = E2[x] + T2[ts] ---- */
    k_pre<<<MSU, 512>>>(x, t_slot);

    /* ---- RNN (cluster HMMA) ---- */
    k_rnn<<<128, 256, RNN_SMEM>>>((const float*)pPre, W_hh, h0, (float*)pOut);

    /* ---- attention ---- */
    k_w<<<dim3(S_, U_), 256>>>(t, s);
    k_att<<<dim3(S_ / 8, U_), 512>>>();

    /* ---- final projection with fused adds ---- */
    hmma_gemm<<<dim3(VPAD / 256, MSU / 128), 256, GEMM_SMEM>>>(
        (const __nv_bfloat16*)pOwh, (const __nv_bfloat16*)pOwl,
        (const __nv_bfloat16*)pFcwAh, (const __nv_bfloat16*)pFcwAl,
        fc_b, (const float*)pP2, (const float*)pP3, y_t_slot,
        out, nullptr, nullptr, H_, V_);

    /* ---- h_final tail ---- */
    size_t yelems = (size_t)S_ * U_ * V_;
    if ((size_t)out_size >= yelems + U_ * H_)
        k_hfinal<<<(U_ * H_ + 255) / 256, 256>>>(out + yelems);
}

// round 6
// speedup vs baseline: 3.0785x; 1.3829x over previous
#include <cuda_runtime.h>
#include <cuda_bf16.h>
#include <cuda_fp16.h>
#include <math.h>
#include <stdint.h>

#define S_  256
#define U_  64
#define H_  512
#define H2_ 256
#define V_  5000
#define MSU 16384   /* S*U */
#define VPAD 5120
#define PI_F 3.14159265358979323846f

/* ------------------------------------------------------------------ */
/* scratch (device globals; allocation-free)                           */
/* ------------------------------------------------------------------ */
__device__ float         g_T    [168 * H2_];
__device__ __nv_bfloat16 g_ench [(size_t)VPAD * H_];
__device__ __nv_bfloat16 g_encl [(size_t)VPAD * H_];
__device__ __nv_bfloat16 g_M1h  [(size_t)VPAD * H_];
__device__ __nv_bfloat16 g_M1l  [(size_t)VPAD * H_];
__device__ float         g_E2   [(size_t)VPAD * H_];
__device__ __nv_bfloat16 g_Th   [256 * H2_];
__device__ __nv_bfloat16 g_Tl   [256 * H2_];
__device__ __nv_bfloat16 g_N1h  [256 * H_];
__device__ __nv_bfloat16 g_N1l  [256 * H_];
__device__ float         g_T2   [256 * H_];
__device__ __nv_bfloat16 g_uwh  [128 * H_];
__device__ __nv_bfloat16 g_uwl  [128 * H_];
__device__ float         g_P2   [(size_t)128 * V_];
__device__ float         g_P3   [(size_t)256 * V_];
__device__ __nv_bfloat16 g_fcpAh[512 * H_];
__device__ __nv_bfloat16 g_fcpAl[512 * H_];
__device__ __nv_bfloat16 g_fcpBh[512 * H2_];
__device__ __nv_bfloat16 g_fcpBl[512 * H2_];
__device__ __nv_bfloat16 g_wihh [512 * H_];
__device__ __nv_bfloat16 g_wihl [512 * H_];
__device__ __half        g_fcwA16[(size_t)VPAD * H_];
__device__ __nv_bfloat16 g_fcwBh[(size_t)VPAD * H_];
__device__ __nv_bfloat16 g_fcwBl[(size_t)VPAD * H_];
__device__ __nv_bfloat16 g_fcwCh[(size_t)VPAD * H2_];
__device__ __nv_bfloat16 g_fcwCl[(size_t)VPAD * H2_];
__device__ float         g_cvec [H_];
__device__ float         g_pre  [(size_t)MSU * H_];
__device__ float         g_out  [(size_t)MSU * H_];
__device__ float         g_w    [(size_t)U_ * S_ * S_];
__device__ float         g_den  [(size_t)U_ * S_];
__device__ __half        g_ow16 [(size_t)MSU * H_];

/* ------------------------------------------------------------------ */
/* helpers                                                             */
/* ------------------------------------------------------------------ */
__device__ __forceinline__ uint32_t smem_u32(const void* p) {
    uint32_t a;
    asm("{ .reg .u64 t; cvta.to.shared.u64 t, %1; cvt.u32.u64 %0, t; }"
        : "=r"(a) : "l"(p));
    return a;
}

#define CP_ASYNC16(dst, src) \
    asm volatile("cp.async.cg.shared.global [%0], [%1], 16;" :: "r"(dst), "l"(src))
#define CP_COMMIT() asm volatile("cp.async.commit_group;" ::: "memory")
#define CP_WAIT(n)  asm volatile("cp.async.wait_group %0;" :: "n"(n) : "memory")

#define LDS32(v, addr) \
    asm volatile("ld.shared.b32 %0, [%1];" : "=r"(v) : "r"(addr))

#define LDSM4(r0, r1, r2, r3, a) \
    asm volatile("ldmatrix.sync.aligned.m8n8.x4.shared.b16 {%0,%1,%2,%3}, [%4];" \
        : "=r"(r0), "=r"(r1), "=r"(r2), "=r"(r3) : "r"(a))

#define CLUSTER_SYNC() do { \
    asm volatile("barrier.cluster.arrive.aligned;" ::: "memory"); \
    asm volatile("barrier.cluster.wait.aligned;" ::: "memory"); \
} while (0)

__device__ __forceinline__ void st_cluster_b16(uint32_t addr, uint32_t rank, uint16_t v) {
    asm volatile(
        "{ .reg .b32 ra; mapa.shared::cluster.u32 ra, %0, %1; "
        "st.shared::cluster.b16 [ra], %2; }"
        :: "r"(addr), "r"(rank), "h"(v) : "memory");
}

__device__ __forceinline__ void mma16816(float* c, const uint32_t* a, const uint32_t* b)
{
    asm volatile(
        "mma.sync.aligned.m16n8k16.row.col.f32.bf16.bf16.f32 "
        "{%0,%1,%2,%3}, {%4,%5,%6,%7}, {%8,%9}, {%0,%1,%2,%3};"
        : "+f"(c[0]), "+f"(c[1]), "+f"(c[2]), "+f"(c[3])
        : "r"(a[0]), "r"(a[1]), "r"(a[2]), "r"(a[3]), "r"(b[0]), "r"(b[1]));
}

__device__ __forceinline__ void mma16816h(float* c, const uint32_t* a, const uint32_t* b)
{
    asm volatile(
        "mma.sync.aligned.m16n8k16.row.col.f32.f16.f16.f32 "
        "{%0,%1,%2,%3}, {%4,%5,%6,%7}, {%8,%9}, {%0,%1,%2,%3};"
        : "+f"(c[0]), "+f"(c[1]), "+f"(c[2]), "+f"(c[3])
        : "r"(a[0]), "r"(a[1]), "r"(a[2]), "r"(a[3]), "r"(b[0]), "r"(b[1]));
}

__device__ __forceinline__ void split2(float v, __nv_bfloat16& h, __nv_bfloat16& l)
{
    h = __float2bfloat16(v);
    l = __float2bfloat16(v - __bfloat162float(h));
}

/* ------------------------------------------------------------------ */
/* split-bf16 HMMA GEMM (3-term):  C = A @ B^T (+extras)               */
/* BM=128, BN=256, BK=32, 256 threads (8 warps 2Mx4N), double-buffered */
/* ------------------------------------------------------------------ */
#define SWH 40
#define STAGE_B  61440
#define OFF_AL   10240
#define OFF_BH   20480
#define OFF_BL   40960
#define GEMM_SMEM (2 * STAGE_B)

__global__ __launch_bounds__(256, 1)
void hmma_gemm(const __nv_bfloat16* __restrict__ Ah, const __nv_bfloat16* __restrict__ Al,
               const __nv_bfloat16* __restrict__ Bh, const __nv_bfloat16* __restrict__ Bl,
               const float* __restrict__ bias1,
               float* __restrict__ Cf,
               __nv_bfloat16* __restrict__ Ch, __nv_bfloat16* __restrict__ Cl,
               int K, int Nreal)
{
    extern __shared__ char smem[];
    const uint32_t sbase = smem_u32(smem);
    const int tid  = threadIdx.x;
    const int m0   = blockIdx.y * 128;
    const int n0   = blockIdx.x * 256;
    const int warp = tid >> 5, lane = tid & 31;
    const int wm = warp >> 2, wn = warp & 3;
    const int g  = lane >> 2, tig = lane & 3;
    const int L = K >> 5;

    const uint32_t aoffc = ((uint32_t)(wm * 64 + (lane & 15)) * SWH) * 2u
                         + (uint32_t)(lane >> 4) * 16u;
    const int sel  = (lane >> 3) & 3;
    const uint32_t boffc = ((uint32_t)(wn * 64 + ((sel & 2) << 2) + (lane & 7)) * SWH) * 2u
                         + (uint32_t)(sel & 1) * 16u;

    float acc[4][8][4];
#pragma unroll
    for (int mi = 0; mi < 4; mi++)
#pragma unroll
        for (int ni = 0; ni < 8; ni++)
#pragma unroll
            for (int q = 0; q < 4; q++) acc[mi][ni][q] = 0.0f;

    auto load_stage = [&](int chunk, int buf) {
        const uint32_t sg = sbase + (uint32_t)buf * STAGE_B;
        const int k0 = chunk << 5;
#pragma unroll 2
        for (int idx = tid; idx < 512; idx += 256) {
            int r = idx >> 2, c = idx & 3;
            uint32_t dsto = (uint32_t)(r * SWH + c * 8) * 2u;
            size_t srco = (size_t)(m0 + r) * K + k0 + c * 8;
            CP_ASYNC16(sg + dsto,            Ah + srco);
            CP_ASYNC16(sg + OFF_AL + dsto,   Al + srco);
        }
#pragma unroll 4
        for (int idx = tid; idx < 1024; idx += 256) {
            int r = idx >> 2, c = idx & 3;
            uint32_t dsto = (uint32_t)(r * SWH + c * 8) * 2u;
            size_t srco = (size_t)(n0 + r) * K + k0 + c * 8;
            CP_ASYNC16(sg + OFF_BH + dsto,   Bh + srco);
            CP_ASYNC16(sg + OFF_BL + dsto,   Bl + srco);
        }
        CP_COMMIT();
    };

    load_stage(0, 0);

    for (int i = 0; i < L; i++) {
        if (i + 1 < L) { load_stage(i + 1, (i + 1) & 1); CP_WAIT(1); }
        else           { CP_WAIT(0); }
        __syncthreads();

        const uint32_t sg = sbase + (uint32_t)(i & 1) * STAGE_B;
#pragma unroll
        for (int ks = 0; ks < 2; ks++) {
            const uint32_t kb = (uint32_t)ks * 32u;
            uint32_t ah[4][4], al[4][4], bb[8][2];
#pragma unroll
            for (int mi = 0; mi < 4; mi++)
                LDSM4(ah[mi][0], ah[mi][1], ah[mi][2], ah[mi][3],
                      sg + kb + aoffc + (uint32_t)mi * (16 * SWH * 2));
#pragma unroll
            for (int n2 = 0; n2 < 4; n2++)
                LDSM4(bb[2*n2][0], bb[2*n2][1], bb[2*n2+1][0], bb[2*n2+1][1],
                      sg + OFF_BH + kb + boffc + (uint32_t)n2 * (16 * SWH * 2));
#pragma unroll
            for (int mi = 0; mi < 4; mi++)
#pragma unroll
                for (int ni = 0; ni < 8; ni++)
                    mma16816(acc[mi][ni], ah[mi], bb[ni]);
#pragma unroll
            for (int mi = 0; mi < 4; mi++)
                LDSM4(al[mi][0], al[mi][1], al[mi][2], al[mi][3],
                      sg + OFF_AL + kb + aoffc + (uint32_t)mi * (16 * SWH * 2));
#pragma unroll
            for (int mi = 0; mi < 4; mi++)
#pragma unroll
                for (int ni = 0; ni < 8; ni++)
                    mma16816(acc[mi][ni], al[mi], bb[ni]);
#pragma unroll
            for (int n2 = 0; n2 < 4; n2++)
                LDSM4(bb[2*n2][0], bb[2*n2][1], bb[2*n2+1][0], bb[2*n2+1][1],
                      sg + OFF_BL + kb + boffc + (uint32_t)n2 * (16 * SWH * 2));
#pragma unroll
            for (int mi = 0; mi < 4; mi++)
#pragma unroll
                for (int ni = 0; ni < 8; ni++)
                    mma16816(acc[mi][ni], ah[mi], bb[ni]);
        }
        __syncthreads();
    }

#pragma unroll
    for (int mi = 0; mi < 4; mi++) {
        const int row0 = m0 + wm * 64 + mi * 16 + g;
#pragma unroll
        for (int ni = 0; ni < 8; ni++) {
            const int n = n0 + wn * 64 + ni * 8 + tig * 2;
#pragma unroll
            for (int q = 0; q < 4; q++) {
                int rr = row0 + ((q >= 2) ? 8 : 0);
                int nn = n + (q & 1);
                if (nn >= Nreal) continue;
                float f = acc[mi][ni][q];
                if (bias1) f += bias1[nn];
                if (Cf) {
                    Cf[(size_t)rr * Nreal + nn] = f;
                } else {
                    __nv_bfloat16 hi, lo;
                    split2(f, hi, lo);
                    Ch[(size_t)rr * Nreal + nn] = hi;
                    Cl[(size_t)rr * Nreal + nn] = lo;
                }
            }
        }
    }
}

/* ------------------------------------------------------------------ */
/* fp16 single-product HMMA GEMM (final projection)                    */
/* BM=128, BN=256, BK=64, 256 threads, double-buffered                 */
/* epilogue: + bias1[n] + add1[(m&63),n] + add2[idx2[m],n]             */
/* ------------------------------------------------------------------ */
#define SWH2      72                    /* halves per smem row (144 B) */
#define G16_OFFB  18432
#define G16_STAGE 55296
#define GEMM16_SMEM (2 * G16_STAGE)

__global__ __launch_bounds__(256, 1)
void hmma_gemm16(const __half* __restrict__ A, const __half* __restrict__ B,
                 const float* __restrict__ bias1,
                 const float* __restrict__ add1,
                 const float* __restrict__ add2, const int* __restrict__ idx2,
                 float* __restrict__ Cf, int K, int Nreal)
{
    extern __shared__ char smem[];
    const uint32_t sbase = smem_u32(smem);
    const int tid  = threadIdx.x;
    const int m0   = blockIdx.y * 128;
    const int n0   = blockIdx.x * 256;
    const int warp = tid >> 5, lane = tid & 31;
    const int wm = warp >> 2, wn = warp & 3;
    const int g  = lane >> 2, tig = lane & 3;
    const int L = K >> 6;

    const uint32_t aoffc = ((uint32_t)(wm * 64 + (lane & 15)) * SWH2) * 2u
                         + (uint32_t)(lane >> 4) * 16u;
    const int sel  = (lane >> 3) & 3;
    const uint32_t boffc = ((uint32_t)(wn * 64 + ((sel & 2) << 2) + (lane & 7)) * SWH2) * 2u
                         + (uint32_t)(sel & 1) * 16u;

    float acc[4][8][4];
#pragma unroll
    for (int mi = 0; mi < 4; mi++)
#pragma unroll
        for (int ni = 0; ni < 8; ni++)
#pragma unroll
            for (int q = 0; q < 4; q++) acc[mi][ni][q] = 0.0f;

    auto load_stage = [&](int chunk, int buf) {
        const uint32_t sg = sbase + (uint32_t)buf * G16_STAGE;
        const int k0 = chunk << 6;
#pragma unroll 4
        for (int idx = tid; idx < 1024; idx += 256) {
            int r = idx >> 3, c = idx & 7;
            CP_ASYNC16(sg + (uint32_t)(r * SWH2 + c * 8) * 2u,
                       A + (size_t)(m0 + r) * K + k0 + c * 8);
        }
#pragma unroll 8
        for (int idx = tid; idx < 2048; idx += 256) {
            int r = idx >> 3, c = idx & 7;
            CP_ASYNC16(sg + G16_OFFB + (uint32_t)(r * SWH2 + c * 8) * 2u,
                       B + (size_t)(n0 + r) * K + k0 + c * 8);
        }
        CP_COMMIT();
    };

    load_stage(0, 0);

    for (int i = 0; i < L; i++) {
        if (i + 1 < L) { load_stage(i + 1, (i + 1) & 1); CP_WAIT(1); }
        else           { CP_WAIT(0); }
        __syncthreads();

        const uint32_t sg = sbase + (uint32_t)(i & 1) * G16_STAGE;
#pragma unroll
        for (int ks = 0; ks < 4; ks++) {
            const uint32_t kb = (uint32_t)ks * 32u;
            uint32_t ah[4][4], bb[8][2];
#pragma unroll
            for (int mi = 0; mi < 4; mi++)
                LDSM4(ah[mi][0], ah[mi][1], ah[mi][2], ah[mi][3],
                      sg + kb + aoffc + (uint32_t)mi * (16 * SWH2 * 2));
#pragma unroll
            for (int n2 = 0; n2 < 4; n2++)
                LDSM4(bb[2*n2][0], bb[2*n2][1], bb[2*n2+1][0], bb[2*n2+1][1],
                      sg + G16_OFFB + kb + boffc + (uint32_t)n2 * (16 * SWH2 * 2));
#pragma unroll
            for (int mi = 0; mi < 4; mi++)
#pragma unroll
                for (int ni = 0; ni < 8; ni++)
                    mma16816h(acc[mi][ni], ah[mi], bb[ni]);
        }
        __syncthreads();
    }

#pragma unroll
    for (int mi = 0; mi < 4; mi++) {
        const int row0 = m0 + wm * 64 + mi * 16 + g;
        int i2[2] = { 0, 0 };
        if (add2) { i2[0] = idx2[row0]; i2[1] = idx2[row0 + 8]; }
#pragma unroll
        for (int ni = 0; ni < 8; ni++) {
            const int n = n0 + wn * 64 + ni * 8 + tig * 2;
#pragma unroll
            for (int q = 0; q < 4; q++) {
                int rr = row0 + ((q >= 2) ? 8 : 0);
                int nn = n + (q & 1);
                if (nn >= Nreal) continue;
                float f = acc[mi][ni][q] + bias1[nn]
                        + add1[(size_t)(rr & 63) * Nreal + nn]
                        + add2[(size_t)i2[q >> 1] * Nreal + nn];
                Cf[(size_t)rr * Nreal + nn] = f;
            }
        }
    }
}

/* ------------------------------------------------------------------ */
/* subview splits                                                      */
/* ------------------------------------------------------------------ */
__global__ void k_split_sub(const float* __restrict__ src, int pitch, int col0,
                            int rows, int cols, int padRows,
                            __nv_bfloat16* __restrict__ dh, __nv_bfloat16* __restrict__ dl)
{
    size_t total = (size_t)padRows * cols;
    for (size_t idx = (size_t)blockIdx.x * blockDim.x + threadIdx.x;
         idx < total; idx += (size_t)gridDim.x * blockDim.x) {
        int r = (int)(idx / cols);
        int c = (int)(idx - (size_t)r * cols);
        float v = (r < rows) ? src[(size_t)r * pitch + col0 + c] : 0.0f;
        __nv_bfloat16 hi, lo;
        split2(v, hi, lo);
        dh[idx] = hi; dl[idx] = lo;
    }
}

__global__ void k_split16(const float* __restrict__ src, int pitch, int col0,
                          int rows, int cols, int padRows, __half* __restrict__ d)
{
    size_t total = (size_t)padRows * cols;
    for (size_t idx = (size_t)blockIdx.x * blockDim.x + threadIdx.x;
         idx < total; idx += (size_t)gridDim.x * blockDim.x) {
        int r = (int)(idx / cols);
        int c = (int)(idx - (size_t)r * cols);
        float v = (r < rows) ? src[(size_t)r * pitch + col0 + c] : 0.0f;
        d[idx] = __float2half(v);
    }
}

/* ------------------------------------------------------------------ */
__global__ void k_userw(const float* __restrict__ user_w, const int* __restrict__ au)
{
    const int u = blockIdx.x;
    const int c = threadIdx.x;
    float v = 0.0f;
    if (u < U_) v = user_w[(size_t)au[u] * H_ + c];
    __nv_bfloat16 hi, lo;
    split2(v, hi, lo);
    g_uwh[u * H_ + c] = hi;
    g_uwl[u * H_ + c] = lo;
}

__global__ void k_cvec(const float* __restrict__ fcpt_b, const float* __restrict__ W_ih,
                       const float* __restrict__ b_ih, const float* __restrict__ b_hh)
{
    const int n = blockIdx.x * blockDim.x + threadIdx.x;
    if (n >= H_) return;
    float a = b_ih[n] + b_hh[n];
    for (int k = 0; k < H_; k++) a += fcpt_b[k] * W_ih[(size_t)n * H_ + k];
    g_cvec[n] = a;
}

__global__ __launch_bounds__(512)
void k_pre(const int* __restrict__ x, const int* __restrict__ ts)
{
    const int m = blockIdx.x;
    const int c = threadIdx.x;
    const int xm = x[m], tm = ts[m];
    g_pre[(size_t)m * H_ + c] = g_E2[(size_t)xm * H_ + c] + g_T2[(size_t)tm * H_ + c];
}

/* T2 variant with cvec bias added in epilogue is handled via hmma_gemm bias1 */

/* ------------------------------------------------------------------ */
__global__ void k_week(const float* __restrict__ sigma,
                       const float* __restrict__ wwi,
                       const int*   __restrict__ wm,
                       const float* __restrict__ wenc)
{
    const int slot = blockIdx.x;
    const int tid  = threadIdx.x;
    __shared__ float ww[168];
    __shared__ float red[256];

    float sig    = fabsf(sigma[slot]);
    float inv2s2 = 1.0f / (2.0f * sig * sig);
    float coef   = rsqrtf(2.0f * PI_F * sig * sig);

    float v = 0.0f;
    if (tid < 168) {
        float x = wwi[slot * 168 + tid];
        v = coef * expf(-x * x * inv2s2);
        ww[tid] = v;
    }
    red[tid] = v;
    __syncthreads();
    for (int off = 128; off > 0; off >>= 1) {
        if (tid < off) red[tid] += red[tid + off];
        __syncthreads();
    }
    const float inv = 1.0f / red[0];

    float acc = 0.0f;
    for (int k = 0; k < 168; k++) {
        int row = wm[slot * 168 + k];
        acc += (ww[k] * inv) * wenc[row * H2_ + tid];
    }
    g_T[slot * H2_ + tid] = acc;
}

/* ------------------------------------------------------------------ */
/* RNN: cluster(8) HMMA (unchanged from R5)                            */
/* ------------------------------------------------------------------ */
#define WPAD 520
#define WST_H    0
#define WST_L    66560
#define HB0H     133120
#define HB0L     141440
#define HB1H     149760
#define HB1L     158080
#define PSUM_OFF 166400
#define RNN_SMEM 182784

__global__ __cluster_dims__(8, 1, 1) __launch_bounds__(256, 1)
void k_rnn(const float* __restrict__ pre, const float* __restrict__ Whh,
           const float* __restrict__ h0, float* __restrict__ out)
{
    extern __shared__ char sm[];
    const uint32_t sb = smem_u32(sm);
    const int tid = threadIdx.x;
    const int warp = tid >> 5, lane = tid & 31;
    const int gu = blockIdx.x >> 3;
    uint32_t gn;
    asm("mov.u32 %0, %%cluster_ctarank;" : "=r"(gn));

    __nv_bfloat16* wsth = (__nv_bfloat16*)(sm + WST_H);
    __nv_bfloat16* wstl = (__nv_bfloat16*)(sm + WST_L);

    for (int idx = tid; idx < 64 * 512; idx += 256) {
        int r = idx >> 9, c = idx & 511;
        float v = Whh[(size_t)(gn * 64 + r) * H_ + c];
        __nv_bfloat16 hi, lo;
        split2(v, hi, lo);
        wsth[r * WPAD + c] = hi;
        wstl[r * WPAD + c] = lo;
    }
    __syncthreads();

    uint32_t Wh[4][4][4], Wl[4][4][4];
    {
        const uint32_t la = (uint32_t)(lane & 15) * (WPAD * 2)
                          + (uint32_t)(lane >> 4) * 16u;
#pragma unroll
        for (int mi = 0; mi < 4; mi++)
#pragma unroll
            for (int kt = 0; kt < 4; kt++) {
                uint32_t ofs = la + (uint32_t)mi * 16u * (WPAD * 2)
                             + (uint32_t)(warp * 64 + kt * 16) * 2u;
                LDSM4(Wh[mi][kt][0], Wh[mi][kt][1], Wh[mi][kt][2], Wh[mi][kt][3],
                      sb + WST_H + ofs);
                LDSM4(Wl[mi][kt][0], Wl[mi][kt][1], Wl[mi][kt][2], Wl[mi][kt][3],
                      sb + WST_L + ofs);
            }
    }

    __nv_bfloat16* hb00 = (__nv_bfloat16*)(sm + HB0H);
    __nv_bfloat16* hb01 = (__nv_bfloat16*)(sm + HB0L);
    __nv_bfloat16* hb10 = (__nv_bfloat16*)(sm + HB1H);
    __nv_bfloat16* hb11 = (__nv_bfloat16*)(sm + HB1L);
    const __nv_bfloat16 z = __float2bfloat16(0.0f);
    for (int idx = tid; idx < 8 * WPAD; idx += 256) {
        hb00[idx] = z; hb01[idx] = z; hb10[idx] = z; hb11[idx] = z;
    }
    __syncthreads();
    for (int idx = tid; idx < 4 * 512; idx += 256) {
        int u = idx >> 9, c = idx & 511;
        float v = h0[(size_t)(gu * 4 + u) * H_ + c];
        __nv_bfloat16 hi, lo;
        split2(v, hi, lo);
        hb00[u * WPAD + c] = hi;
        hb01[u * WPAD + c] = lo;
    }
    CLUSTER_SYNC();

    float* psum = (float*)(sm + PSUM_OFF);
    const int n_out = tid & 63, u_out = tid >> 6;
    const int mi_r = n_out >> 4, r16 = n_out & 15;
    const int lr = ((r16 & 7) << 2) + (u_out >> 1);
    const int cc = (u_out & 1) + ((r16 >> 3) << 1);
    const uint32_t bbase = (uint32_t)(lane >> 2) * (WPAD * 2)
                         + (uint32_t)(warp * 64 + (lane & 3) * 2) * 2u;

    for (int s = 0; s < S_; s++) {
        const int cb = s & 1;
        const size_t o = (size_t)s * U_ * H_ + (size_t)(gu * 4 + u_out) * H_
                       + gn * 64 + n_out;
        float pv = __ldcg(pre + o);

        const uint32_t hbh = sb + (cb ? HB1H : HB0H);
        const uint32_t hbl = sb + (cb ? HB1L : HB0L);

        float acc[4][4];
#pragma unroll
        for (int mi = 0; mi < 4; mi++)
#pragma unroll
            for (int q = 0; q < 4; q++) acc[mi][q] = 0.0f;

#pragma unroll
        for (int kt = 0; kt < 4; kt++) {
            uint32_t off = bbase + (uint32_t)kt * 32u;
            uint32_t bh[2], bl[2];
            LDS32(bh[0], hbh + off); LDS32(bh[1], hbh + off + 16u);
            LDS32(bl[0], hbl + off); LDS32(bl[1], hbl + off + 16u);
#pragma unroll
            for (int mi = 0; mi < 4; mi++) {
                mma16816(acc[mi], Wh[mi][kt], bh);
                mma16816(acc[mi], Wl[mi][kt], bh);
                mma16816(acc[mi], Wh[mi][kt], bl);
            }
        }
#pragma unroll
        for (int mi = 0; mi < 4; mi++) {
            float4 v4 = make_float4(acc[mi][0], acc[mi][1], acc[mi][2], acc[mi][3]);
            *(float4*)&psum[(warp * 4 + mi) * 128 + lane * 4] = v4;
        }
        __syncthreads();

        float v = 0.0f;
#pragma unroll
        for (int w2 = 0; w2 < 8; w2++)
            v += psum[(w2 * 4 + mi_r) * 128 + lr * 4 + cc];

        float hv = tanhf(pv + v);
        out[o] = hv;

        if (s < S_ - 1) {
            __nv_bfloat16 hi, lo;
            split2(hv, hi, lo);
            uint16_t hu = *(uint16_t*)&hi, lu = *(uint16_t*)&lo;
            uint32_t dsth = sb + (cb ? HB0H : HB1H)
                          + (uint32_t)(u_out * WPAD + gn * 64 + n_out) * 2u;
            uint32_t dstl = dsth + (HB0L - HB0H);
#pragma unroll
            for (int r = 0; r < 8; r++) {
                st_cluster_b16(dsth, (uint32_t)r, hu);
                st_cluster_b16(dstl, (uint32_t)r, lu);
            }
            CLUSTER_SYNC();
        }
    }
}

/* ------------------------------------------------------------------ */
__global__ void k_w(const float* __restrict__ t, const float* __restrict__ s)
{
    const int i = blockIdx.x, u = blockIdx.y;
    const int j = threadIdx.x;
    __shared__ float red[256];

    float wv = 0.0f;
    if (j <= i) {
        float dt = t[i * U_ + u] - t[j * U_ + u];
        float d0 = s[((size_t)i * U_ + u) * 2 + 0] - s[((size_t)j * U_ + u) * 2 + 0];
        float d1 = s[((size_t)i * U_ + u) * 2 + 1] - s[((size_t)j * U_ + u) * 2 + 1];
        float ds = sqrtf(d0 * d0 + d1 * d1);
        float ft = (cosf(dt * (2.0f * PI_F / 86400.0f)) + 1.0f) * 0.5f
                 * expf(-(dt / 86400.0f) * 0.1f);
        float fs = expf(-ds * 100.0f);
        wv = ft * fs + 1e-10f;
    }
    g_w[((size_t)u * S_ + i) * S_ + j] = wv;

    red[j] = wv;
    __syncthreads();
    for (int off = 128; off > 0; off >>= 1) {
        if (j < off) red[j] += red[j + off];
        __syncthreads();
    }
    if (j == 0) g_den[u * S_ + i] = red[0];
}

/* ------------------------------------------------------------------ */
__global__ __launch_bounds__(512)
void k_att()
{
    __shared__ float wsh[8 * 64];
    const int it = blockIdx.x;
    const int u  = blockIdx.y;
    const int i0 = it * 8;
    const int h  = threadIdx.x;
    const float* wb = g_w + (size_t)u * S_ * S_;

    float acc[8];
#pragma unroll
    for (int ii = 0; ii < 8; ii++) acc[ii] = 0.0f;

    const int jend = i0 + 8;
    for (int j0 = 0; j0 < jend; j0 += 64) {
        int ii = h >> 6, jj = h & 63;
        wsh[h] = wb[(size_t)(i0 + ii) * S_ + j0 + jj];
        __syncthreads();
        int jcnt = (jend - j0 < 64) ? (jend - j0) : 64;
        for (int q = 0; q < jcnt; q++) {
            float ov = g_out[((size_t)(j0 + q) * U_ + u) * H_ + h];
#pragma unroll
            for (int ii2 = 0; ii2 < 8; ii2++)
                acc[ii2] += wsh[ii2 * 64 + q] * ov;
        }
        __syncthreads();
    }
#pragma unroll
    for (int ii = 0; ii < 8; ii++) {
        float d = g_den[u * S_ + i0 + ii];
        float f = acc[ii] / d;
        g_ow16[((size_t)(i0 + ii) * U_ + u) * H_ + h] = __float2half(f);
    }
}

/* ------------------------------------------------------------------ */
__global__ void k_hfinal(float* __restrict__ dst)
{
    int i = blockIdx.x * blockDim.x + threadIdx.x;
    if (i < U_ * H_) dst[i] = g_out[(size_t)(S_ - 1) * U_ * H_ + i];
}

/* ------------------------------------------------------------------ */
extern "C" void kernel_launch(void* const* d_in, const int* in_sizes, int n_in,
                              void* d_out, int out_size)
{
    const int*   x        = (const int*)  d_in[0];
    const float* t        = (const float*)d_in[1];
    const int*   t_slot   = (const int*)  d_in[2];
    const float* s        = (const float*)d_in[3];
    const int*   y_t_slot = (const int*)  d_in[5];
    const float* h0       = (const float*)d_in[7];
    const int*   act_user = (const int*)  d_in[8];
    const int*   wm       = (const int*)  d_in[9];
    const float* wwi      = (const float*)d_in[10];
    const float* sigma    = (const float*)d_in[11];
    const float* enc_w    = (const float*)d_in[12];
    const float* user_w   = (const float*)d_in[13];
    const float* wenc     = (const float*)d_in[14];
    const float* fcpt_w   = (const float*)d_in[15];
    const float* fcpt_b   = (const float*)d_in[16];
    const float* W_ih     = (const float*)d_in[17];
    const float* W_hh     = (const float*)d_in[18];
    const float* b_ih     = (const float*)d_in[19];
    const float* b_hh     = (const float*)d_in[20];
    const float* fc_w     = (const float*)d_in[21];
    const float* fc_b     = (const float*)d_in[22];
    float* out = (float*)d_out;

    void *pT, *pEnch, *pEncl, *pM1h, *pM1l, *pE2, *pTh, *pTl, *pN1h, *pN1l, *pT2;
    void *pUwh, *pUwl, *pP2, *pP3, *pCvec;
    void *pFcpAh, *pFcpAl, *pFcpBh, *pFcpBl, *pWihh, *pWihl;
    void *pFcwA16, *pFcwBh, *pFcwBl, *pFcwCh, *pFcwCl;
    void *pPre, *pOut, *pOw16;
    cudaGetSymbolAddress(&pT, g_T);
    cudaGetSymbolAddress(&pEnch, g_ench);  cudaGetSymbolAddress(&pEncl, g_encl);
    cudaGetSymbolAddress(&pM1h, g_M1h);    cudaGetSymbolAddress(&pM1l, g_M1l);
    cudaGetSymbolAddress(&pE2, g_E2);
    cudaGetSymbolAddress(&pTh, g_Th);      cudaGetSymbolAddress(&pTl, g_Tl);
    cudaGetSymbolAddress(&pN1h, g_N1h);    cudaGetSymbolAddress(&pN1l, g_N1l);
    cudaGetSymbolAddress(&pT2, g_T2);
    cudaGetSymbolAddress(&pUwh, g_uwh);    cudaGetSymbolAddress(&pUwl, g_uwl);
    cudaGetSymbolAddress(&pP2, g_P2);      cudaGetSymbolAddress(&pP3, g_P3);
    cudaGetSymbolAddress(&pCvec, g_cvec);
    cudaGetSymbolAddress(&pFcpAh, g_fcpAh); cudaGetSymbolAddress(&pFcpAl, g_fcpAl);
    cudaGetSymbolAddress(&pFcpBh, g_fcpBh); cudaGetSymbolAddress(&pFcpBl, g_fcpBl);
    cudaGetSymbolAddress(&pWihh, g_wihh);  cudaGetSymbolAddress(&pWihl, g_wihl);
    cudaGetSymbolAddress(&pFcwA16, g_fcwA16);
    cudaGetSymbolAddress(&pFcwBh, g_fcwBh); cudaGetSymbolAddress(&pFcwBl, g_fcwBl);
    cudaGetSymbolAddress(&pFcwCh, g_fcwCh); cudaGetSymbolAddress(&pFcwCl, g_fcwCl);
    cudaGetSymbolAddress(&pPre, g_pre);    cudaGetSymbolAddress(&pOut, g_out);
    cudaGetSymbolAddress(&pOw16, g_ow16);

    cudaFuncSetAttribute(hmma_gemm,   cudaFuncAttributeMaxDynamicSharedMemorySize, GEMM_SMEM);
    cudaFuncSetAttribute(hmma_gemm16, cudaFuncAttributeMaxDynamicSharedMemorySize, GEMM16_SMEM);
    cudaFuncSetAttribute(k_rnn,       cudaFuncAttributeMaxDynamicSharedMemorySize, RNN_SMEM);

    /* 1 */ k_week<<<168, 256>>>(sigma, wwi, wm, wenc);
    /* 2 */ k_split_sub<<<256, 256>>>(enc_w,  H_,  0,    V_,   H_,  VPAD,
                              (__nv_bfloat16*)pEnch, (__nv_bfloat16*)pEncl);
    /* 3 */ k_split_sub<<<128, 256>>>(fcpt_w, 768, 0,    512,  H_,  512,
                              (__nv_bfloat16*)pFcpAh, (__nv_bfloat16*)pFcpAl);
    /* 4 */ k_split_sub<<<128, 256>>>(W_ih,   H_,  0,    512,  H_,  512,
                              (__nv_bfloat16*)pWihh, (__nv_bfloat16*)pWihl);
    /* 5 */ hmma_gemm<<<dim3(2, VPAD / 128), 256, GEMM_SMEM>>>(
        (const __nv_bfloat16*)pEnch, (const __nv_bfloat16*)pEncl,
        (const __nv_bfloat16*)pFcpAh, (const __nv_bfloat16*)pFcpAl,
        nullptr, nullptr, (__nv_bfloat16*)pM1h, (__nv_bfloat16*)pM1l, H_, H_);
    /* 6 (ncu window) */ hmma_gemm<<<dim3(2, VPAD / 128), 256, GEMM_SMEM>>>(
        (const __nv_bfloat16*)pM1h, (const __nv_bfloat16*)pM1l,
        (const __nv_bfloat16*)pWihh, (const __nv_bfloat16*)pWihl,
        nullptr, (float*)pE2, nullptr, nullptr, H_, H_);
    /* 7 */ k_split_sub<<<32, 256>>>((const float*)pT, H2_, 0, 168, H2_, 256,
                              (__nv_bfloat16*)pTh, (__nv_bfloat16*)pTl);
    /* 8 */ k_split_sub<<<64, 256>>>(fcpt_w,  768, 512,  512,  H2_, 512,
                              (__nv_bfloat16*)pFcpBh, (__nv_bfloat16*)pFcpBl);
    /* 9 */ hmma_gemm<<<dim3(2, 2), 256, GEMM_SMEM>>>(
        (const __nv_bfloat16*)pTh, (const __nv_bfloat16*)pTl,
        (const __nv_bfloat16*)pFcpBh, (const __nv_bfloat16*)pFcpBl,
        nullptr, nullptr, (__nv_bfloat16*)pN1h, (__nv_bfloat16*)pN1l, H2_, H_);
    /* 10 */ k_cvec<<<2, 256>>>(fcpt_b, W_ih, b_ih, b_hh);
    /* 11 */ hmma_gemm<<<dim3(2, 2), 256, GEMM_SMEM>>>(
        (const __nv_bfloat16*)pN1h, (const __nv_bfloat16*)pN1l,
        (const __nv_bfloat16*)pWihh, (const __nv_bfloat16*)pWihl,
        (const float*)pCvec, (float*)pT2, nullptr, nullptr, H_, H_);
    /* 12 */ k_split_sub<<<256, 256>>>(fc_w, 1280, 512, V_, H_, VPAD,
                              (__nv_bfloat16*)pFcwBh, (__nv_bfloat16*)pFcwBl);
    /* 13 */ k_userw<<<128, 512>>>(user_w, act_user);
    /* 14 */ hmma_gemm<<<dim3(VPAD / 256, 1), 256, GEMM_SMEM>>>(
        (const __nv_bfloat16*)pUwh, (const __nv_bfloat16*)pUwl,
        (const __nv_bfloat16*)pFcwBh, (const __nv_bfloat16*)pFcwBl,
        nullptr, (float*)pP2, nullptr, nullptr, H_, V_);
    /* 15 */ k_split_sub<<<256, 256>>>(fc_w, 1280, 1024, V_, H2_, VPAD,
                              (__nv_bfloat16*)pFcwCh, (__nv_bfloat16*)pFcwCl);
    /* 16 */ hmma_gemm<<<dim3(VPAD / 256, 2), 256, GEMM_SMEM>>>(
        (const __nv_bfloat16*)pTh, (const __nv_bfloat16*)pTl,
        (const __nv_bfloat16*)pFcwCh, (const __nv_bfloat16*)pFcwCl,
        nullptr, (float*)pP3, nullptr, nullptr, H2_, V_);
    /* 17 */ k_split16<<<256, 256>>>(fc_w, 1280, 0, V_, H_, VPAD, (__half*)pFcwA16);
    /* 18 */ k_pre<<<MSU, 512>>>(x, t_slot);
    /* 19 */ k_rnn<<<128, 256, RNN_SMEM>>>((const float*)pPre, W_hh, h0, (float*)pOut);
    /* 20 */ k_w<<<dim3(S_, U_), 256>>>(t, s);
    /* 21 */ k_att<<<dim3(S_ / 8, U_), 512>>>();
    /* 22 */ hmma_gemm16<<<dim3(VPAD / 256, MSU / 128), 256, GEMM16_SMEM>>>(
        (const __half*)pOw16, (const __half*)pFcwA16,
        fc_b, (const float*)pP2, (const float*)pP3, y_t_slot,
        out, H_, V_);

    size_t yelems = (size_t)S_ * U_ * V_;
    if ((size_t)out_size >= yelems + U_ * H_)
        k_hfinal<<<(U_ * H_ + 255) / 256, 256>>>(out + yelems);
}

// round 7
// speedup vs baseline: 3.1208x; 1.0138x over previous
#include <cuda_runtime.h>
#include <cuda_bf16.h>
#include <cuda_fp16.h>
#include <math.h>
#include <stdint.h>

#define S_  256
#define U_  64
#define H_  512
#define H2_ 256
#define V_  5000
#define MSU 16384   /* S*U */
#define VPAD 5120
#define PI_F 3.14159265358979323846f

/* ------------------------------------------------------------------ */
/* scratch (device globals; allocation-free)                           */
/* ------------------------------------------------------------------ */
__device__ float         g_T    [168 * H2_];
__device__ __nv_bfloat16 g_ench [(size_t)VPAD * H_];
__device__ __nv_bfloat16 g_encl [(size_t)VPAD * H_];
__device__ __nv_bfloat16 g_M1h  [(size_t)VPAD * H_];
__device__ __nv_bfloat16 g_M1l  [(size_t)VPAD * H_];
__device__ float         g_E2   [(size_t)VPAD * H_];
__device__ __nv_bfloat16 g_Th   [256 * H2_];
__device__ __nv_bfloat16 g_Tl   [256 * H2_];
__device__ __nv_bfloat16 g_N1h  [256 * H_];
__device__ __nv_bfloat16 g_N1l  [256 * H_];
__device__ float         g_T2   [256 * H_];
__device__ __nv_bfloat16 g_uwh  [128 * H_];
__device__ __nv_bfloat16 g_uwl  [128 * H_];
__device__ float         g_P2   [(size_t)128 * V_];
__device__ float         g_P3   [(size_t)256 * V_];
__device__ __nv_bfloat16 g_fcpAh[512 * H_];
__device__ __nv_bfloat16 g_fcpAl[512 * H_];
__device__ __nv_bfloat16 g_fcpBh[512 * H2_];
__device__ __nv_bfloat16 g_fcpBl[512 * H2_];
__device__ __nv_bfloat16 g_wihh [512 * H_];
__device__ __nv_bfloat16 g_wihl [512 * H_];
__device__ __half        g_fcwA16[(size_t)VPAD * H_];
__device__ __nv_bfloat16 g_fcwBh[(size_t)VPAD * H_];
__device__ __nv_bfloat16 g_fcwBl[(size_t)VPAD * H_];
__device__ __nv_bfloat16 g_fcwCh[(size_t)VPAD * H2_];
__device__ __nv_bfloat16 g_fcwCl[(size_t)VPAD * H2_];
__device__ float         g_cvec [H_];
__device__ __half        g_out16[(size_t)MSU * H_];   /* RNN h, [s][u][h] */
__device__ float         g_hfin [U_ * H_];
__device__ __half        g_w16  [(size_t)U_ * S_ * S_];
__device__ float         g_den  [(size_t)U_ * S_];
__device__ __half        g_ow16 [(size_t)MSU * H_];

/* ------------------------------------------------------------------ */
/* helpers                                                             */
/* ------------------------------------------------------------------ */
__device__ __forceinline__ uint32_t smem_u32(const void* p) {
    uint32_t a;
    asm("{ .reg .u64 t; cvta.to.shared.u64 t, %1; cvt.u32.u64 %0, t; }"
        : "=r"(a) : "l"(p));
    return a;
}

#define CP_ASYNC16(dst, src) \
    asm volatile("cp.async.cg.shared.global [%0], [%1], 16;" :: "r"(dst), "l"(src))
#define CP_COMMIT() asm volatile("cp.async.commit_group;" ::: "memory")
#define CP_WAIT(n)  asm volatile("cp.async.wait_group %0;" :: "n"(n) : "memory")

#define LDS32(v, addr) \
    asm volatile("ld.shared.b32 %0, [%1];" : "=r"(v) : "r"(addr))

#define LDSM4(r0, r1, r2, r3, a) \
    asm volatile("ldmatrix.sync.aligned.m8n8.x4.shared.b16 {%0,%1,%2,%3}, [%4];" \
        : "=r"(r0), "=r"(r1), "=r"(r2), "=r"(r3) : "r"(a))

#define LDSM4T(r0, r1, r2, r3, a) \
    asm volatile("ldmatrix.sync.aligned.m8n8.x4.trans.shared.b16 {%0,%1,%2,%3}, [%4];" \
        : "=r"(r0), "=r"(r1), "=r"(r2), "=r"(r3) : "r"(a))

#define CLUSTER_ARRIVE() \
    asm volatile("barrier.cluster.arrive.aligned;" ::: "memory")
#define CLUSTER_WAIT() \
    asm volatile("barrier.cluster.wait.aligned;" ::: "memory")
#define CLUSTER_SYNC() do { CLUSTER_ARRIVE(); CLUSTER_WAIT(); } while (0)

__device__ __forceinline__ void st_cluster_b32(uint32_t addr, uint32_t rank, uint32_t v) {
    asm volatile(
        "{ .reg .b32 ra; mapa.shared::cluster.u32 ra, %0, %1; "
        "st.shared::cluster.b32 [ra], %2; }"
        :: "r"(addr), "r"(rank), "r"(v) : "memory");
}

__device__ __forceinline__ void mma16816(float* c, const uint32_t* a, const uint32_t* b)
{
    asm volatile(
        "mma.sync.aligned.m16n8k16.row.col.f32.bf16.bf16.f32 "
        "{%0,%1,%2,%3}, {%4,%5,%6,%7}, {%8,%9}, {%0,%1,%2,%3};"
        : "+f"(c[0]), "+f"(c[1]), "+f"(c[2]), "+f"(c[3])
        : "r"(a[0]), "r"(a[1]), "r"(a[2]), "r"(a[3]), "r"(b[0]), "r"(b[1]));
}

__device__ __forceinline__ void mma16816h(float* c, const uint32_t* a, const uint32_t* b)
{
    asm volatile(
        "mma.sync.aligned.m16n8k16.row.col.f32.f16.f16.f32 "
        "{%0,%1,%2,%3}, {%4,%5,%6,%7}, {%8,%9}, {%0,%1,%2,%3};"
        : "+f"(c[0]), "+f"(c[1]), "+f"(c[2]), "+f"(c[3])
        : "r"(a[0]), "r"(a[1]), "r"(a[2]), "r"(a[3]), "r"(b[0]), "r"(b[1]));
}

__device__ __forceinline__ void split2(float v, __nv_bfloat16& h, __nv_bfloat16& l)
{
    h = __float2bfloat16(v);
    l = __float2bfloat16(v - __bfloat162float(h));
}

/* ------------------------------------------------------------------ */
/* split-bf16 HMMA GEMM (3-term) — unchanged                           */
/* ------------------------------------------------------------------ */
#define SWH 40
#define STAGE_B  61440
#define OFF_AL   10240
#define OFF_BH   20480
#define OFF_BL   40960
#define GEMM_SMEM (2 * STAGE_B)

__global__ __launch_bounds__(256, 1)
void hmma_gemm(const __nv_bfloat16* __restrict__ Ah, const __nv_bfloat16* __restrict__ Al,
               const __nv_bfloat16* __restrict__ Bh, const __nv_bfloat16* __restrict__ Bl,
               const float* __restrict__ bias1,
               float* __restrict__ Cf,
               __nv_bfloat16* __restrict__ Ch, __nv_bfloat16* __restrict__ Cl,
               int K, int Nreal)
{
    extern __shared__ char smem[];
    const uint32_t sbase = smem_u32(smem);
    const int tid  = threadIdx.x;
    const int m0   = blockIdx.y * 128;
    const int n0   = blockIdx.x * 256;
    const int warp = tid >> 5, lane = tid & 31;
    const int wm = warp >> 2, wn = warp & 3;
    const int g  = lane >> 2, tig = lane & 3;
    const int L = K >> 5;

    const uint32_t aoffc = ((uint32_t)(wm * 64 + (lane & 15)) * SWH) * 2u
                         + (uint32_t)(lane >> 4) * 16u;
    const int sel  = (lane >> 3) & 3;
    const uint32_t boffc = ((uint32_t)(wn * 64 + ((sel & 2) << 2) + (lane & 7)) * SWH) * 2u
                         + (uint32_t)(sel & 1) * 16u;

    float acc[4][8][4];
#pragma unroll
    for (int mi = 0; mi < 4; mi++)
#pragma unroll
        for (int ni = 0; ni < 8; ni++)
#pragma unroll
            for (int q = 0; q < 4; q++) acc[mi][ni][q] = 0.0f;

    auto load_stage = [&](int chunk, int buf) {
        const uint32_t sg = sbase + (uint32_t)buf * STAGE_B;
        const int k0 = chunk << 5;
#pragma unroll 2
        for (int idx = tid; idx < 512; idx += 256) {
            int r = idx >> 2, c = idx & 3;
            uint32_t dsto = (uint32_t)(r * SWH + c * 8) * 2u;
            size_t srco = (size_t)(m0 + r) * K + k0 + c * 8;
            CP_ASYNC16(sg + dsto,            Ah + srco);
            CP_ASYNC16(sg + OFF_AL + dsto,   Al + srco);
        }
#pragma unroll 4
        for (int idx = tid; idx < 1024; idx += 256) {
            int r = idx >> 2, c = idx & 3;
            uint32_t dsto = (uint32_t)(r * SWH + c * 8) * 2u;
            size_t srco = (size_t)(n0 + r) * K + k0 + c * 8;
            CP_ASYNC16(sg + OFF_BH + dsto,   Bh + srco);
            CP_ASYNC16(sg + OFF_BL + dsto,   Bl + srco);
        }
        CP_COMMIT();
    };

    load_stage(0, 0);

    for (int i = 0; i < L; i++) {
        if (i + 1 < L) { load_stage(i + 1, (i + 1) & 1); CP_WAIT(1); }
        else           { CP_WAIT(0); }
        __syncthreads();

        const uint32_t sg = sbase + (uint32_t)(i & 1) * STAGE_B;
#pragma unroll
        for (int ks = 0; ks < 2; ks++) {
            const uint32_t kb = (uint32_t)ks * 32u;
            uint32_t ah[4][4], al[4][4], bb[8][2];
#pragma unroll
            for (int mi = 0; mi < 4; mi++)
                LDSM4(ah[mi][0], ah[mi][1], ah[mi][2], ah[mi][3],
                      sg + kb + aoffc + (uint32_t)mi * (16 * SWH * 2));
#pragma unroll
            for (int n2 = 0; n2 < 4; n2++)
                LDSM4(bb[2*n2][0], bb[2*n2][1], bb[2*n2+1][0], bb[2*n2+1][1],
                      sg + OFF_BH + kb + boffc + (uint32_t)n2 * (16 * SWH * 2));
#pragma unroll
            for (int mi = 0; mi < 4; mi++)
#pragma unroll
                for (int ni = 0; ni < 8; ni++)
                    mma16816(acc[mi][ni], ah[mi], bb[ni]);
#pragma unroll
            for (int mi = 0; mi < 4; mi++)
                LDSM4(al[mi][0], al[mi][1], al[mi][2], al[mi][3],
                      sg + OFF_AL + kb + aoffc + (uint32_t)mi * (16 * SWH * 2));
#pragma unroll
            for (int mi = 0; mi < 4; mi++)
#pragma unroll
                for (int ni = 0; ni < 8; ni++)
                    mma16816(acc[mi][ni], al[mi], bb[ni]);
#pragma unroll
            for (int n2 = 0; n2 < 4; n2++)
                LDSM4(bb[2*n2][0], bb[2*n2][1], bb[2*n2+1][0], bb[2*n2+1][1],
                      sg + OFF_BL + kb + boffc + (uint32_t)n2 * (16 * SWH * 2));
#pragma unroll
            for (int mi = 0; mi < 4; mi++)
#pragma unroll
                for (int ni = 0; ni < 8; ni++)
                    mma16816(acc[mi][ni], ah[mi], bb[ni]);
        }
        __syncthreads();
    }

#pragma unroll
    for (int mi = 0; mi < 4; mi++) {
        const int row0 = m0 + wm * 64 + mi * 16 + g;
#pragma unroll
        for (int ni = 0; ni < 8; ni++) {
            const int n = n0 + wn * 64 + ni * 8 + tig * 2;
#pragma unroll
            for (int q = 0; q < 4; q++) {
                int rr = row0 + ((q >= 2) ? 8 : 0);
                int nn = n + (q & 1);
                if (nn >= Nreal) continue;
                float f = acc[mi][ni][q];
                if (bias1) f += bias1[nn];
                if (Cf) {
                    Cf[(size_t)rr * Nreal + nn] = f;
                } else {
                    __nv_bfloat16 hi, lo;
                    split2(f, hi, lo);
                    Ch[(size_t)rr * Nreal + nn] = hi;
                    Cl[(size_t)rr * Nreal + nn] = lo;
                }
            }
        }
    }
}

/* ------------------------------------------------------------------ */
/* fp16 single-product HMMA GEMM (final projection) — unchanged        */
/* ------------------------------------------------------------------ */
#define SWH2      72
#define G16_OFFB  18432
#define G16_STAGE 55296
#define GEMM16_SMEM (2 * G16_STAGE)

__global__ __launch_bounds__(256, 1)
void hmma_gemm16(const __half* __restrict__ A, const __half* __restrict__ B,
                 const float* __restrict__ bias1,
                 const float* __restrict__ add1,
                 const float* __restrict__ add2, const int* __restrict__ idx2,
                 float* __restrict__ Cf, int K, int Nreal)
{
    extern __shared__ char smem[];
    const uint32_t sbase = smem_u32(smem);
    const int tid  = threadIdx.x;
    const int m0   = blockIdx.y * 128;
    const int n0   = blockIdx.x * 256;
    const int warp = tid >> 5, lane = tid & 31;
    const int wm = warp >> 2, wn = warp & 3;
    const int g  = lane >> 2, tig = lane & 3;
    const int L = K >> 6;

    const uint32_t aoffc = ((uint32_t)(wm * 64 + (lane & 15)) * SWH2) * 2u
                         + (uint32_t)(lane >> 4) * 16u;
    const int sel  = (lane >> 3) & 3;
    const uint32_t boffc = ((uint32_t)(wn * 64 + ((sel & 2) << 2) + (lane & 7)) * SWH2) * 2u
                         + (uint32_t)(sel & 1) * 16u;

    float acc[4][8][4];
#pragma unroll
    for (int mi = 0; mi < 4; mi++)
#pragma unroll
        for (int ni = 0; ni < 8; ni++)
#pragma unroll
            for (int q = 0; q < 4; q++) acc[mi][ni][q] = 0.0f;

    auto load_stage = [&](int chunk, int buf) {
        const uint32_t sg = sbase + (uint32_t)buf * G16_STAGE;
        const int k0 = chunk << 6;
#pragma unroll 4
        for (int idx = tid; idx < 1024; idx += 256) {
            int r = idx >> 3, c = idx & 7;
            CP_ASYNC16(sg + (uint32_t)(r * SWH2 + c * 8) * 2u,
                       A + (size_t)(m0 + r) * K + k0 + c * 8);
        }
#pragma unroll 8
        for (int idx = tid; idx < 2048; idx += 256) {
            int r = idx >> 3, c = idx & 7;
            CP_ASYNC16(sg + G16_OFFB + (uint32_t)(r * SWH2 + c * 8) * 2u,
                       B + (size_t)(n0 + r) * K + k0 + c * 8);
        }
        CP_COMMIT();
    };

    load_stage(0, 0);

    for (int i = 0; i < L; i++) {
        if (i + 1 < L) { load_stage(i + 1, (i + 1) & 1); CP_WAIT(1); }
        else           { CP_WAIT(0); }
        __syncthreads();

        const uint32_t sg = sbase + (uint32_t)(i & 1) * G16_STAGE;
#pragma unroll
        for (int ks = 0; ks < 4; ks++) {
            const uint32_t kb = (uint32_t)ks * 32u;
            uint32_t ah[4][4], bb[8][2];
#pragma unroll
            for (int mi = 0; mi < 4; mi++)
                LDSM4(ah[mi][0], ah[mi][1], ah[mi][2], ah[mi][3],
                      sg + kb + aoffc + (uint32_t)mi * (16 * SWH2 * 2));
#pragma unroll
            for (int n2 = 0; n2 < 4; n2++)
                LDSM4(bb[2*n2][0], bb[2*n2][1], bb[2*n2+1][0], bb[2*n2+1][1],
                      sg + G16_OFFB + kb + boffc + (uint32_t)n2 * (16 * SWH2 * 2));
#pragma unroll
            for (int mi = 0; mi < 4; mi++)
#pragma unroll
                for (int ni = 0; ni < 8; ni++)
                    mma16816h(acc[mi][ni], ah[mi], bb[ni]);
        }
        __syncthreads();
    }

#pragma unroll
    for (int mi = 0; mi < 4; mi++) {
        const int row0 = m0 + wm * 64 + mi * 16 + g;
        int i2[2] = { 0, 0 };
        if (add2) { i2[0] = idx2[row0]; i2[1] = idx2[row0 + 8]; }
#pragma unroll
        for (int ni = 0; ni < 8; ni++) {
            const int n = n0 + wn * 64 + ni * 8 + tig * 2;
#pragma unroll
            for (int q = 0; q < 4; q++) {
                int rr = row0 + ((q >= 2) ? 8 : 0);
                int nn = n + (q & 1);
                if (nn >= Nreal) continue;
                float f = acc[mi][ni][q] + bias1[nn]
                        + add1[(size_t)(rr & 63) * Nreal + nn]
                        + add2[(size_t)i2[q >> 1] * Nreal + nn];
                Cf[(size_t)rr * Nreal + nn] = f;
            }
        }
    }
}

/* ------------------------------------------------------------------ */
/* attention HMMA: ow[i,u,h] = (sum_j w16[u,i,j] * out16[j,u,h])/den   */
/* grid (2 h-tiles, 2 i-tiles, 64 u); block 256 (8 warps 2x4)          */
/* ------------------------------------------------------------------ */
#define ATT_SWA   40
#define ATT_SWB   264
#define ATT_B_OFF (128 * ATT_SWA * 2)                 /* 10240 */
#define ATT_STAGE (ATT_B_OFF + 32 * ATT_SWB * 2)      /* 27136 */
#define ATT_SMEM  (2 * ATT_STAGE)                     /* 54272 */

__global__ __launch_bounds__(256, 1)
void k_att_mma(const __half* __restrict__ w16, const __half* __restrict__ o16,
               const float* __restrict__ den, __half* __restrict__ ow)
{
    extern __shared__ char smem[];
    const uint32_t sbase = smem_u32(smem);
    const int tid  = threadIdx.x;
    const int u    = blockIdx.z;
    const int i0   = blockIdx.y * 128;
    const int h0   = blockIdx.x * 256;
    const int warp = tid >> 5, lane = tid & 31;
    const int wm = warp >> 2, wn = warp & 3;
    const int g  = lane >> 2, tig = lane & 3;
    const int L  = (i0 + 128) >> 5;

    const uint32_t aoffc = ((uint32_t)(wm * 64 + (lane & 15)) * ATT_SWA) * 2u
                         + (uint32_t)(lane >> 4) * 16u;
    const uint32_t boffc = ((uint32_t)((lane & 7) + ((lane >> 3) & 1) * 8) * ATT_SWB) * 2u
                         + (uint32_t)(lane >> 4) * 16u;

    float acc[4][8][4];
#pragma unroll
    for (int mi = 0; mi < 4; mi++)
#pragma unroll
        for (int ni = 0; ni < 8; ni++)
#pragma unroll
            for (int q = 0; q < 4; q++) acc[mi][ni][q] = 0.0f;

    auto load_stage = [&](int chunk, int buf) {
        const uint32_t sg = sbase + (uint32_t)buf * ATT_STAGE;
        const int j0 = chunk << 5;
#pragma unroll 2
        for (int idx = tid; idx < 512; idx += 256) {
            int r = idx >> 2, c = idx & 3;
            CP_ASYNC16(sg + (uint32_t)(r * ATT_SWA + c * 8) * 2u,
                       w16 + (size_t)u * (S_ * S_) + (size_t)(i0 + r) * S_ + j0 + c * 8);
        }
#pragma unroll 4
        for (int idx = tid; idx < 1024; idx += 256) {
            int r = idx >> 5, c = idx & 31;
            CP_ASYNC16(sg + ATT_B_OFF + (uint32_t)(r * ATT_SWB + c * 8) * 2u,
                       o16 + ((size_t)(j0 + r) * U_ + u) * H_ + h0 + c * 8);
        }
        CP_COMMIT();
    };

    load_stage(0, 0);

    for (int i = 0; i < L; i++) {
        if (i + 1 < L) { load_stage(i + 1, (i + 1) & 1); CP_WAIT(1); }
        else           { CP_WAIT(0); }
        __syncthreads();

        const uint32_t sg = sbase + (uint32_t)(i & 1) * ATT_STAGE;
#pragma unroll
        for (int ks = 0; ks < 2; ks++) {
            uint32_t ah[4][4], bb[8][2];
#pragma unroll
            for (int mi = 0; mi < 4; mi++)
                LDSM4(ah[mi][0], ah[mi][1], ah[mi][2], ah[mi][3],
                      sg + (uint32_t)ks * 32u + aoffc + (uint32_t)mi * (16 * ATT_SWA * 2));
#pragma unroll
            for (int n2 = 0; n2 < 4; n2++)
                LDSM4T(bb[2*n2][0], bb[2*n2][1], bb[2*n2+1][0], bb[2*n2+1][1],
                       sg + ATT_B_OFF + (uint32_t)ks * (16 * ATT_SWB * 2) + boffc
                          + (uint32_t)(wn * 64 + n2 * 16) * 2u);
#pragma unroll
            for (int mi = 0; mi < 4; mi++)
#pragma unroll
                for (int ni = 0; ni < 8; ni++)
                    mma16816h(acc[mi][ni], ah[mi], bb[ni]);
        }
        __syncthreads();
    }

    /* epilogue: divide by den, store fp16 pairs */
#pragma unroll
    for (int mi = 0; mi < 4; mi++) {
        const int ia = i0 + wm * 64 + mi * 16 + g;
        const float d0 = 1.0f / den[u * S_ + ia];
        const float d1 = 1.0f / den[u * S_ + ia + 8];
#pragma unroll
        for (int ni = 0; ni < 8; ni++) {
            const int h = h0 + wn * 64 + ni * 8 + tig * 2;
            uint32_t p0 = (uint32_t)__half_as_ushort(__float2half(acc[mi][ni][0] * d0))
                        | ((uint32_t)__half_as_ushort(__float2half(acc[mi][ni][1] * d0)) << 16);
            uint32_t p1 = (uint32_t)__half_as_ushort(__float2half(acc[mi][ni][2] * d1))
                        | ((uint32_t)__half_as_ushort(__float2half(acc[mi][ni][3] * d1)) << 16);
            ((uint32_t*)ow)[(((size_t)ia      * U_ + u) * H_ + h) >> 1] = p0;
            ((uint32_t*)ow)[(((size_t)(ia + 8)* U_ + u) * H_ + h) >> 1] = p1;
        }
    }
}

/* ------------------------------------------------------------------ */
/* subview splits                                                      */
/* ------------------------------------------------------------------ */
__global__ void k_split_sub(const float* __restrict__ src, int pitch, int col0,
                            int rows, int cols, int padRows,
                            __nv_bfloat16* __restrict__ dh, __nv_bfloat16* __restrict__ dl)
{
    size_t total = (size_t)padRows * cols;
    for (size_t idx = (size_t)blockIdx.x * blockDim.x + threadIdx.x;
         idx < total; idx += (size_t)gridDim.x * blockDim.x) {
        int r = (int)(idx / cols);
        int c = (int)(idx - (size_t)r * cols);
        float v = (r < rows) ? src[(size_t)r * pitch + col0 + c] : 0.0f;
        __nv_bfloat16 hi, lo;
        split2(v, hi, lo);
        dh[idx] = hi; dl[idx] = lo;
    }
}

__global__ void k_split16(const float* __restrict__ src, int pitch, int col0,
                          int rows, int cols, int padRows, __half* __restrict__ d)
{
    size_t total = (size_t)padRows * cols;
    for (size_t idx = (size_t)blockIdx.x * blockDim.x + threadIdx.x;
         idx < total; idx += (size_t)gridDim.x * blockDim.x) {
        int r = (int)(idx / cols);
        int c = (int)(idx - (size_t)r * cols);
        float v = (r < rows) ? src[(size_t)r * pitch + col0 + c] : 0.0f;
        d[idx] = __float2half(v);
    }
}

/* ------------------------------------------------------------------ */
__global__ void k_userw(const float* __restrict__ user_w, const int* __restrict__ au)
{
    const int u = blockIdx.x;
    const int c = threadIdx.x;
    float v = 0.0f;
    if (u < U_) v = user_w[(size_t)au[u] * H_ + c];
    __nv_bfloat16 hi, lo;
    split2(v, hi, lo);
    g_uwh[u * H_ + c] = hi;
    g_uwl[u * H_ + c] = lo;
}

__global__ void k_cvec(const float* __restrict__ fcpt_b, const float* __restrict__ W_ih,
                       const float* __restrict__ b_ih, const float* __restrict__ b_hh)
{
    const int n = blockIdx.x * blockDim.x + threadIdx.x;
    if (n >= H_) return;
    float a = b_ih[n] + b_hh[n];
    for (int k = 0; k < H_; k++) a += fcpt_b[k] * W_ih[(size_t)n * H_ + k];
    g_cvec[n] = a;
}

/* ------------------------------------------------------------------ */
__global__ void k_week(const float* __restrict__ sigma,
                       const float* __restrict__ wwi,
                       const int*   __restrict__ wm,
                       const float* __restrict__ wenc)
{
    const int slot = blockIdx.x;
    const int tid  = threadIdx.x;
    __shared__ float ww[168];
    __shared__ float red[256];

    float sig    = fabsf(sigma[slot]);
    float inv2s2 = 1.0f / (2.0f * sig * sig);
    float coef   = rsqrtf(2.0f * PI_F * sig * sig);

    float v = 0.0f;
    if (tid < 168) {
        float x = wwi[slot * 168 + tid];
        v = coef * expf(-x * x * inv2s2);
        ww[tid] = v;
    }
    red[tid] = v;
    __syncthreads();
    for (int off = 128; off > 0; off >>= 1) {
        if (tid < off) red[tid] += red[tid + off];
        __syncthreads();
    }
    const float inv = 1.0f / red[0];

    float acc = 0.0f;
    for (int k = 0; k < 168; k++) {
        int row = wm[slot * 168 + k];
        acc += (ww[k] * inv) * wenc[row * H2_ + tid];
    }
    g_T[slot * H2_ + tid] = acc;
}

/* ------------------------------------------------------------------ */
/* RNN: cluster(8) fp16 HMMA, Wh in regs / Wl in smem, fused pre gather*/
/* ------------------------------------------------------------------ */
#define WPAD 520
#define R_WH   0
#define R_WL   66560
#define R_HB0  133120
#define R_HB1  141440
#define R_PSUM 149760
#define RNN_SMEM 166144

__global__ __cluster_dims__(8, 1, 1) __launch_bounds__(256, 1)
void k_rnn(const float* __restrict__ E2, const float* __restrict__ T2,
           const int* __restrict__ x, const int* __restrict__ ts,
           const float* __restrict__ Whh, const float* __restrict__ h0,
           __half* __restrict__ out16, float* __restrict__ hfin)
{
    extern __shared__ char sm[];
    const uint32_t sb = smem_u32(sm);
    const int tid = threadIdx.x;
    const int warp = tid >> 5, lane = tid & 31;
    const int gu = blockIdx.x >> 3;
    uint32_t gn;
    asm("mov.u32 %0, %%cluster_ctarank;" : "=r"(gn));

    __half* wsth = (__half*)(sm + R_WH);
    __half* wstl = (__half*)(sm + R_WL);

    /* stage W slice (rows gn*64..+64) as fp16 hi + fp16 residual */
    for (int idx = tid; idx < 64 * 512; idx += 256) {
        int r = idx >> 9, c = idx & 511;
        float v = Whh[(size_t)(gn * 64 + r) * H_ + c];
        __half hh = __float2half(v);
        __half ll = __float2half(v - __half2float(hh));
        wsth[r * WPAD + c] = hh;
        wstl[r * WPAD + c] = ll;
    }
    __syncthreads();

    /* Wh fragments -> registers (128 regs); Wl stays in smem */
    const uint32_t la = (uint32_t)(lane & 15) * (WPAD * 2)
                      + (uint32_t)(lane >> 4) * 16u;
    uint32_t Wh[4][4][4];
#pragma unroll
    for (int mi = 0; mi < 4; mi++)
#pragma unroll
        for (int kt = 0; kt < 4; kt++) {
            uint32_t ofs = la + (uint32_t)mi * 16u * (WPAD * 2)
                         + (uint32_t)(warp * 64 + kt * 16) * 2u;
            LDSM4(Wh[mi][kt][0], Wh[mi][kt][1], Wh[mi][kt][2], Wh[mi][kt][3],
                  sb + R_WH + ofs);
        }

    /* h buffers (fp16 single) */
    __half* hb0 = (__half*)(sm + R_HB0);
    __half* hb1 = (__half*)(sm + R_HB1);
    for (int idx = tid; idx < 8 * WPAD; idx += 256) {
        hb0[idx] = __float2half(0.0f);
        hb1[idx] = __float2half(0.0f);
    }
    __syncthreads();
    for (int idx = tid; idx < 4 * 512; idx += 256) {
        int u = idx >> 9, c = idx & 511;
        hb0[u * WPAD + c] = __float2half(h0[(size_t)(gu * 4 + u) * H_ + c]);
    }
    CLUSTER_SYNC();

    float* psum = (float*)(sm + R_PSUM);
    const int n_out = tid & 63, u_out = tid >> 6;
    const int mi_r = n_out >> 4, r16 = n_out & 15;
    const int lr = ((r16 & 7) << 2) + (u_out >> 1);
    const int cc = (u_out & 1) + ((r16 >> 3) << 1);
    const int cidx = (int)gn * 64 + n_out;
    const uint32_t bbase = (uint32_t)(lane >> 2) * (WPAD * 2)
                         + (uint32_t)(warp * 64 + (lane & 3) * 2) * 2u;

    /* prefetch pre for s=0 */
    int xm = __ldg(x + gu * 4 + u_out);
    int tm = __ldg(ts + gu * 4 + u_out);
    float pv = __ldg(E2 + (size_t)xm * H_ + cidx) + __ldg(T2 + (size_t)tm * H_ + cidx);

    for (int s = 0; s < S_; s++) {
        const uint32_t hb = sb + ((s & 1) ? R_HB1 : R_HB0);

        float acc[4][4];
#pragma unroll
        for (int mi = 0; mi < 4; mi++)
#pragma unroll
            for (int q = 0; q < 4; q++) acc[mi][q] = 0.0f;

#pragma unroll
        for (int kt = 0; kt < 4; kt++) {
            uint32_t wl[4][4];
#pragma unroll
            for (int mi = 0; mi < 4; mi++)
                LDSM4(wl[mi][0], wl[mi][1], wl[mi][2], wl[mi][3],
                      sb + R_WL + la + (uint32_t)mi * 16u * (WPAD * 2)
                         + (uint32_t)(warp * 64 + kt * 16) * 2u);
            uint32_t bh[2];
            LDS32(bh[0], hb + bbase + (uint32_t)kt * 32u);
            LDS32(bh[1], hb + bbase + (uint32_t)kt * 32u + 16u);
#pragma unroll
            for (int mi = 0; mi < 4; mi++) {
                mma16816h(acc[mi], Wh[mi][kt], bh);
                mma16816h(acc[mi], wl[mi], bh);
            }
        }
#pragma unroll
        for (int mi = 0; mi < 4; mi++) {
            float4 v4 = make_float4(acc[mi][0], acc[mi][1], acc[mi][2], acc[mi][3]);
            *(float4*)&psum[(warp * 4 + mi) * 128 + lane * 4] = v4;
        }
        __syncthreads();

        float v = 0.0f;
#pragma unroll
        for (int w2 = 0; w2 < 8; w2++)
            v += psum[(w2 * 4 + mi_r) * 128 + lr * 4 + cc];

        float hv = tanhf(pv + v);
        const size_t o = (size_t)s * U_ * H_ + (size_t)(gu * 4 + u_out) * H_ + cidx;
        out16[o] = __float2half(hv);

        if (s == S_ - 1) {
            hfin[(size_t)(gu * 4 + u_out) * H_ + cidx] = hv;
        } else {
            uint32_t mine = (uint32_t)__half_as_ushort(__float2half(hv));
            uint32_t part = __shfl_xor_sync(0xffffffffu, mine, 1);
            if (!(lane & 1)) {
                uint32_t packed = mine | (part << 16);
                uint32_t dst = sb + ((s & 1) ? R_HB0 : R_HB1)
                             + (uint32_t)(u_out * WPAD + (int)gn * 64 + n_out) * 2u;
#pragma unroll
                for (int r = 0; r < 8; r++)
                    st_cluster_b32(dst, (uint32_t)r, packed);
            }
            CLUSTER_ARRIVE();
            int s1 = s + 1;
            xm = __ldg(x + s1 * U_ + gu * 4 + u_out);
            tm = __ldg(ts + s1 * U_ + gu * 4 + u_out);
            float pvn = __ldg(E2 + (size_t)xm * H_ + cidx)
                      + __ldg(T2 + (size_t)tm * H_ + cidx);
            CLUSTER_WAIT();
            pv = pvn;
        }
    }
}

/* ------------------------------------------------------------------ */
/* attention weights (fp16) and row sums den[u,i]                      */
/* ------------------------------------------------------------------ */
__global__ void k_w(const float* __restrict__ t, const float* __restrict__ s)
{
    const int i = blockIdx.x, u = blockIdx.y;
    const int j = threadIdx.x;
    __shared__ float red[256];

    float wv = 0.0f;
    if (j <= i) {
        float dt = t[i * U_ + u] - t[j * U_ + u];
        float d0 = s[((size_t)i * U_ + u) * 2 + 0] - s[((size_t)j * U_ + u) * 2 + 0];
        float d1 = s[((size_t)i * U_ + u) * 2 + 1] - s[((size_t)j * U_ + u) * 2 + 1];
        float ds = sqrtf(d0 * d0 + d1 * d1);
        float ft = (cosf(dt * (2.0f * PI_F / 86400.0f)) + 1.0f) * 0.5f
                 * expf(-(dt / 86400.0f) * 0.1f);
        float fs = expf(-ds * 100.0f);
        wv = ft * fs + 1e-10f;
    }
    g_w16[((size_t)u * S_ + i) * S_ + j] = __float2half(wv);

    red[j] = wv;
    __syncthreads();
    for (int off = 128; off > 0; off >>= 1) {
        if (j < off) red[j] += red[j + off];
        __syncthreads();
    }
    if (j == 0) g_den[u * S_ + i] = red[0];
}

/* ------------------------------------------------------------------ */
__global__ void k_hfinal(float* __restrict__ dst)
{
    int i = blockIdx.x * blockDim.x + threadIdx.x;
    if (i < U_ * H_) dst[i] = g_hfin[i];
}

/* ------------------------------------------------------------------ */
extern "C" void kernel_launch(void* const* d_in, const int* in_sizes, int n_in,
                              void* d_out, int out_size)
{
    const int*   x        = (const int*)  d_in[0];
    const float* t        = (const float*)d_in[1];
    const int*   t_slot   = (const int*)  d_in[2];
    const float* s        = (const float*)d_in[3];
    const int*   y_t_slot = (const int*)  d_in[5];
    const float* h0       = (const float*)d_in[7];
    const int*   act_user = (const int*)  d_in[8];
    const int*   wm       = (const int*)  d_in[9];
    const float* wwi      = (const float*)d_in[10];
    const float* sigma    = (const float*)d_in[11];
    const float* enc_w    = (const float*)d_in[12];
    const float* user_w   = (const float*)d_in[13];
    const float* wenc     = (const float*)d_in[14];
    const float* fcpt_w   = (const float*)d_in[15];
    const float* fcpt_b   = (const float*)d_in[16];
    const float* W_ih     = (const float*)d_in[17];
    const float* W_hh     = (const float*)d_in[18];
    const float* b_ih     = (const float*)d_in[19];
    const float* b_hh     = (const float*)d_in[20];
    const float* fc_w     = (const float*)d_in[21];
    const float* fc_b     = (const float*)d_in[22];
    float* out = (float*)d_out;

    void *pT, *pEnch, *pEncl, *pM1h, *pM1l, *pE2, *pTh, *pTl, *pN1h, *pN1l, *pT2;
    void *pUwh, *pUwl, *pP2, *pP3, *pCvec;
    void *pFcpAh, *pFcpAl, *pFcpBh, *pFcpBl, *pWihh, *pWihl;
    void *pFcwA16, *pFcwBh, *pFcwBl, *pFcwCh, *pFcwCl;
    void *pOut16, *pHfin, *pW16, *pDen, *pOw16;
    cudaGetSymbolAddress(&pT, g_T);
    cudaGetSymbolAddress(&pEnch, g_ench);  cudaGetSymbolAddress(&pEncl, g_encl);
    cudaGetSymbolAddress(&pM1h, g_M1h);    cudaGetSymbolAddress(&pM1l, g_M1l);
    cudaGetSymbolAddress(&pE2, g_E2);
    cudaGetSymbolAddress(&pTh, g_Th);      cudaGetSymbolAddress(&pTl, g_Tl);
    cudaGetSymbolAddress(&pN1h, g_N1h);    cudaGetSymbolAddress(&pN1l, g_N1l);
    cudaGetSymbolAddress(&pT2, g_T2);
    cudaGetSymbolAddress(&pUwh, g_uwh);    cudaGetSymbolAddress(&pUwl, g_uwl);
    cudaGetSymbolAddress(&pP2, g_P2);      cudaGetSymbolAddress(&pP3, g_P3);
    cudaGetSymbolAddress(&pCvec, g_cvec);
    cudaGetSymbolAddress(&pFcpAh, g_fcpAh); cudaGetSymbolAddress(&pFcpAl, g_fcpAl);
    cudaGetSymbolAddress(&pFcpBh, g_fcpBh); cudaGetSymbolAddress(&pFcpBl, g_fcpBl);
    cudaGetSymbolAddress(&pWihh, g_wihh);  cudaGetSymbolAddress(&pWihl, g_wihl);
    cudaGetSymbolAddress(&pFcwA16, g_fcwA16);
    cudaGetSymbolAddress(&pFcwBh, g_fcwBh); cudaGetSymbolAddress(&pFcwBl, g_fcwBl);
    cudaGetSymbolAddress(&pFcwCh, g_fcwCh); cudaGetSymbolAddress(&pFcwCl, g_fcwCl);
    cudaGetSymbolAddress(&pOut16, g_out16); cudaGetSymbolAddress(&pHfin, g_hfin);
    cudaGetSymbolAddress(&pW16, g_w16);    cudaGetSymbolAddress(&pDen, g_den);
    cudaGetSymbolAddress(&pOw16, g_ow16);

    cudaFuncSetAttribute(hmma_gemm,   cudaFuncAttributeMaxDynamicSharedMemorySize, GEMM_SMEM);
    cudaFuncSetAttribute(hmma_gemm16, cudaFuncAttributeMaxDynamicSharedMemorySize, GEMM16_SMEM);
    cudaFuncSetAttribute(k_att_mma,   cudaFuncAttributeMaxDynamicSharedMemorySize, ATT_SMEM);
    cudaFuncSetAttribute(k_rnn,       cudaFuncAttributeMaxDynamicSharedMemorySize, RNN_SMEM);

    /* tables & splits */
    k_week<<<168, 256>>>(sigma, wwi, wm, wenc);
    k_split_sub<<<256, 256>>>(enc_w,  H_,  0,    V_,   H_,  VPAD,
                              (__nv_bfloat16*)pEnch, (__nv_bfloat16*)pEncl);
    k_split_sub<<<128, 256>>>(fcpt_w, 768, 0,    512,  H_,  512,
                              (__nv_bfloat16*)pFcpAh, (__nv_bfloat16*)pFcpAl);
    k_split_sub<<<128, 256>>>(W_ih,   H_,  0,    512,  H_,  512,
                              (__nv_bfloat16*)pWihh, (__nv_bfloat16*)pWihl);
    hmma_gemm<<<dim3(2, VPAD / 128), 256, GEMM_SMEM>>>(
        (const __nv_bfloat16*)pEnch, (const __nv_bfloat16*)pEncl,
        (const __nv_bfloat16*)pFcpAh, (const __nv_bfloat16*)pFcpAl,
        nullptr, nullptr, (__nv_bfloat16*)pM1h, (__nv_bfloat16*)pM1l, H_, H_);
    hmma_gemm<<<dim3(2, VPAD / 128), 256, GEMM_SMEM>>>(
        (const __nv_bfloat16*)pM1h, (const __nv_bfloat16*)pM1l,
        (const __nv_bfloat16*)pWihh, (const __nv_bfloat16*)pWihl,
        nullptr, (float*)pE2, nullptr, nullptr, H_, H_);
    k_split_sub<<<32, 256>>>((const float*)pT, H2_, 0, 168, H2_, 256,
                              (__nv_bfloat16*)pTh, (__nv_bfloat16*)pTl);
    k_split_sub<<<64, 256>>>(fcpt_w,  768, 512,  512,  H2_, 512,
                              (__nv_bfloat16*)pFcpBh, (__nv_bfloat16*)pFcpBl);
    hmma_gemm<<<dim3(2, 2), 256, GEMM_SMEM>>>(
        (const __nv_bfloat16*)pTh, (const __nv_bfloat16*)pTl,
        (const __nv_bfloat16*)pFcpBh, (const __nv_bfloat16*)pFcpBl,
        nullptr, nullptr, (__nv_bfloat16*)pN1h, (__nv_bfloat16*)pN1l, H2_, H_);
    k_cvec<<<2, 256>>>(fcpt_b, W_ih, b_ih, b_hh);
    hmma_gemm<<<dim3(2, 2), 256, GEMM_SMEM>>>(
        (const __nv_bfloat16*)pN1h, (const __nv_bfloat16*)pN1l,
        (const __nv_bfloat16*)pWihh, (const __nv_bfloat16*)pWihl,
        (const float*)pCvec, (float*)pT2, nullptr, nullptr, H_, H_);
    k_split_sub<<<256, 256>>>(fc_w, 1280, 512, V_, H_, VPAD,
                              (__nv_bfloat16*)pFcwBh, (__nv_bfloat16*)pFcwBl);
    k_userw<<<128, 512>>>(user_w, act_user);
    hmma_gemm<<<dim3(VPAD / 256, 1), 256, GEMM_SMEM>>>(
        (const __nv_bfloat16*)pUwh, (const __nv_bfloat16*)pUwl,
        (const __nv_bfloat16*)pFcwBh, (const __nv_bfloat16*)pFcwBl,
        nullptr, (float*)pP2, nullptr, nullptr, H_, V_);
    k_split_sub<<<256, 256>>>(fc_w, 1280, 1024, V_, H2_, VPAD,
                              (__nv_bfloat16*)pFcwCh, (__nv_bfloat16*)pFcwCl);
    hmma_gemm<<<dim3(VPAD / 256, 2), 256, GEMM_SMEM>>>(
        (const __nv_bfloat16*)pTh, (const __nv_bfloat16*)pTl,
        (const __nv_bfloat16*)pFcwCh, (const __nv_bfloat16*)pFcwCl,
        nullptr, (float*)pP3, nullptr, nullptr, H2_, V_);
    k_split16<<<256, 256>>>(fc_w, 1280, 0, V_, H_, VPAD, (__half*)pFcwA16);

    /* RNN (fused pre gather) */
    k_rnn<<<128, 256, RNN_SMEM>>>((const float*)pE2, (const float*)pT2,
                                  x, t_slot, W_hh, h0,
                                  (__half*)pOut16, (float*)pHfin);

    /* attention */
    k_w<<<dim3(S_, U_), 256>>>(t, s);
    k_att_mma<<<dim3(2, 2, U_), 256, ATT_SMEM>>>(
        (const __half*)pW16, (const __half*)pOut16,
        (const float*)pDen, (__half*)pOw16);

    /* final projection */
    hmma_gemm16<<<dim3(VPAD / 256, MSU / 128), 256, GEMM16_SMEM>>>(
        (const __half*)pOw16, (const __half*)pFcwA16,
        fc_b, (const float*)pP2, (const float*)pP3, y_t_slot,
        out, H_, V_);

    size_t yelems = (size_t)S_ * U_ * V_;
    if ((size_t)out_size >= yelems + U_ * H_)
        k_hfinal<<<(U_ * H_ + 255) / 256, 256>>>(out + yelems);
}

// round 8
// speedup vs baseline: 3.1238x; 1.0010x over previous
#include <cuda_runtime.h>
#include <cuda_bf16.h>
#include <cuda_fp16.h>
#include <math.h>
#include <stdint.h>

#define S_  256
#define U_  64
#define H_  512
#define H2_ 256
#define V_  5000
#define MSU 16384   /* S*U */
#define VPAD 5120
#define PI_F 3.14159265358979323846f

/* ------------------------------------------------------------------ */
/* scratch (device globals; allocation-free)                           */
/* ------------------------------------------------------------------ */
__device__ float         g_T    [168 * H2_];
__device__ __nv_bfloat16 g_ench [(size_t)VPAD * H_];
__device__ __nv_bfloat16 g_encl [(size_t)VPAD * H_];
__device__ __nv_bfloat16 g_M1h  [(size_t)VPAD * H_];
__device__ __nv_bfloat16 g_M1l  [(size_t)VPAD * H_];
__device__ float         g_E2   [(size_t)VPAD * H_];
__device__ __nv_bfloat16 g_Th   [256 * H2_];
__device__ __nv_bfloat16 g_Tl   [256 * H2_];
__device__ __nv_bfloat16 g_N1h  [256 * H_];
__device__ __nv_bfloat16 g_N1l  [256 * H_];
__device__ float         g_T2   [256 * H_];
__device__ __nv_bfloat16 g_uwh  [128 * H_];
__device__ __nv_bfloat16 g_uwl  [128 * H_];
__device__ float         g_P2   [(size_t)128 * V_];
__device__ float         g_P3   [(size_t)256 * V_];
__device__ __nv_bfloat16 g_fcpAh[512 * H_];
__device__ __nv_bfloat16 g_fcpAl[512 * H_];
__device__ __nv_bfloat16 g_fcpBh[512 * H2_];
__device__ __nv_bfloat16 g_fcpBl[512 * H2_];
__device__ __nv_bfloat16 g_wihh [512 * H_];
__device__ __nv_bfloat16 g_wihl [512 * H_];
__device__ __half        g_fcwA16[(size_t)VPAD * H_];
__device__ __nv_bfloat16 g_fcwBh[(size_t)VPAD * H_];
__device__ __nv_bfloat16 g_fcwBl[(size_t)VPAD * H_];
__device__ __nv_bfloat16 g_fcwCh[(size_t)VPAD * H2_];
__device__ __nv_bfloat16 g_fcwCl[(size_t)VPAD * H2_];
__device__ float         g_cvec [H_];
__device__ __half        g_out16[(size_t)MSU * H_];   /* RNN h, [s][u][h] */
__device__ float         g_hfin [U_ * H_];
__device__ __half        g_w16  [(size_t)U_ * S_ * S_];
__device__ float         g_den  [(size_t)U_ * S_];
__device__ __half        g_ow16 [(size_t)MSU * H_];

/* ------------------------------------------------------------------ */
/* helpers                                                             */
/* ------------------------------------------------------------------ */
__device__ __forceinline__ uint32_t smem_u32(const void* p) {
    uint32_t a;
    asm("{ .reg .u64 t; cvta.to.shared.u64 t, %1; cvt.u32.u64 %0, t; }"
        : "=r"(a) : "l"(p));
    return a;
}

#define CP_ASYNC16(dst, src) \
    asm volatile("cp.async.cg.shared.global [%0], [%1], 16;" :: "r"(dst), "l"(src))
#define CP_COMMIT() asm volatile("cp.async.commit_group;" ::: "memory")
#define CP_WAIT(n)  asm volatile("cp.async.wait_group %0;" :: "n"(n) : "memory")

#define LDS32(v, addr) \
    asm volatile("ld.shared.b32 %0, [%1];" : "=r"(v) : "r"(addr))

#define LDSM4(r0, r1, r2, r3, a) \
    asm volatile("ldmatrix.sync.aligned.m8n8.x4.shared.b16 {%0,%1,%2,%3}, [%4];" \
        : "=r"(r0), "=r"(r1), "=r"(r2), "=r"(r3) : "r"(a))

#define LDSM4T(r0, r1, r2, r3, a) \
    asm volatile("ldmatrix.sync.aligned.m8n8.x4.trans.shared.b16 {%0,%1,%2,%3}, [%4];" \
        : "=r"(r0), "=r"(r1), "=r"(r2), "=r"(r3) : "r"(a))

#define CLUSTER_ARRIVE() \
    asm volatile("barrier.cluster.arrive.aligned;" ::: "memory")
#define CLUSTER_WAIT() \
    asm volatile("barrier.cluster.wait.aligned;" ::: "memory")
#define CLUSTER_SYNC() do { CLUSTER_ARRIVE(); CLUSTER_WAIT(); } while (0)

__device__ __forceinline__ void st_cluster_b32(uint32_t addr, uint32_t rank, uint32_t v) {
    asm volatile(
        "{ .reg .b32 ra; mapa.shared::cluster.u32 ra, %0, %1; "
        "st.shared::cluster.b32 [ra], %2; }"
        :: "r"(addr), "r"(rank), "r"(v) : "memory");
}

__device__ __forceinline__ void mma16816(float* c, const uint32_t* a, const uint32_t* b)
{
    asm volatile(
        "mma.sync.aligned.m16n8k16.row.col.f32.bf16.bf16.f32 "
        "{%0,%1,%2,%3}, {%4,%5,%6,%7}, {%8,%9}, {%0,%1,%2,%3};"
        : "+f"(c[0]), "+f"(c[1]), "+f"(c[2]), "+f"(c[3])
        : "r"(a[0]), "r"(a[1]), "r"(a[2]), "r"(a[3]), "r"(b[0]), "r"(b[1]));
}

__device__ __forceinline__ void mma16816h(float* c, const uint32_t* a, const uint32_t* b)
{
    asm volatile(
        "mma.sync.aligned.m16n8k16.row.col.f32.f16.f16.f32 "
        "{%0,%1,%2,%3}, {%4,%5,%6,%7}, {%8,%9}, {%0,%1,%2,%3};"
        : "+f"(c[0]), "+f"(c[1]), "+f"(c[2]), "+f"(c[3])
        : "r"(a[0]), "r"(a[1]), "r"(a[2]), "r"(a[3]), "r"(b[0]), "r"(b[1]));
}

__device__ __forceinline__ void split2(float v, __nv_bfloat16& h, __nv_bfloat16& l)
{
    h = __float2bfloat16(v);
    l = __float2bfloat16(v - __bfloat162float(h));
}

/* ------------------------------------------------------------------ */
/* split-bf16 HMMA GEMM (3-term) — unchanged                           */
/* ------------------------------------------------------------------ */
#define SWH 40
#define STAGE_B  61440
#define OFF_AL   10240
#define OFF_BH   20480
#define OFF_BL   40960
#define GEMM_SMEM (2 * STAGE_B)

__global__ __launch_bounds__(256, 1)
void hmma_gemm(const __nv_bfloat16* __restrict__ Ah, const __nv_bfloat16* __restrict__ Al,
               const __nv_bfloat16* __restrict__ Bh, const __nv_bfloat16* __restrict__ Bl,
               const float* __restrict__ bias1,
               float* __restrict__ Cf,
               __nv_bfloat16* __restrict__ Ch, __nv_bfloat16* __restrict__ Cl,
               int K, int Nreal)
{
    extern __shared__ char smem[];
    const uint32_t sbase = smem_u32(smem);
    const int tid  = threadIdx.x;
    const int m0   = blockIdx.y * 128;
    const int n0   = blockIdx.x * 256;
    const int warp = tid >> 5, lane = tid & 31;
    const int wm = warp >> 2, wn = warp & 3;
    const int g  = lane >> 2, tig = lane & 3;
    const int L = K >> 5;

    const uint32_t aoffc = ((uint32_t)(wm * 64 + (lane & 15)) * SWH) * 2u
                         + (uint32_t)(lane >> 4) * 16u;
    const int sel  = (lane >> 3) & 3;
    const uint32_t boffc = ((uint32_t)(wn * 64 + ((sel & 2) << 2) + (lane & 7)) * SWH) * 2u
                         + (uint32_t)(sel & 1) * 16u;

    float acc[4][8][4];
#pragma unroll
    for (int mi = 0; mi < 4; mi++)
#pragma unroll
        for (int ni = 0; ni < 8; ni++)
#pragma unroll
            for (int q = 0; q < 4; q++) acc[mi][ni][q] = 0.0f;

    auto load_stage = [&](int chunk, int buf) {
        const uint32_t sg = sbase + (uint32_t)buf * STAGE_B;
        const int k0 = chunk << 5;
#pragma unroll 2
        for (int idx = tid; idx < 512; idx += 256) {
            int r = idx >> 2, c = idx & 3;
            uint32_t dsto = (uint32_t)(r * SWH + c * 8) * 2u;
            size_t srco = (size_t)(m0 + r) * K + k0 + c * 8;
            CP_ASYNC16(sg + dsto,            Ah + srco);
            CP_ASYNC16(sg + OFF_AL + dsto,   Al + srco);
        }
#pragma unroll 4
        for (int idx = tid; idx < 1024; idx += 256) {
            int r = idx >> 2, c = idx & 3;
            uint32_t dsto = (uint32_t)(r * SWH + c * 8) * 2u;
            size_t srco = (size_t)(n0 + r) * K + k0 + c * 8;
            CP_ASYNC16(sg + OFF_BH + dsto,   Bh + srco);
            CP_ASYNC16(sg + OFF_BL + dsto,   Bl + srco);
        }
        CP_COMMIT();
    };

    load_stage(0, 0);

    for (int i = 0; i < L; i++) {
        if (i + 1 < L) { load_stage(i + 1, (i + 1) & 1); CP_WAIT(1); }
        else           { CP_WAIT(0); }
        __syncthreads();

        const uint32_t sg = sbase + (uint32_t)(i & 1) * STAGE_B;
#pragma unroll
        for (int ks = 0; ks < 2; ks++) {
            const uint32_t kb = (uint32_t)ks * 32u;
            uint32_t ah[4][4], al[4][4], bb[8][2];
#pragma unroll
            for (int mi = 0; mi < 4; mi++)
                LDSM4(ah[mi][0], ah[mi][1], ah[mi][2], ah[mi][3],
                      sg + kb + aoffc + (uint32_t)mi * (16 * SWH * 2));
#pragma unroll
            for (int n2 = 0; n2 < 4; n2++)
                LDSM4(bb[2*n2][0], bb[2*n2][1], bb[2*n2+1][0], bb[2*n2+1][1],
                      sg + OFF_BH + kb + boffc + (uint32_t)n2 * (16 * SWH * 2));
#pragma unroll
            for (int mi = 0; mi < 4; mi++)
#pragma unroll
                for (int ni = 0; ni < 8; ni++)
                    mma16816(acc[mi][ni], ah[mi], bb[ni]);
#pragma unroll
            for (int mi = 0; mi < 4; mi++)
                LDSM4(al[mi][0], al[mi][1], al[mi][2], al[mi][3],
                      sg + OFF_AL + kb + aoffc + (uint32_t)mi * (16 * SWH * 2));
#pragma unroll
            for (int mi = 0; mi < 4; mi++)
#pragma unroll
                for (int ni = 0; ni < 8; ni++)
                    mma16816(acc[mi][ni], al[mi], bb[ni]);
#pragma unroll
            for (int n2 = 0; n2 < 4; n2++)
                LDSM4(bb[2*n2][0], bb[2*n2][1], bb[2*n2+1][0], bb[2*n2+1][1],
                      sg + OFF_BL + kb + boffc + (uint32_t)n2 * (16 * SWH * 2));
#pragma unroll
            for (int mi = 0; mi < 4; mi++)
#pragma unroll
                for (int ni = 0; ni < 8; ni++)
                    mma16816(acc[mi][ni], ah[mi], bb[ni]);
        }
        __syncthreads();
    }

#pragma unroll
    for (int mi = 0; mi < 4; mi++) {
        const int row0 = m0 + wm * 64 + mi * 16 + g;
#pragma unroll
        for (int ni = 0; ni < 8; ni++) {
            const int n = n0 + wn * 64 + ni * 8 + tig * 2;
#pragma unroll
            for (int q = 0; q < 4; q++) {
                int rr = row0 + ((q >= 2) ? 8 : 0);
                int nn = n + (q & 1);
                if (nn >= Nreal) continue;
                float f = acc[mi][ni][q];
                if (bias1) f += bias1[nn];
                if (Cf) {
                    Cf[(size_t)rr * Nreal + nn] = f;
                } else {
                    __nv_bfloat16 hi, lo;
                    split2(f, hi, lo);
                    Ch[(size_t)rr * Nreal + nn] = hi;
                    Cl[(size_t)rr * Nreal + nn] = lo;
                }
            }
        }
    }
}

/* ------------------------------------------------------------------ */
/* fp16 single-product HMMA GEMM (final projection) — unchanged        */
/* ------------------------------------------------------------------ */
#define SWH2      72
#define G16_OFFB  18432
#define G16_STAGE 55296
#define GEMM16_SMEM (2 * G16_STAGE)

__global__ __launch_bounds__(256, 1)
void hmma_gemm16(const __half* __restrict__ A, const __half* __restrict__ B,
                 const float* __restrict__ bias1,
                 const float* __restrict__ add1,
                 const float* __restrict__ add2, const int* __restrict__ idx2,
                 float* __restrict__ Cf, int K, int Nreal)
{
    extern __shared__ char smem[];
    const uint32_t sbase = smem_u32(smem);
    const int tid  = threadIdx.x;
    const int m0   = blockIdx.y * 128;
    const int n0   = blockIdx.x * 256;
    const int warp = tid >> 5, lane = tid & 31;
    const int wm = warp >> 2, wn = warp & 3;
    const int g  = lane >> 2, tig = lane & 3;
    const int L = K >> 6;

    const uint32_t aoffc = ((uint32_t)(wm * 64 + (lane & 15)) * SWH2) * 2u
                         + (uint32_t)(lane >> 4) * 16u;
    const int sel  = (lane >> 3) & 3;
    const uint32_t boffc = ((uint32_t)(wn * 64 + ((sel & 2) << 2) + (lane & 7)) * SWH2) * 2u
                         + (uint32_t)(sel & 1) * 16u;

    float acc[4][8][4];
#pragma unroll
    for (int mi = 0; mi < 4; mi++)
#pragma unroll
        for (int ni = 0; ni < 8; ni++)
#pragma unroll
            for (int q = 0; q < 4; q++) acc[mi][ni][q] = 0.0f;

    auto load_stage = [&](int chunk, int buf) {
        const uint32_t sg = sbase + (uint32_t)buf * G16_STAGE;
        const int k0 = chunk << 6;
#pragma unroll 4
        for (int idx = tid; idx < 1024; idx += 256) {
            int r = idx >> 3, c = idx & 7;
            CP_ASYNC16(sg + (uint32_t)(r * SWH2 + c * 8) * 2u,
                       A + (size_t)(m0 + r) * K + k0 + c * 8);
        }
#pragma unroll 8
        for (int idx = tid; idx < 2048; idx += 256) {
            int r = idx >> 3, c = idx & 7;
            CP_ASYNC16(sg + G16_OFFB + (uint32_t)(r * SWH2 + c * 8) * 2u,
                       B + (size_t)(n0 + r) * K + k0 + c * 8);
        }
        CP_COMMIT();
    };

    load_stage(0, 0);

    for (int i = 0; i < L; i++) {
        if (i + 1 < L) { load_stage(i + 1, (i + 1) & 1); CP_WAIT(1); }
        else           { CP_WAIT(0); }
        __syncthreads();

        const uint32_t sg = sbase + (uint32_t)(i & 1) * G16_STAGE;
#pragma unroll
        for (int ks = 0; ks < 4; ks++) {
            const uint32_t kb = (uint32_t)ks * 32u;
            uint32_t ah[4][4], bb[8][2];
#pragma unroll
            for (int mi = 0; mi < 4; mi++)
                LDSM4(ah[mi][0], ah[mi][1], ah[mi][2], ah[mi][3],
                      sg + kb + aoffc + (uint32_t)mi * (16 * SWH2 * 2));
#pragma unroll
            for (int n2 = 0; n2 < 4; n2++)
                LDSM4(bb[2*n2][0], bb[2*n2][1], bb[2*n2+1][0], bb[2*n2+1][1],
                      sg + G16_OFFB + kb + boffc + (uint32_t)n2 * (16 * SWH2 * 2));
#pragma unroll
            for (int mi = 0; mi < 4; mi++)
#pragma unroll
                for (int ni = 0; ni < 8; ni++)
                    mma16816h(acc[mi][ni], ah[mi], bb[ni]);
        }
        __syncthreads();
    }

#pragma unroll
    for (int mi = 0; mi < 4; mi++) {
        const int row0 = m0 + wm * 64 + mi * 16 + g;
        int i2[2] = { 0, 0 };
        if (add2) { i2[0] = idx2[row0]; i2[1] = idx2[row0 + 8]; }
#pragma unroll
        for (int ni = 0; ni < 8; ni++) {
            const int n = n0 + wn * 64 + ni * 8 + tig * 2;
#pragma unroll
            for (int q = 0; q < 4; q++) {
                int rr = row0 + ((q >= 2) ? 8 : 0);
                int nn = n + (q & 1);
                if (nn >= Nreal) continue;
                float f = acc[mi][ni][q] + bias1[nn]
                        + add1[(size_t)(rr & 63) * Nreal + nn]
                        + add2[(size_t)i2[q >> 1] * Nreal + nn];
                Cf[(size_t)rr * Nreal + nn] = f;
            }
        }
    }
}

/* ------------------------------------------------------------------ */
/* attention HMMA: ow[i,u,h] = (sum_j w16[u,i,j] * out16[j,u,h])/den   */
/* grid (2 h-tiles, 2 i-tiles, 64 u); block 256 (8 warps 2x4)          */
/* ------------------------------------------------------------------ */
#define ATT_SWA   40
#define ATT_SWB   264
#define ATT_B_OFF (128 * ATT_SWA * 2)                 /* 10240 */
#define ATT_STAGE (ATT_B_OFF + 32 * ATT_SWB * 2)      /* 27136 */
#define ATT_SMEM  (2 * ATT_STAGE)                     /* 54272 */

__global__ __launch_bounds__(256, 1)
void k_att_mma(const __half* __restrict__ w16, const __half* __restrict__ o16,
               const float* __restrict__ den, __half* __restrict__ ow)
{
    extern __shared__ char smem[];
    const uint32_t sbase = smem_u32(smem);
    const int tid  = threadIdx.x;
    const int u    = blockIdx.z;
    const int i0   = blockIdx.y * 128;
    const int h0   = blockIdx.x * 256;
    const int warp = tid >> 5, lane = tid & 31;
    const int wm = warp >> 2, wn = warp & 3;
    const int g  = lane >> 2, tig = lane & 3;
    const int L  = (i0 + 128) >> 5;

    const uint32_t aoffc = ((uint32_t)(wm * 64 + (lane & 15)) * ATT_SWA) * 2u
                         + (uint32_t)(lane >> 4) * 16u;
    const uint32_t boffc = ((uint32_t)((lane & 7) + ((lane >> 3) & 1) * 8) * ATT_SWB) * 2u
                         + (uint32_t)(lane >> 4) * 16u;

    float acc[4][8][4];
#pragma unroll
    for (int mi = 0; mi < 4; mi++)
#pragma unroll
        for (int ni = 0; ni < 8; ni++)
#pragma unroll
            for (int q = 0; q < 4; q++) acc[mi][ni][q] = 0.0f;

    auto load_stage = [&](int chunk, int buf) {
        const uint32_t sg = sbase + (uint32_t)buf * ATT_STAGE;
        const int j0 = chunk << 5;
#pragma unroll 2
        for (int idx = tid; idx < 512; idx += 256) {
            int r = idx >> 2, c = idx & 3;
            CP_ASYNC16(sg + (uint32_t)(r * ATT_SWA + c * 8) * 2u,
                       w16 + (size_t)u * (S_ * S_) + (size_t)(i0 + r) * S_ + j0 + c * 8);
        }
#pragma unroll 4
        for (int idx = tid; idx < 1024; idx += 256) {
            int r = idx >> 5, c = idx & 31;
            CP_ASYNC16(sg + ATT_B_OFF + (uint32_t)(r * ATT_SWB + c * 8) * 2u,
                       o16 + ((size_t)(j0 + r) * U_ + u) * H_ + h0 + c * 8);
        }
        CP_COMMIT();
    };

    load_stage(0, 0);

    for (int i = 0; i < L; i++) {
        if (i + 1 < L) { load_stage(i + 1, (i + 1) & 1); CP_WAIT(1); }
        else           { CP_WAIT(0); }
        __syncthreads();

        const uint32_t sg = sbase + (uint32_t)(i & 1) * ATT_STAGE;
#pragma unroll
        for (int ks = 0; ks < 2; ks++) {
            uint32_t ah[4][4], bb[8][2];
#pragma unroll
            for (int mi = 0; mi < 4; mi++)
                LDSM4(ah[mi][0], ah[mi][1], ah[mi][2], ah[mi][3],
                      sg + (uint32_t)ks * 32u + aoffc + (uint32_t)mi * (16 * ATT_SWA * 2));
#pragma unroll
            for (int n2 = 0; n2 < 4; n2++)
                LDSM4T(bb[2*n2][0], bb[2*n2][1], bb[2*n2+1][0], bb[2*n2+1][1],
                       sg + ATT_B_OFF + (uint32_t)ks * (16 * ATT_SWB * 2) + boffc
                          + (uint32_t)(wn * 64 + n2 * 16) * 2u);
#pragma unroll
            for (int mi = 0; mi < 4; mi++)
#pragma unroll
                for (int ni = 0; ni < 8; ni++)
                    mma16816h(acc[mi][ni], ah[mi], bb[ni]);
        }
        __syncthreads();
    }

    /* epilogue: divide by den, store fp16 pairs */
#pragma unroll
    for (int mi = 0; mi < 4; mi++) {
        const int ia = i0 + wm * 64 + mi * 16 + g;
        const float d0 = 1.0f / den[u * S_ + ia];
        const float d1 = 1.0f / den[u * S_ + ia + 8];
#pragma unroll
        for (int ni = 0; ni < 8; ni++) {
            const int h = h0 + wn * 64 + ni * 8 + tig * 2;
            uint32_t p0 = (uint32_t)__half_as_ushort(__float2half(acc[mi][ni][0] * d0))
                        | ((uint32_t)__half_as_ushort(__float2half(acc[mi][ni][1] * d0)) << 16);
            uint32_t p1 = (uint32_t)__half_as_ushort(__float2half(acc[mi][ni][2] * d1))
                        | ((uint32_t)__half_as_ushort(__float2half(acc[mi][ni][3] * d1)) << 16);
            ((uint32_t*)ow)[(((size_t)ia      * U_ + u) * H_ + h) >> 1] = p0;
            ((uint32_t*)ow)[(((size_t)(ia + 8)* U_ + u) * H_ + h) >> 1] = p1;
        }
    }
}

/* ------------------------------------------------------------------ */
/* subview splits                                                      */
/* ------------------------------------------------------------------ */
__global__ void k_split_sub(const float* __restrict__ src, int pitch, int col0,
                            int rows, int cols, int padRows,
                            __nv_bfloat16* __restrict__ dh, __nv_bfloat16* __restrict__ dl)
{
    size_t total = (size_t)padRows * cols;
    for (size_t idx = (size_t)blockIdx.x * blockDim.x + threadIdx.x;
         idx < total; idx += (size_t)gridDim.x * blockDim.x) {
        int r = (int)(idx / cols);
        int c = (int)(idx - (size_t)r * cols);
        float v = (r < rows) ? src[(size_t)r * pitch + col0 + c] : 0.0f;
        __nv_bfloat16 hi, lo;
        split2(v, hi, lo);
        dh[idx] = hi; dl[idx] = lo;
    }
}

__global__ void k_split16(const float* __restrict__ src, int pitch, int col0,
                          int rows, int cols, int padRows, __half* __restrict__ d)
{
    size_t total = (size_t)padRows * cols;
    for (size_t idx = (size_t)blockIdx.x * blockDim.x + threadIdx.x;
         idx < total; idx += (size_t)gridDim.x * blockDim.x) {
        int r = (int)(idx / cols);
        int c = (int)(idx - (size_t)r * cols);
        float v = (r < rows) ? src[(size_t)r * pitch + col0 + c] : 0.0f;
        d[idx] = __float2half(v);
    }
}

/* ------------------------------------------------------------------ */
__global__ void k_userw(const float* __restrict__ user_w, const int* __restrict__ au)
{
    const int u = blockIdx.x;
    const int c = threadIdx.x;
    float v = 0.0f;
    if (u < U_) v = user_w[(size_t)au[u] * H_ + c];
    __nv_bfloat16 hi, lo;
    split2(v, hi, lo);
    g_uwh[u * H_ + c] = hi;
    g_uwl[u * H_ + c] = lo;
}

__global__ void k_cvec(const float* __restrict__ fcpt_b, const float* __restrict__ W_ih,
                       const float* __restrict__ b_ih, const float* __restrict__ b_hh)
{
    const int n = blockIdx.x * blockDim.x + threadIdx.x;
    if (n >= H_) return;
    float a = b_ih[n] + b_hh[n];
    for (int k = 0; k < H_; k++) a += fcpt_b[k] * W_ih[(size_t)n * H_ + k];
    g_cvec[n] = a;
}

/* ------------------------------------------------------------------ */
__global__ void k_week(const float* __restrict__ sigma,
                       const float* __restrict__ wwi,
                       const int*   __restrict__ wm,
                       const float* __restrict__ wenc)
{
    const int slot = blockIdx.x;
    const int tid  = threadIdx.x;
    __shared__ float ww[168];
    __shared__ float red[256];

    float sig    = fabsf(sigma[slot]);
    float inv2s2 = 1.0f / (2.0f * sig * sig);
    float coef   = rsqrtf(2.0f * PI_F * sig * sig);

    float v = 0.0f;
    if (tid < 168) {
        float x = wwi[slot * 168 + tid];
        v = coef * expf(-x * x * inv2s2);
        ww[tid] = v;
    }
    red[tid] = v;
    __syncthreads();
    for (int off = 128; off > 0; off >>= 1) {
        if (tid < off) red[tid] += red[tid + off];
        __syncthreads();
    }
    const float inv = 1.0f / red[0];

    float acc = 0.0f;
    for (int k = 0; k < 168; k++) {
        int row = wm[slot * 168 + k];
        acc += (ww[k] * inv) * wenc[row * H2_ + tid];
    }
    g_T[slot * H2_ + tid] = acc;
}

/* ------------------------------------------------------------------ */
/* RNN: cluster(8) fp16 HMMA, Wh in regs / Wl in smem, fused pre gather*/
/* ------------------------------------------------------------------ */
#define WPAD 520
#define R_WH   0
#define R_WL   66560
#define R_HB0  133120
#define R_HB1  141440
#define R_PSUM 149760
#define RNN_SMEM 166144

__global__ __cluster_dims__(8, 1, 1) __launch_bounds__(256, 1)
void k_rnn(const float* __restrict__ E2, const float* __restrict__ T2,
           const int* __restrict__ x, const int* __restrict__ ts,
           const float* __restrict__ Whh, const float* __restrict__ h0,
           __half* __restrict__ out16, float* __restrict__ hfin)
{
    extern __shared__ char sm[];
    const uint32_t sb = smem_u32(sm);
    const int tid = threadIdx.x;
    const int warp = tid >> 5, lane = tid & 31;
    const int gu = blockIdx.x >> 3;
    uint32_t gn;
    asm("mov.u32 %0, %%cluster_ctarank;" : "=r"(gn));

    __half* wsth = (__half*)(sm + R_WH);
    __half* wstl = (__half*)(sm + R_WL);

    /* stage W slice (rows gn*64..+64) as fp16 hi + fp16 residual */
    for (int idx = tid; idx < 64 * 512; idx += 256) {
        int r = idx >> 9, c = idx & 511;
        float v = Whh[(size_t)(gn * 64 + r) * H_ + c];
        __half hh = __float2half(v);
        __half ll = __float2half(v - __half2float(hh));
        wsth[r * WPAD + c] = hh;
        wstl[r * WPAD + c] = ll;
    }
    __syncthreads();

    /* Wh fragments -> registers (128 regs); Wl stays in smem */
    const uint32_t la = (uint32_t)(lane & 15) * (WPAD * 2)
                      + (uint32_t)(lane >> 4) * 16u;
    uint32_t Wh[4][4][4];
#pragma unroll
    for (int mi = 0; mi < 4; mi++)
#pragma unroll
        for (int kt = 0; kt < 4; kt++) {
            uint32_t ofs = la + (uint32_t)mi * 16u * (WPAD * 2)
                         + (uint32_t)(warp * 64 + kt * 16) * 2u;
            LDSM4(Wh[mi][kt][0], Wh[mi][kt][1], Wh[mi][kt][2], Wh[mi][kt][3],
                  sb + R_WH + ofs);
        }

    /* h buffers (fp16 single) */
    __half* hb0 = (__half*)(sm + R_HB0);
    __half* hb1 = (__half*)(sm + R_HB1);
    for (int idx = tid; idx < 8 * WPAD; idx += 256) {
        hb0[idx] = __float2half(0.0f);
        hb1[idx] = __float2half(0.0f);
    }
    __syncthreads();
    for (int idx = tid; idx < 4 * 512; idx += 256) {
        int u = idx >> 9, c = idx & 511;
        hb0[u * WPAD + c] = __float2half(h0[(size_t)(gu * 4 + u) * H_ + c]);
    }
    CLUSTER_SYNC();

    float* psum = (float*)(sm + R_PSUM);
    const int n_out = tid & 63, u_out = tid >> 6;
    const int mi_r = n_out >> 4, r16 = n_out & 15;
    const int lr = ((r16 & 7) << 2) + (u_out >> 1);
    const int cc = (u_out & 1) + ((r16 >> 3) << 1);
    const int cidx = (int)gn * 64 + n_out;
    const uint32_t bbase = (uint32_t)(lane >> 2) * (WPAD * 2)
                         + (uint32_t)(warp * 64 + (lane & 3) * 2) * 2u;

    /* prefetch pre for s=0 */
    int xm = __ldg(x + gu * 4 + u_out);
    int tm = __ldg(ts + gu * 4 + u_out);
    float pv = __ldg(E2 + (size_t)xm * H_ + cidx) + __ldg(T2 + (size_t)tm * H_ + cidx);

    for (int s = 0; s < S_; s++) {
        const uint32_t hb = sb + ((s & 1) ? R_HB1 : R_HB0);

        float acc[4][4];
#pragma unroll
        for (int mi = 0; mi < 4; mi++)
#pragma unroll
            for (int q = 0; q < 4; q++) acc[mi][q] = 0.0f;

#pragma unroll
        for (int kt = 0; kt < 4; kt++) {
            uint32_t wl[4][4];
#pragma unroll
            for (int mi = 0; mi < 4; mi++)
                LDSM4(wl[mi][0], wl[mi][1], wl[mi][2], wl[mi][3],
                      sb + R_WL + la + (uint32_t)mi * 16u * (WPAD * 2)
                         + (uint32_t)(warp * 64 + kt * 16) * 2u);
            uint32_t bh[2];
            LDS32(bh[0], hb + bbase + (uint32_t)kt * 32u);
            LDS32(bh[1], hb + bbase + (uint32_t)kt * 32u + 16u);
#pragma unroll
            for (int mi = 0; mi < 4; mi++) {
                mma16816h(acc[mi], Wh[mi][kt], bh);
                mma16816h(acc[mi], wl[mi], bh);
            }
        }
#pragma unroll
        for (int mi = 0; mi < 4; mi++) {
            float4 v4 = make_float4(acc[mi][0], acc[mi][1], acc[mi][2], acc[mi][3]);
            *(float4*)&psum[(warp * 4 + mi) * 128 + lane * 4] = v4;
        }
        __syncthreads();

        float v = 0.0f;
#pragma unroll
        for (int w2 = 0; w2 < 8; w2++)
            v += psum[(w2 * 4 + mi_r) * 128 + lr * 4 + cc];

        float hv = tanhf(pv + v);
        const size_t o = (size_t)s * U_ * H_ + (size_t)(gu * 4 + u_out) * H_ + cidx;
        out16[o] = __float2half(hv);

        if (s == S_ - 1) {
            hfin[(size_t)(gu * 4 + u_out) * H_ + cidx] = hv;
        } else {
            uint32_t mine = (uint32_t)__half_as_ushort(__float2half(hv));
            uint32_t part = __shfl_xor_sync(0xffffffffu, mine, 1);
            if (!(lane & 1)) {
                uint32_t packed = mine | (part << 16);
                uint32_t dst = sb + ((s & 1) ? R_HB0 : R_HB1)
                             + (uint32_t)(u_out * WPAD + (int)gn * 64 + n_out) * 2u;
#pragma unroll
                for (int r = 0; r < 8; r++)
                    st_cluster_b32(dst, (uint32_t)r, packed);
            }
            CLUSTER_ARRIVE();
            int s1 = s + 1;
            xm = __ldg(x + s1 * U_ + gu * 4 + u_out);
            tm = __ldg(ts + s1 * U_ + gu * 4 + u_out);
            float pvn = __ldg(E2 + (size_t)xm * H_ + cidx)
                      + __ldg(T2 + (size_t)tm * H_ + cidx);
            CLUSTER_WAIT();
            pv = pvn;
        }
    }
}

/* ------------------------------------------------------------------ */
/* attention weights (fp16) and row sums den[u,i]                      */
/* ------------------------------------------------------------------ */
__global__ void k_w(const float* __restrict__ t, const float* __restrict__ s)
{
    const int i = blockIdx.x, u = blockIdx.y;
    const int j = threadIdx.x;
    __shared__ float red[256];

    float wv = 0.0f;
    if (j <= i) {
        float dt = t[i * U_ + u] - t[j * U_ + u];
        float d0 = s[((size_t)i * U_ + u) * 2 + 0] - s[((size_t)j * U_ + u) * 2 + 0];
        float d1 = s[((size_t)i * U_ + u) * 2 + 1] - s[((size_t)j * U_ + u) * 2 + 1];
        float ds = sqrtf(d0 * d0 + d1 * d1);
        float ft = (cosf(dt * (2.0f * PI_F / 86400.0f)) + 1.0f) * 0.5f
                 * expf(-(dt / 86400.0f) * 0.1f);
        float fs = expf(-ds * 100.0f);
        wv = ft * fs + 1e-10f;
    }
    g_w16[((size_t)u * S_ + i) * S_ + j] = __float2half(wv);

    red[j] = wv;
    __syncthreads();
    for (int off = 128; off > 0; off >>= 1) {
        if (j < off) red[j] += red[j + off];
        __syncthreads();
    }
    if (j == 0) g_den[u * S_ + i] = red[0];
}

/* ------------------------------------------------------------------ */
__global__ void k_hfinal(float* __restrict__ dst)
{
    int i = blockIdx.x * blockDim.x + threadIdx.x;
    if (i < U_ * H_) dst[i] = g_hfin[i];
}

/* ------------------------------------------------------------------ */
extern "C" void kernel_launch(void* const* d_in, const int* in_sizes, int n_in,
                              void* d_out, int out_size)
{
    const int*   x        = (const int*)  d_in[0];
    const float* t        = (const float*)d_in[1];
    const int*   t_slot   = (const int*)  d_in[2];
    const float* s        = (const float*)d_in[3];
    const int*   y_t_slot = (const int*)  d_in[5];
    const float* h0       = (const float*)d_in[7];
    const int*   act_user = (const int*)  d_in[8];
    const int*   wm       = (const int*)  d_in[9];
    const float* wwi      = (const float*)d_in[10];
    const float* sigma    = (const float*)d_in[11];
    const float* enc_w    = (const float*)d_in[12];
    const float* user_w   = (const float*)d_in[13];
    const float* wenc     = (const float*)d_in[14];
    const float* fcpt_w   = (const float*)d_in[15];
    const float* fcpt_b   = (const float*)d_in[16];
    const float* W_ih     = (const float*)d_in[17];
    const float* W_hh     = (const float*)d_in[18];
    const float* b_ih     = (const float*)d_in[19];
    const float* b_hh     = (const float*)d_in[20];
    const float* fc_w     = (const float*)d_in[21];
    const float* fc_b     = (const float*)d_in[22];
    float* out = (float*)d_out;

    void *pT, *pEnch, *pEncl, *pM1h, *pM1l, *pE2, *pTh, *pTl, *pN1h, *pN1l, *pT2;
    void *pUwh, *pUwl, *pP2, *pP3, *pCvec;
    void *pFcpAh, *pFcpAl, *pFcpBh, *pFcpBl, *pWihh, *pWihl;
    void *pFcwA16, *pFcwBh, *pFcwBl, *pFcwCh, *pFcwCl;
    void *pOut16, *pHfin, *pW16, *pDen, *pOw16;
    cudaGetSymbolAddress(&pT, g_T);
    cudaGetSymbolAddress(&pEnch, g_ench);  cudaGetSymbolAddress(&pEncl, g_encl);
    cudaGetSymbolAddress(&pM1h, g_M1h);    cudaGetSymbolAddress(&pM1l, g_M1l);
    cudaGetSymbolAddress(&pE2, g_E2);
    cudaGetSymbolAddress(&pTh, g_Th);      cudaGetSymbolAddress(&pTl, g_Tl);
    cudaGetSymbolAddress(&pN1h, g_N1h);    cudaGetSymbolAddress(&pN1l, g_N1l);
    cudaGetSymbolAddress(&pT2, g_T2);
    cudaGetSymbolAddress(&pUwh, g_uwh);    cudaGetSymbolAddress(&pUwl, g_uwl);
    cudaGetSymbolAddress(&pP2, g_P2);      cudaGetSymbolAddress(&pP3, g_P3);
    cudaGetSymbolAddress(&pCvec, g_cvec);
    cudaGetSymbolAddress(&pFcpAh, g_fcpAh); cudaGetSymbolAddress(&pFcpAl, g_fcpAl);
    cudaGetSymbolAddress(&pFcpBh, g_fcpBh); cudaGetSymbolAddress(&pFcpBl, g_fcpBl);
    cudaGetSymbolAddress(&pWihh, g_wihh);  cudaGetSymbolAddress(&pWihl, g_wihl);
    cudaGetSymbolAddress(&pFcwA16, g_fcwA16);
    cudaGetSymbolAddress(&pFcwBh, g_fcwBh); cudaGetSymbolAddress(&pFcwBl, g_fcwBl);
    cudaGetSymbolAddress(&pFcwCh, g_fcwCh); cudaGetSymbolAddress(&pFcwCl, g_fcwCl);
    cudaGetSymbolAddress(&pOut16, g_out16); cudaGetSymbolAddress(&pHfin, g_hfin);
    cudaGetSymbolAddress(&pW16, g_w16);    cudaGetSymbolAddress(&pDen, g_den);
    cudaGetSymbolAddress(&pOw16, g_ow16);

    cudaFuncSetAttribute(hmma_gemm,   cudaFuncAttributeMaxDynamicSharedMemorySize, GEMM_SMEM);
    cudaFuncSetAttribute(hmma_gemm16, cudaFuncAttributeMaxDynamicSharedMemorySize, GEMM16_SMEM);
    cudaFuncSetAttribute(k_att_mma,   cudaFuncAttributeMaxDynamicSharedMemorySize, ATT_SMEM);
    cudaFuncSetAttribute(k_rnn,       cudaFuncAttributeMaxDynamicSharedMemorySize, RNN_SMEM);

    /* tables & splits */
    k_week<<<168, 256>>>(sigma, wwi, wm, wenc);
    k_split_sub<<<256, 256>>>(enc_w,  H_,  0,    V_,   H_,  VPAD,
                              (__nv_bfloat16*)pEnch, (__nv_bfloat16*)pEncl);
    k_split_sub<<<128, 256>>>(fcpt_w, 768, 0,    512,  H_,  512,
                              (__nv_bfloat16*)pFcpAh, (__nv_bfloat16*)pFcpAl);
    k_split_sub<<<128, 256>>>(W_ih,   H_,  0,    512,  H_,  512,
                              (__nv_bfloat16*)pWihh, (__nv_bfloat16*)pWihl);
    hmma_gemm<<<dim3(2, VPAD / 128), 256, GEMM_SMEM>>>(
        (const __nv_bfloat16*)pEnch, (const __nv_bfloat16*)pEncl,
        (const __nv_bfloat16*)pFcpAh, (const __nv_bfloat16*)pFcpAl,
        nullptr, nullptr, (__nv_bfloat16*)pM1h, (__nv_bfloat16*)pM1l, H_, H_);
    hmma_gemm<<<dim3(2, VPAD / 128), 256, GEMM_SMEM>>>(
        (const __nv_bfloat16*)pM1h, (const __nv_bfloat16*)pM1l,
        (const __nv_bfloat16*)pWihh, (const __nv_bfloat16*)pWihl,
        nullptr, (float*)pE2, nullptr, nullptr, H_, H_);
    k_split_sub<<<32, 256>>>((const float*)pT, H2_, 0, 168, H2_, 256,
                              (__nv_bfloat16*)pTh, (__nv_bfloat16*)pTl);
    k_split_sub<<<64, 256>>>(fcpt_w,  768, 512,  512,  H2_, 512,
                              (__nv_bfloat16*)pFcpBh, (__nv_bfloat16*)pFcpBl);
    hmma_gemm<<<dim3(2, 2), 256, GEMM_SMEM>>>(
        (const __nv_bfloat16*)pTh, (const __nv_bfloat16*)pTl,
        (const __nv_bfloat16*)pFcpBh, (const __nv_bfloat16*)pFcpBl,
        nullptr, nullptr, (__nv_bfloat16*)pN1h, (__nv_bfloat16*)pN1l, H2_, H_);
    k_cvec<<<2, 256>>>(fcpt_b, W_ih, b_ih, b_hh);
    hmma_gemm<<<dim3(2, 2), 256, GEMM_SMEM>>>(
        (const __nv_bfloat16*)pN1h, (const __nv_bfloat16*)pN1l,
        (const __nv_bfloat16*)pWihh, (const __nv_bfloat16*)pWihl,
        (const float*)pCvec, (float*)pT2, nullptr, nullptr, H_, H_);
    k_split_sub<<<256, 256>>>(fc_w, 1280, 512, V_, H_, VPAD,
                              (__nv_bfloat16*)pFcwBh, (__nv_bfloat16*)pFcwBl);
    k_userw<<<128, 512>>>(user_w, act_user);
    hmma_gemm<<<dim3(VPAD / 256, 1), 256, GEMM_SMEM>>>(
        (const __nv_bfloat16*)pUwh, (const __nv_bfloat16*)pUwl,
        (const __nv_bfloat16*)pFcwBh, (const __nv_bfloat16*)pFcwBl,
        nullptr, (float*)pP2, nullptr, nullptr, H_, V_);
    k_split_sub<<<256, 256>>>(fc_w, 1280, 1024, V_, H2_, VPAD,
                              (__nv_bfloat16*)pFcwCh, (__nv_bfloat16*)pFcwCl);
    hmma_gemm<<<dim3(VPAD / 256, 2), 256, GEMM_SMEM>>>(
        (const __nv_bfloat16*)pTh, (const __nv_bfloat16*)pTl,
        (const __nv_bfloat16*)pFcwCh, (const __nv_bfloat16*)pFcwCl,
        nullptr, (float*)pP3, nullptr, nullptr, H2_, V_);
    k_split16<<<256, 256>>>(fc_w, 1280, 0, V_, H_, VPAD, (__half*)pFcwA16);

    /* RNN (fused pre gather) */
    k_rnn<<<128, 256, RNN_SMEM>>>((const float*)pE2, (const float*)pT2,
                                  x, t_slot, W_hh, h0,
                                  (__half*)pOut16, (float*)pHfin);

    /* attention */
    k_w<<<dim3(S_, U_), 256>>>(t, s);
    k_att_mma<<<dim3(2, 2, U_), 256, ATT_SMEM>>>(
        (const __half*)pW16, (const __half*)pOut16,
        (const float*)pDen, (__half*)pOw16);

    /* final projection */
    hmma_gemm16<<<dim3(VPAD / 256, MSU / 128), 256, GEMM16_SMEM>>>(
        (const __half*)pOw16, (const __half*)pFcwA16,
        fc_b, (const float*)pP2, (const float*)pP3, y_t_slot,
        out, H_, V_);

    size_t yelems = (size_t)S_ * U_ * V_;
    if ((size_t)out_size >= yelems + U_ * H_)
        k_hfinal<<<(U_ * H_ + 255) / 256, 256>>>(out + yelems);
}